// round 8
// baseline (speedup 1.0000x reference)
#include <cuda_runtime.h>
#include <cuda_bf16.h>
#include <math.h>
#include <stdint.h>

// ---------------- problem constants ----------------
#define BN    4096          // nodes (B*N)
#define NE    131072        // edges
#define DIMN  480           // 128 + 3*64 + 5*32
#define W3    192           // 3*MSG
#define RBFD  32
#define CUT   5.0f

// ---------------- packed f32x2 helpers ----------------
__device__ __forceinline__ unsigned long long pack2(float lo, float hi) {
    unsigned long long r;
    asm("mov.b64 %0, {%1, %2};" : "=l"(r) : "f"(lo), "f"(hi));
    return r;
}
__device__ __forceinline__ void unpack2(unsigned long long v, float& lo, float& hi) {
    asm("mov.b64 {%0, %1}, %2;" : "=f"(lo), "=f"(hi) : "l"(v));
}
__device__ __forceinline__ void fma2(unsigned long long& d, unsigned long long a,
                                     unsigned long long b) {
    asm("fma.rn.f32x2 %0, %1, %2, %3;" : "=l"(d) : "l"(a), "l"(b), "l"(d));
}

// ---------------- scratch (device globals; no allocation) ----------------
__device__ float g_x[BN * DIMN];                 // node features
__device__ float g_P[BN * W3];                   // per-node projection x[:, :128] @ Wp
__device__ float g_m[BN * 576];                  // per-node segment sums
__device__ float g_rbf[(size_t)NE * RBFD];       // per-edge rbf
__device__ float g_sh[(size_t)NE * 9];           // per-edge sph harmonics
__device__ float g_fcut[NE];                     // per-edge cutoff
__device__ float g_w[(size_t)NE * W3];           // per-EDGE message weights
__device__ int   g_cnt[BN];                      // zero-init at load; re-zeroed by k_scan
__device__ int   g_off[BN + 1];
__device__ int   g_cur[BN];
__device__ int   g_perm[NE];

// ---------------- fused setup: init (32 nodes/CTA) + geometry + count ----------------
#define G_INIT 128
#define G_GEO  512
#define G_CNT  512
__global__ void __launch_bounds__(256) k_setup(const int* __restrict__ z,
                                               const float* __restrict__ mask,
                                               const float* __restrict__ z_emb,
                                               const float* __restrict__ W_in,
                                               const float* __restrict__ ew,
                                               const float* __restrict__ evec,
                                               const int* __restrict__ dst) {
    int bx = blockIdx.x;
    int t = threadIdx.x;
    if (bx < G_INIT) {
        // ---- init: x0 = z_emb[z] @ W_in ----
        __shared__ float sZ[32 * 128];
        __shared__ int   sZi[32];
        __shared__ float sMk[32];
        int n0 = bx * 32;
        if (t < 32) { sZi[t] = z[n0 + t]; sMk[t] = mask[n0 + t]; }
        __syncthreads();
        for (int q = t; q < 32 * 128; q += 256) {
            int nl = q >> 7, k = q & 127;
            sZ[q] = z_emb[sZi[nl] * 128 + k];
        }
        __syncthreads();
        int j = t & 127, g = t >> 7;   // g in {0,1}: 16 nodes each
        float acc[16];
#pragma unroll
        for (int nn = 0; nn < 16; nn++) acc[nn] = 0.f;
#pragma unroll 4
        for (int k = 0; k < 128; k++) {
            float wv = W_in[k * 128 + j];
            const float* zr = &sZ[(g * 16) * 128 + k];
#pragma unroll
            for (int nn = 0; nn < 16; nn++) acc[nn] += zr[nn * 128] * wv;
        }
#pragma unroll
        for (int nn = 0; nn < 16; nn++) {
            int nl = g * 16 + nn;
            g_x[(size_t)(n0 + nl) * DIMN + j] = acc[nn] * sMk[nl];
        }
        for (int idx = t; idx < 32 * 352; idx += 256) {
            int nl = idx / 352, o = 128 + (idx - nl * 352);
            g_x[(size_t)(n0 + nl) * DIMN + o] = 0.f;
        }
    } else if (bx < G_INIT + G_GEO) {
        // ---- geometry ----
        int e = (bx - G_INIT) * 256 + t;
        float len = ew[e];
        float inv = 1.f / fmaxf(len, 1e-8f);
        float x = evec[e * 3 + 0] * inv;
        float y = evec[e * 3 + 1] * inv;
        float zc = evec[e * 3 + 2] * inv;
        float d = fminf(len, CUT);
        const float width = CUT / 31.f;
#pragma unroll
        for (int k = 0; k < RBFD; k++) {
            float c = CUT * (float)k / 31.f;
            float u = (d - c) / width;
            g_rbf[(size_t)e * RBFD + k] = expf(-0.5f * u * u);
        }
        const float s3 = 1.7320508075688772f;
        const float s5 = 2.2360679774997896f;
        const float s15 = 3.872983346207417f;
        float sh[9];
        sh[0] = 1.f;
        sh[1] = s3 * x; sh[2] = s3 * y; sh[3] = s3 * zc;
        sh[4] = s15 * x * y; sh[5] = s15 * y * zc;
        sh[6] = 0.5f * s5 * (3.f * zc * zc - 1.f);
        sh[7] = s15 * x * zc; sh[8] = 0.5f * s15 * (x * x - y * y);
#pragma unroll
        for (int j2 = 0; j2 < 9; j2++) g_sh[(size_t)e * 9 + j2] = sh[j2];
        float tt = fminf(len / CUT, 1.f);
        g_fcut[e] = 0.5f * (cosf(3.14159265358979323846f * tt) + 1.f);
    } else {
        // ---- count ----
        int e = (bx - G_INIT - G_GEO) * 256 + t;
        atomicAdd(&g_cnt[dst[e]], 1);
    }
}

// ---------------- scan (+ self-zero g_cnt for graph replay) ----------------
__global__ void k_scan() {
    __shared__ int part[1024];
    int t = threadIdx.x;
    int base = t * 4;
    int loc[4];
    int s = 0;
#pragma unroll
    for (int i = 0; i < 4; i++) { loc[i] = s; s += g_cnt[base + i]; }
    part[t] = s;
    __syncthreads();
    for (int off = 1; off < 1024; off <<= 1) {
        int v = (t >= off) ? part[t - off] : 0;
        __syncthreads();
        part[t] += v;
        __syncthreads();
    }
    int pre = (t == 0) ? 0 : part[t - 1];
#pragma unroll
    for (int i = 0; i < 4; i++) {
        g_off[base + i] = pre + loc[i];
        g_cur[base + i] = pre + loc[i];
        g_cnt[base + i] = 0;
    }
    if (t == 1023) g_off[BN] = part[1023];
}

__global__ void k_fill(const int* __restrict__ dst) {
    int e = blockIdx.x * 256 + threadIdx.x;
    if (e < NE) {
        int p = atomicAdd(&g_cur[dst[e]], 1);
        g_perm[p] = e;
    }
}

// ---------------- per-node deterministic sort (odd-even in smem, 1 warp/node) ----------------
#define SORT_CAP 1024
__global__ void __launch_bounds__(256) k_sortseg() {
    __shared__ int sbuf[8 * SORT_CAP];
    int warp = threadIdx.x >> 5, lane = threadIdx.x & 31;
    int n = blockIdx.x * 8 + warp;
    int lo = g_off[n], hi = g_off[n + 1];
    int len = hi - lo;
    int* buf = sbuf + warp * SORT_CAP;
    if (len <= 1) return;
    if (len <= SORT_CAP) {
        for (int i = lane; i < len; i += 32) buf[i] = g_perm[lo + i];
        __syncwarp();
        for (int r = 0; r < len; r++) {
            int st = r & 1;
            for (int i = st + 2 * lane; i + 1 < len; i += 64) {
                int a = buf[i], b = buf[i + 1];
                if (a > b) { buf[i] = b; buf[i + 1] = a; }
            }
            __syncwarp();
        }
        for (int i = lane; i < len; i += 32) g_perm[lo + i] = buf[i];
    } else if (lane == 0) {   // fallback (never expected at avg degree 32)
        for (int i = lo + 1; i < hi; i++) {
            int key = g_perm[i];
            int j = i - 1;
            while (j >= lo && g_perm[j] > key) { g_perm[j + 1] = g_perm[j]; j--; }
            g_perm[j + 1] = key;
        }
    }
}

// ---------------- per-node proj GEMM: g_P = x[:, :128] @ Wp[b]  (4096x192x128) ----------------
#define PROJN_SMEM_BYTES (33280 * 4)
__global__ void __launch_bounds__(256) k_projnode(const float* __restrict__ Wpb) {
    extern __shared__ float sm[];
    float* sAT = sm;          // [128][68]
    float* sWp = sm + 8704;   // [128*192]
    int t = threadIdx.x;
    int n0 = blockIdx.x * 64;

    {
        int i = t >> 2, q = t & 3;
        const float* xr = g_x + (size_t)(n0 + i) * DIMN + q * 32;
#pragma unroll
        for (int r = 0; r < 8; r++) {
            float4 v = *(const float4*)(xr + r * 4);
            int k = q * 32 + r * 4;
            sAT[(k + 0) * 68 + i] = v.x;
            sAT[(k + 1) * 68 + i] = v.y;
            sAT[(k + 2) * 68 + i] = v.z;
            sAT[(k + 3) * 68 + i] = v.w;
        }
    }
    for (int q = t; q < 6144; q += 256) ((float4*)sWp)[q] = ((const float4*)Wpb)[q];
    __syncthreads();

    int tx = t & 15, ty = t >> 4;
    int i0 = ty * 4, j0 = tx * 12;
    unsigned long long acc2[4][6];
#pragma unroll
    for (int a = 0; a < 4; a++)
#pragma unroll
        for (int b = 0; b < 6; b++) acc2[a][b] = 0ull;

#pragma unroll 4
    for (int k = 0; k < 128; k++) {
        float4 a0 = *(const float4*)&sAT[k * 68 + i0];
        const float* br = &sWp[k * 192 + j0];
        ulonglong2 q0 = ((const ulonglong2*)br)[0];
        ulonglong2 q1 = ((const ulonglong2*)br)[1];
        ulonglong2 q2 = ((const ulonglong2*)br)[2];
        unsigned long long bb2[6] = {q0.x, q0.y, q1.x, q1.y, q2.x, q2.y};
        float av[4] = {a0.x, a0.y, a0.z, a0.w};
#pragma unroll
        for (int a = 0; a < 4; a++) {
            unsigned long long aa = pack2(av[a], av[a]);
#pragma unroll
            for (int b = 0; b < 6; b++) fma2(acc2[a][b], aa, bb2[b]);
        }
    }
#pragma unroll
    for (int a = 0; a < 4; a++) {
        float accs[12];
#pragma unroll
        for (int b = 0; b < 6; b++) unpack2(acc2[a][b], accs[2 * b], accs[2 * b + 1]);
        float* pr = g_P + (size_t)(n0 + i0 + a) * W3 + j0;
#pragma unroll
        for (int g = 0; g < 3; g++) {
            float4 v;
            v.x = accs[g * 4 + 0]; v.y = accs[g * 4 + 1];
            v.z = accs[g * 4 + 2]; v.w = accs[g * 4 + 3];
            *(float4*)(pr + g * 4) = v;
        }
    }
}

// ---------------- per-edge: g_w[e] = P[src] * (silu(rbf@rW1+rb1)@rW2 + rb2) * fcut ----------
// 64 edges/CTA, 256 threads, 3 CTAs/SM. rW2 staged in 2 k-chunks of 32x192 (24 KB).
// smem floats:
//   sRbfT [32][68]     @0      2176
//   s_rW1 [32*64]      @2176   2048
//   sHT   [64][68]     @4224   4352
//   s_rW2 [32*192]     @8576   6144   (one k-chunk)
//   sFcut 64           @14720
//   s_rb1 64           @14784
//   s_rb2 192          @14848
//   s_src 64 (int)     @15040   -> total 15104 floats = 60416 B
#define EDGE_TILE 64
#define EDGE_SMEM_BYTES (15104 * 4)
__global__ void __launch_bounds__(256, 3) k_edge(const float* __restrict__ rW1b,
                                                 const float* __restrict__ rb1b,
                                                 const float* __restrict__ rW2b,
                                                 const float* __restrict__ rb2b,
                                                 const int* __restrict__ esrc) {
    extern __shared__ float sm[];
    float* sRbfT = sm;
    float* s_rW1 = sm + 2176;
    float* sHT   = sm + 4224;
    float* s_rW2 = sm + 8576;
    float* sFcut = sm + 14720;
    float* s_rb1 = sm + 14784;
    float* s_rb2 = sm + 14848;
    int*   s_src = (int*)(sm + 15040);

    int t = threadIdx.x;
    int e0 = blockIdx.x * EDGE_TILE;

    {   // rbf tile transposed: 4 threads per edge row, 8 floats each
        int i = t >> 2, q = t & 3;
        const float4* r4 = (const float4*)(g_rbf + (size_t)(e0 + i) * RBFD + q * 8);
#pragma unroll
        for (int r = 0; r < 2; r++) {
            float4 v = r4[r];
            int k = q * 8 + r * 4;
            sRbfT[(k + 0) * 68 + i] = v.x;
            sRbfT[(k + 1) * 68 + i] = v.y;
            sRbfT[(k + 2) * 68 + i] = v.z;
            sRbfT[(k + 3) * 68 + i] = v.w;
        }
    }
    for (int q = t; q < 512; q += 256)  ((float4*)s_rW1)[q] = ((const float4*)rW1b)[q];
    if (t < 64)  { sFcut[t] = g_fcut[e0 + t]; s_src[t] = esrc[e0 + t]; s_rb1[t] = rb1b[t]; }
    if (t >= 64 && t < 256) s_rb2[t - 64] = rb2b[t - 64];
    __syncthreads();

    int tx = t & 15, ty = t >> 4;
    int i0 = ty * 4;

    {   // h tile [64 edges][64 cols], thread 4x4 via f32x2
        int c0 = tx * 4;
        unsigned long long hh2[4][2];
#pragma unroll
        for (int a = 0; a < 4; a++) { hh2[a][0] = 0ull; hh2[a][1] = 0ull; }
#pragma unroll 4
        for (int k = 0; k < 32; k++) {
            float4 a0 = *(const float4*)&sRbfT[k * 68 + i0];
            ulonglong2 bq = *(const ulonglong2*)&s_rW1[k * 64 + c0];
            float av[4] = {a0.x, a0.y, a0.z, a0.w};
#pragma unroll
            for (int a = 0; a < 4; a++) {
                unsigned long long aa = pack2(av[a], av[a]);
                fma2(hh2[a][0], aa, bq.x);
                fma2(hh2[a][1], aa, bq.y);
            }
        }
#pragma unroll
        for (int a = 0; a < 4; a++) {
            float hv[4];
            unpack2(hh2[a][0], hv[0], hv[1]);
            unpack2(hh2[a][1], hv[2], hv[3]);
#pragma unroll
            for (int b = 0; b < 4; b++) {
                float v = hv[b] + s_rb1[c0 + b];
                v = v / (1.f + expf(-v));      // silu
                sHT[(c0 + b) * 68 + (i0 + a)] = v;
            }
        }
    }
    __syncthreads();

    {   // r tile [64][192], thread 4x12 via f32x2; rW2 staged in 2 k-chunks of 32
        int j0 = tx * 12;
        unsigned long long acc2[4][6];
#pragma unroll
        for (int a = 0; a < 4; a++)
#pragma unroll
            for (int b = 0; b < 6; b++) acc2[a][b] = 0ull;

#pragma unroll
        for (int c = 0; c < 2; c++) {
            if (c) __syncthreads();   // previous chunk's compute done before overwrite
            for (int q = t; q < 1536; q += 256)
                ((float4*)s_rW2)[q] = ((const float4*)(rW2b + c * 32 * 192))[q];
            __syncthreads();
#pragma unroll 4
            for (int kk = 0; kk < 32; kk++) {
                int k = c * 32 + kk;
                float4 a0 = *(const float4*)&sHT[k * 68 + i0];
                const float* br = &s_rW2[kk * 192 + j0];
                ulonglong2 q0 = ((const ulonglong2*)br)[0];
                ulonglong2 q1 = ((const ulonglong2*)br)[1];
                ulonglong2 q2 = ((const ulonglong2*)br)[2];
                unsigned long long bb2[6] = {q0.x, q0.y, q1.x, q1.y, q2.x, q2.y};
                float av[4] = {a0.x, a0.y, a0.z, a0.w};
#pragma unroll
                for (int a = 0; a < 4; a++) {
                    unsigned long long aa = pack2(av[a], av[a]);
#pragma unroll
                    for (int b = 0; b < 6; b++) fma2(acc2[a][b], aa, bb2[b]);
                }
            }
        }

        float rb[12];
#pragma unroll
        for (int b = 0; b < 12; b++) rb[b] = s_rb2[j0 + b];
#pragma unroll
        for (int a = 0; a < 4; a++) {
            float accs[12];
#pragma unroll
            for (int b = 0; b < 6; b++) unpack2(acc2[a][b], accs[2 * b], accs[2 * b + 1]);
            float f = sFcut[i0 + a];
            const float* pr = g_P + (size_t)s_src[i0 + a] * W3 + j0;
            float* wout = g_w + (size_t)(e0 + i0 + a) * W3 + j0;
#pragma unroll
            for (int g = 0; g < 3; g++) {
                float4 p = *(const float4*)(pr + g * 4);
                float4 v;
                v.x = (accs[g * 4 + 0] + rb[g * 4 + 0]) * f * p.x;
                v.y = (accs[g * 4 + 1] + rb[g * 4 + 1]) * f * p.y;
                v.z = (accs[g * 4 + 2] + rb[g * 4 + 2]) * f * p.z;
                v.w = (accs[g * 4 + 3] + rb[g * 4 + 3]) * f * p.w;
                *(float4*)(wout + g * 4) = v;
            }
        }
    }
}

// ---------------- segment sum (perm-gathered g_w rows) -> g_m ----------------
__global__ void __launch_bounds__(192) k_seg() {
    int n = blockIdx.x;
    int t = threadIdx.x;
    int lo = g_off[n], hi = g_off[n + 1];
    float acc[5] = {0.f, 0.f, 0.f, 0.f, 0.f};
    for (int p = lo; p < hi; p++) {
        int e = g_perm[p];
        float w = g_w[(size_t)e * W3 + t];
        if (t < 64) {
            acc[0] += w;
        } else if (t < 128) {
            const float* sh = g_sh + (size_t)e * 9 + 1;
#pragma unroll
            for (int d = 0; d < 3; d++) acc[d] += w * sh[d];
        } else {
            const float* sh = g_sh + (size_t)e * 9 + 4;
#pragma unroll
            for (int d = 0; d < 5; d++) acc[d] += w * sh[d];
        }
    }
    float* mr = g_m + (size_t)n * 576;
    if (t < 64) {
        mr[t] = acc[0];
    } else if (t < 128) {
        int c = t - 64;
#pragma unroll
        for (int d = 0; d < 3; d++) mr[64 + c * 3 + d] = acc[d];
    } else {
        int c = t - 128;
#pragma unroll
        for (int d = 0; d < 5; d++) mr[256 + c * 5 + d] = acc[d];
    }
}

// ---------------- apply Wo + residual: x += rs * (m @ Wo), 16 nodes/CTA ----------------
#define OUT_SMEM_BYTES (23552 * 4)
__global__ void __launch_bounds__(256) k_out(const float* __restrict__ Wo0b,
                                             const float* __restrict__ Wo1b,
                                             const float* __restrict__ Wo2b,
                                             const float* __restrict__ res_scale, int b) {
    extern __shared__ float sm[];
    float* sW0 = sm;
    float* sW1 = sm + 8192;
    float* sW2 = sm + 12288;
    float* sM  = sm + 14336;
    int t = threadIdx.x;
    int n0 = blockIdx.x * 16;

    for (int q = t; q < 2048; q += 256) ((float4*)sW0)[q] = ((const float4*)Wo0b)[q];
    for (int q = t; q < 1024; q += 256) ((float4*)sW1)[q] = ((const float4*)Wo1b)[q];
    for (int q = t; q < 512;  q += 256) ((float4*)sW2)[q] = ((const float4*)Wo2b)[q];
    {
        const float4* mg = (const float4*)(g_m + (size_t)n0 * 576);
        for (int q = t; q < 2304; q += 256) ((float4*)sM)[q] = mg[q];
    }
    __syncthreads();

    float rs = res_scale[b];
    for (int idx = t; idx < 16 * 480; idx += 256) {
        int nl = idx / 480, o = idx - nl * 480;
        const float* m = sM + nl * 576;
        float u = 0.f;
        if (o < 128) {
#pragma unroll 8
            for (int k = 0; k < 64; k++) u += m[k] * sW0[k * 128 + o];
        } else if (o < 320) {
            int q = o - 128;
            int c = q / 3, d = q - c * 3;
#pragma unroll 8
            for (int k = 0; k < 64; k++) u += m[64 + k * 3 + d] * sW1[k * 64 + c];
        } else {
            int q = o - 320;
            int c = q / 5, d = q - c * 5;
#pragma unroll 8
            for (int k = 0; k < 64; k++) u += m[256 + k * 5 + d] * sW2[k * 32 + c];
        }
        g_x[(size_t)(n0 + nl) * DIMN + o] += rs * u;
    }
}

// ---------------- irrep RMS norm + mask -> out ----------------
__global__ void __launch_bounds__(256) k_norm(const float* __restrict__ mask,
                                              float* __restrict__ out) {
    __shared__ float r0[256], r1[256], r2[256];
    int n = blockIdx.x, t = threadIdx.x;
    const float* xr = g_x + (size_t)n * DIMN;
    float p0 = 0.f, p1 = 0.f, p2 = 0.f;
    for (int o = t; o < DIMN; o += 256) {
        float v = xr[o];
        float v2 = v * v;
        if (o < 128) p0 += v2;
        else if (o < 320) p1 += v2;
        else p2 += v2;
    }
    r0[t] = p0; r1[t] = p1; r2[t] = p2;
    __syncthreads();
    for (int s = 128; s > 0; s >>= 1) {
        if (t < s) { r0[t] += r0[t + s]; r1[t] += r1[t + s]; r2[t] += r2[t + s]; }
        __syncthreads();
    }
    float inv0 = 1.f / sqrtf(r0[0] / 128.f + 1e-6f);
    float inv1 = 1.f / sqrtf(r1[0] / 64.f + 1e-6f);
    float inv2 = 1.f / sqrtf(r2[0] / 32.f + 1e-6f);
    float m = mask[n];
    for (int o = t; o < DIMN; o += 256) {
        float inv = (o < 128) ? inv0 : ((o < 320) ? inv1 : inv2);
        out[(size_t)n * DIMN + o] = xr[o] * inv * m;
    }
}

// ---------------- launch ----------------
extern "C" void kernel_launch(void* const* d_in, const int* in_sizes, int n_in,
                              void* d_out, int out_size) {
    const int*   z         = (const int*)d_in[0];
    const float* mask      = (const float*)d_in[1];
    const int*   edge_src  = (const int*)d_in[2];
    const int*   edge_dst  = (const int*)d_in[3];
    const float* edge_w    = (const float*)d_in[4];
    const float* edge_vec  = (const float*)d_in[5];
    const float* z_emb     = (const float*)d_in[6];
    const float* W_in      = (const float*)d_in[7];
    const float* Wp        = (const float*)d_in[8];
    const float* rW1       = (const float*)d_in[9];
    const float* rb1       = (const float*)d_in[10];
    const float* rW2       = (const float*)d_in[11];
    const float* rb2       = (const float*)d_in[12];
    const float* Wo0       = (const float*)d_in[13];
    const float* Wo1       = (const float*)d_in[14];
    const float* Wo2       = (const float*)d_in[15];
    const float* res_scale = (const float*)d_in[16];
    float* out = (float*)d_out;

    cudaFuncSetAttribute(k_projnode, cudaFuncAttributeMaxDynamicSharedMemorySize, PROJN_SMEM_BYTES);
    cudaFuncSetAttribute(k_edge, cudaFuncAttributeMaxDynamicSharedMemorySize, EDGE_SMEM_BYTES);
    cudaFuncSetAttribute(k_out, cudaFuncAttributeMaxDynamicSharedMemorySize, OUT_SMEM_BYTES);

    // launch order keeps k_edge at index 3 (where the ncu capture window lands).
    k_setup<<<G_INIT + G_GEO + G_CNT, 256>>>(z, mask, z_emb, W_in, edge_w, edge_vec, edge_dst); // 0
    k_scan<<<1, 1024>>>();                                                                       // 1
    k_projnode<<<BN / 64, 256, PROJN_SMEM_BYTES>>>(Wp);                                          // 2
    k_edge<<<NE / EDGE_TILE, 256, EDGE_SMEM_BYTES>>>(rW1, rb1, rW2, rb2, edge_src);              // 3 <- ncu
    k_fill<<<NE / 256, 256>>>(edge_dst);                                                         // 4
    k_sortseg<<<BN / 8, 256>>>();                                                                // 5
    k_seg<<<BN, 192>>>();                                                                        // 6
    k_out<<<BN / 16, 256, OUT_SMEM_BYTES>>>(Wo0, Wo1, Wo2, res_scale, 0);                        // 7

    for (int b = 1; b < 3; b++) {
        k_projnode<<<BN / 64, 256, PROJN_SMEM_BYTES>>>(Wp + b * 128 * 192);
        k_edge<<<NE / EDGE_TILE, 256, EDGE_SMEM_BYTES>>>(rW1 + b * 32 * 64, rb1 + b * 64,
                                                         rW2 + b * 64 * 192, rb2 + b * 192,
                                                         edge_src);
        k_seg<<<BN, 192>>>();
        k_out<<<BN / 16, 256, OUT_SMEM_BYTES>>>(Wo0 + b * 64 * 128, Wo1 + b * 64 * 64,
                                                Wo2 + b * 64 * 32, res_scale, b);
    }
    k_norm<<<BN, 256>>>(mask, out);
}

// round 9
// speedup vs baseline: 1.0463x; 1.0463x over previous
#include <cuda_runtime.h>
#include <cuda_bf16.h>
#include <math.h>
#include <stdint.h>

// ---------------- problem constants ----------------
#define BN    4096          // nodes (B*N)
#define NE    131072        // edges
#define DIMN  480           // 128 + 3*64 + 5*32
#define W3    192           // 3*MSG
#define RBFD  32
#define CUT   5.0f

// ---------------- packed f32x2 helpers ----------------
__device__ __forceinline__ unsigned long long pack2(float lo, float hi) {
    unsigned long long r;
    asm("mov.b64 %0, {%1, %2};" : "=l"(r) : "f"(lo), "f"(hi));
    return r;
}
__device__ __forceinline__ void unpack2(unsigned long long v, float& lo, float& hi) {
    asm("mov.b64 {%0, %1}, %2;" : "=f"(lo), "=f"(hi) : "l"(v));
}
__device__ __forceinline__ void fma2(unsigned long long& d, unsigned long long a,
                                     unsigned long long b) {
    asm("fma.rn.f32x2 %0, %1, %2, %3;" : "=l"(d) : "l"(a), "l"(b), "l"(d));
}

// ---------------- scratch (device globals; no allocation) ----------------
__device__ float g_x[BN * DIMN];                 // node features
__device__ float g_P[BN * W3];                   // per-node projection x[:, :128] @ Wp
__device__ float g_m[BN * 576];                  // per-node segment sums
__device__ float g_rbf[(size_t)NE * RBFD];       // per-edge rbf
__device__ float g_sh[(size_t)NE * 9];           // per-edge sph harmonics
__device__ float g_fcut[NE];                     // per-edge cutoff
__device__ float g_w[(size_t)NE * W3];           // per-EDGE message weights
__device__ int   g_cnt[BN];                      // zero-init at load; re-zeroed by k_scan
__device__ int   g_off[BN + 1];
__device__ int   g_cur[BN];
__device__ int   g_perm[NE];

// ---------------- fused setup: init (32 nodes/CTA) + geometry + count ----------------
#define G_INIT 128
#define G_GEO  512
#define G_CNT  512
__global__ void __launch_bounds__(256) k_setup(const int* __restrict__ z,
                                               const float* __restrict__ mask,
                                               const float* __restrict__ z_emb,
                                               const float* __restrict__ W_in,
                                               const float* __restrict__ ew,
                                               const float* __restrict__ evec,
                                               const int* __restrict__ dst) {
    int bx = blockIdx.x;
    int t = threadIdx.x;
    if (bx < G_INIT) {
        // ---- init: x0 = z_emb[z] @ W_in ----
        __shared__ float sZ[32 * 128];
        __shared__ int   sZi[32];
        __shared__ float sMk[32];
        int n0 = bx * 32;
        if (t < 32) { sZi[t] = z[n0 + t]; sMk[t] = mask[n0 + t]; }
        __syncthreads();
        for (int q = t; q < 32 * 128; q += 256) {
            int nl = q >> 7, k = q & 127;
            sZ[q] = z_emb[sZi[nl] * 128 + k];
        }
        __syncthreads();
        int j = t & 127, g = t >> 7;   // g in {0,1}: 16 nodes each
        float acc[16];
#pragma unroll
        for (int nn = 0; nn < 16; nn++) acc[nn] = 0.f;
#pragma unroll 4
        for (int k = 0; k < 128; k++) {
            float wv = W_in[k * 128 + j];
            const float* zr = &sZ[(g * 16) * 128 + k];
#pragma unroll
            for (int nn = 0; nn < 16; nn++) acc[nn] += zr[nn * 128] * wv;
        }
#pragma unroll
        for (int nn = 0; nn < 16; nn++) {
            int nl = g * 16 + nn;
            g_x[(size_t)(n0 + nl) * DIMN + j] = acc[nn] * sMk[nl];
        }
        for (int idx = t; idx < 32 * 352; idx += 256) {
            int nl = idx / 352, o = 128 + (idx - nl * 352);
            g_x[(size_t)(n0 + nl) * DIMN + o] = 0.f;
        }
    } else if (bx < G_INIT + G_GEO) {
        // ---- geometry ----
        int e = (bx - G_INIT) * 256 + t;
        float len = ew[e];
        float inv = 1.f / fmaxf(len, 1e-8f);
        float x = evec[e * 3 + 0] * inv;
        float y = evec[e * 3 + 1] * inv;
        float zc = evec[e * 3 + 2] * inv;
        float d = fminf(len, CUT);
        const float width = CUT / 31.f;
#pragma unroll
        for (int k = 0; k < RBFD; k++) {
            float c = CUT * (float)k / 31.f;
            float u = (d - c) / width;
            g_rbf[(size_t)e * RBFD + k] = expf(-0.5f * u * u);
        }
        const float s3 = 1.7320508075688772f;
        const float s5 = 2.2360679774997896f;
        const float s15 = 3.872983346207417f;
        float sh[9];
        sh[0] = 1.f;
        sh[1] = s3 * x; sh[2] = s3 * y; sh[3] = s3 * zc;
        sh[4] = s15 * x * y; sh[5] = s15 * y * zc;
        sh[6] = 0.5f * s5 * (3.f * zc * zc - 1.f);
        sh[7] = s15 * x * zc; sh[8] = 0.5f * s15 * (x * x - y * y);
#pragma unroll
        for (int j2 = 0; j2 < 9; j2++) g_sh[(size_t)e * 9 + j2] = sh[j2];
        float tt = fminf(len / CUT, 1.f);
        g_fcut[e] = 0.5f * (cosf(3.14159265358979323846f * tt) + 1.f);
    } else {
        // ---- count ----
        int e = (bx - G_INIT - G_GEO) * 256 + t;
        atomicAdd(&g_cnt[dst[e]], 1);
    }
}

// ---------------- scan (+ self-zero g_cnt for graph replay) ----------------
__global__ void k_scan() {
    __shared__ int part[1024];
    int t = threadIdx.x;
    int base = t * 4;
    int loc[4];
    int s = 0;
#pragma unroll
    for (int i = 0; i < 4; i++) { loc[i] = s; s += g_cnt[base + i]; }
    part[t] = s;
    __syncthreads();
    for (int off = 1; off < 1024; off <<= 1) {
        int v = (t >= off) ? part[t - off] : 0;
        __syncthreads();
        part[t] += v;
        __syncthreads();
    }
    int pre = (t == 0) ? 0 : part[t - 1];
#pragma unroll
    for (int i = 0; i < 4; i++) {
        g_off[base + i] = pre + loc[i];
        g_cur[base + i] = pre + loc[i];
        g_cnt[base + i] = 0;
    }
    if (t == 1023) g_off[BN] = part[1023];
}

__global__ void k_fill(const int* __restrict__ dst) {
    int e = blockIdx.x * 256 + threadIdx.x;
    if (e < NE) {
        int p = atomicAdd(&g_cur[dst[e]], 1);
        g_perm[p] = e;
    }
}

// ---------------- per-node deterministic sort (odd-even in smem, 1 warp/node) ----------------
#define SORT_CAP 1024
__global__ void __launch_bounds__(256) k_sortseg() {
    __shared__ int sbuf[8 * SORT_CAP];
    int warp = threadIdx.x >> 5, lane = threadIdx.x & 31;
    int n = blockIdx.x * 8 + warp;
    int lo = g_off[n], hi = g_off[n + 1];
    int len = hi - lo;
    int* buf = sbuf + warp * SORT_CAP;
    if (len <= 1) return;
    if (len <= SORT_CAP) {
        for (int i = lane; i < len; i += 32) buf[i] = g_perm[lo + i];
        __syncwarp();
        for (int r = 0; r < len; r++) {
            int st = r & 1;
            for (int i = st + 2 * lane; i + 1 < len; i += 64) {
                int a = buf[i], b = buf[i + 1];
                if (a > b) { buf[i] = b; buf[i + 1] = a; }
            }
            __syncwarp();
        }
        for (int i = lane; i < len; i += 32) g_perm[lo + i] = buf[i];
    } else if (lane == 0) {   // fallback (never expected at avg degree 32)
        for (int i = lo + 1; i < hi; i++) {
            int key = g_perm[i];
            int j = i - 1;
            while (j >= lo && g_perm[j] > key) { g_perm[j + 1] = g_perm[j]; j--; }
            g_perm[j + 1] = key;
        }
    }
}

// ---------------- per-node proj GEMM: g_P = x[:, :128] @ Wp[b]  (4096x192x128) ----------------
// Wp staged in smem with conflict-free swizzle: float4 (k, j4) stored at
// [(k*3 + j4%3)*16 + j4/3]  (j4 = j/4).  Read back: thread tx's g-th float4
// of row k is at [(k*3+g)*16 + tx]  -> 16 lanes read 256 contiguous bytes.
#define PROJN_SMEM_BYTES (33280 * 4)
__global__ void __launch_bounds__(256) k_projnode(const float* __restrict__ Wpb) {
    extern __shared__ float sm[];
    float* sAT = sm;          // [128][68]
    float* sWp = sm + 8704;   // [128*192] swizzled
    int t = threadIdx.x;
    int n0 = blockIdx.x * 64;

    {
        int i = t >> 2, q = t & 3;
        const float* xr = g_x + (size_t)(n0 + i) * DIMN + q * 32;
#pragma unroll
        for (int r = 0; r < 8; r++) {
            float4 v = *(const float4*)(xr + r * 4);
            int k = q * 32 + r * 4;
            sAT[(k + 0) * 68 + i] = v.x;
            sAT[(k + 1) * 68 + i] = v.y;
            sAT[(k + 2) * 68 + i] = v.z;
            sAT[(k + 3) * 68 + i] = v.w;
        }
    }
    for (int q = t; q < 6144; q += 256) {
        int k = q / 48, j4 = q - k * 48;
        int txp = j4 / 3, g = j4 - txp * 3;
        ((float4*)sWp)[(k * 3 + g) * 16 + txp] = ((const float4*)Wpb)[q];
    }
    __syncthreads();

    int tx = t & 15, ty = t >> 4;
    int i0 = ty * 4;
    unsigned long long acc2[4][6];
#pragma unroll
    for (int a = 0; a < 4; a++)
#pragma unroll
        for (int b = 0; b < 6; b++) acc2[a][b] = 0ull;

#pragma unroll 4
    for (int k = 0; k < 128; k++) {
        float4 a0 = *(const float4*)&sAT[k * 68 + i0];
        const float4* bbase = (const float4*)sWp + k * 48 + tx;
        float4 f0 = bbase[0];
        float4 f1 = bbase[16];
        float4 f2 = bbase[32];
        unsigned long long bb2[6];
        bb2[0] = pack2(f0.x, f0.y); bb2[1] = pack2(f0.z, f0.w);
        bb2[2] = pack2(f1.x, f1.y); bb2[3] = pack2(f1.z, f1.w);
        bb2[4] = pack2(f2.x, f2.y); bb2[5] = pack2(f2.z, f2.w);
        float av[4] = {a0.x, a0.y, a0.z, a0.w};
#pragma unroll
        for (int a = 0; a < 4; a++) {
            unsigned long long aa = pack2(av[a], av[a]);
#pragma unroll
            for (int b = 0; b < 6; b++) fma2(acc2[a][b], aa, bb2[b]);
        }
    }
    int j0 = tx * 12;
#pragma unroll
    for (int a = 0; a < 4; a++) {
        float accs[12];
#pragma unroll
        for (int b = 0; b < 6; b++) unpack2(acc2[a][b], accs[2 * b], accs[2 * b + 1]);
        float* pr = g_P + (size_t)(n0 + i0 + a) * W3 + j0;
#pragma unroll
        for (int g = 0; g < 3; g++) {
            float4 v;
            v.x = accs[g * 4 + 0]; v.y = accs[g * 4 + 1];
            v.z = accs[g * 4 + 2]; v.w = accs[g * 4 + 3];
            *(float4*)(pr + g * 4) = v;
        }
    }
}

// ---------------- per-edge: g_w[e] = P[src] * (silu(rbf@rW1+rb1)@rW2 + rb2) * fcut ----------
// 64 edges/CTA, 256 threads, 2 CTAs/SM (R7 config). rW2 in smem with the
// conflict-free swizzle described above. smem floats:
//   sRbfT [32][68] @0      2176
//   s_rW1 [32*64]  @2176   2048
//   sHT   [64][68] @4224   4352
//   s_rW2 [64*192] @8576   12288  (swizzled)
//   sFcut 64       @20864
//   s_rb1 64       @20928
//   s_rb2 192      @20992
//   s_src 64 (int) @21184   -> total 21248 floats = 84992 B
#define EDGE_TILE 64
#define EDGE_SMEM_BYTES (21248 * 4)
__global__ void __launch_bounds__(256, 2) k_edge(const float* __restrict__ rW1b,
                                                 const float* __restrict__ rb1b,
                                                 const float* __restrict__ rW2b,
                                                 const float* __restrict__ rb2b,
                                                 const int* __restrict__ esrc) {
    extern __shared__ float sm[];
    float* sRbfT = sm;
    float* s_rW1 = sm + 2176;
    float* sHT   = sm + 4224;
    float* s_rW2 = sm + 8576;
    float* sFcut = sm + 20864;
    float* s_rb1 = sm + 20928;
    float* s_rb2 = sm + 20992;
    int*   s_src = (int*)(sm + 21184);

    int t = threadIdx.x;
    int e0 = blockIdx.x * EDGE_TILE;

    {   // rbf tile transposed: 4 threads per edge row, 8 floats each
        int i = t >> 2, q = t & 3;
        const float4* r4 = (const float4*)(g_rbf + (size_t)(e0 + i) * RBFD + q * 8);
#pragma unroll
        for (int r = 0; r < 2; r++) {
            float4 v = r4[r];
            int k = q * 8 + r * 4;
            sRbfT[(k + 0) * 68 + i] = v.x;
            sRbfT[(k + 1) * 68 + i] = v.y;
            sRbfT[(k + 2) * 68 + i] = v.z;
            sRbfT[(k + 3) * 68 + i] = v.w;
        }
    }
    for (int q = t; q < 512; q += 256)  ((float4*)s_rW1)[q] = ((const float4*)rW1b)[q];
    for (int q = t; q < 3072; q += 256) {   // swizzled rW2 store
        int k = q / 48, j4 = q - k * 48;
        int txp = j4 / 3, g = j4 - txp * 3;
        ((float4*)s_rW2)[(k * 3 + g) * 16 + txp] = ((const float4*)rW2b)[q];
    }
    if (t < 64)  { sFcut[t] = g_fcut[e0 + t]; s_src[t] = esrc[e0 + t]; s_rb1[t] = rb1b[t]; }
    if (t >= 64 && t < 256) s_rb2[t - 64] = rb2b[t - 64];
    __syncthreads();

    int tx = t & 15, ty = t >> 4;
    int i0 = ty * 4;

    {   // h tile [64 edges][64 cols], thread 4x4 via f32x2
        int c0 = tx * 4;
        unsigned long long hh2[4][2];
#pragma unroll
        for (int a = 0; a < 4; a++) { hh2[a][0] = 0ull; hh2[a][1] = 0ull; }
#pragma unroll 4
        for (int k = 0; k < 32; k++) {
            float4 a0 = *(const float4*)&sRbfT[k * 68 + i0];
            ulonglong2 bq = *(const ulonglong2*)&s_rW1[k * 64 + c0];
            float av[4] = {a0.x, a0.y, a0.z, a0.w};
#pragma unroll
            for (int a = 0; a < 4; a++) {
                unsigned long long aa = pack2(av[a], av[a]);
                fma2(hh2[a][0], aa, bq.x);
                fma2(hh2[a][1], aa, bq.y);
            }
        }
#pragma unroll
        for (int a = 0; a < 4; a++) {
            float hv[4];
            unpack2(hh2[a][0], hv[0], hv[1]);
            unpack2(hh2[a][1], hv[2], hv[3]);
#pragma unroll
            for (int b = 0; b < 4; b++) {
                float v = hv[b] + s_rb1[c0 + b];
                v = v / (1.f + expf(-v));      // silu
                sHT[(c0 + b) * 68 + (i0 + a)] = v;
            }
        }
    }
    __syncthreads();

    {   // r tile [64][192], thread 4x12 via f32x2; swizzled B reads
        unsigned long long acc2[4][6];
#pragma unroll
        for (int a = 0; a < 4; a++)
#pragma unroll
            for (int b = 0; b < 6; b++) acc2[a][b] = 0ull;
#pragma unroll 4
        for (int k = 0; k < 64; k++) {
            float4 a0 = *(const float4*)&sHT[k * 68 + i0];
            const float4* bbase = (const float4*)s_rW2 + k * 48 + tx;
            float4 f0 = bbase[0];
            float4 f1 = bbase[16];
            float4 f2 = bbase[32];
            unsigned long long bb2[6];
            bb2[0] = pack2(f0.x, f0.y); bb2[1] = pack2(f0.z, f0.w);
            bb2[2] = pack2(f1.x, f1.y); bb2[3] = pack2(f1.z, f1.w);
            bb2[4] = pack2(f2.x, f2.y); bb2[5] = pack2(f2.z, f2.w);
            float av[4] = {a0.x, a0.y, a0.z, a0.w};
#pragma unroll
            for (int a = 0; a < 4; a++) {
                unsigned long long aa = pack2(av[a], av[a]);
#pragma unroll
                for (int b = 0; b < 6; b++) fma2(acc2[a][b], aa, bb2[b]);
            }
        }
        int j0 = tx * 12;
        float rb[12];
#pragma unroll
        for (int b = 0; b < 12; b++) rb[b] = s_rb2[j0 + b];
#pragma unroll
        for (int a = 0; a < 4; a++) {
            float accs[12];
#pragma unroll
            for (int b = 0; b < 6; b++) unpack2(acc2[a][b], accs[2 * b], accs[2 * b + 1]);
            float f = sFcut[i0 + a];
            const float* pr = g_P + (size_t)s_src[i0 + a] * W3 + j0;
            float* wout = g_w + (size_t)(e0 + i0 + a) * W3 + j0;
#pragma unroll
            for (int g = 0; g < 3; g++) {
                float4 p = *(const float4*)(pr + g * 4);
                float4 v;
                v.x = (accs[g * 4 + 0] + rb[g * 4 + 0]) * f * p.x;
                v.y = (accs[g * 4 + 1] + rb[g * 4 + 1]) * f * p.y;
                v.z = (accs[g * 4 + 2] + rb[g * 4 + 2]) * f * p.z;
                v.w = (accs[g * 4 + 3] + rb[g * 4 + 3]) * f * p.w;
                *(float4*)(wout + g * 4) = v;
            }
        }
    }
}

// ---------------- segment sum (perm-gathered g_w rows) -> g_m ----------------
__global__ void __launch_bounds__(192) k_seg() {
    int n = blockIdx.x;
    int t = threadIdx.x;
    int lo = g_off[n], hi = g_off[n + 1];
    float acc[5] = {0.f, 0.f, 0.f, 0.f, 0.f};
    for (int p = lo; p < hi; p++) {
        int e = g_perm[p];
        float w = g_w[(size_t)e * W3 + t];
        if (t < 64) {
            acc[0] += w;
        } else if (t < 128) {
            const float* sh = g_sh + (size_t)e * 9 + 1;
#pragma unroll
            for (int d = 0; d < 3; d++) acc[d] += w * sh[d];
        } else {
            const float* sh = g_sh + (size_t)e * 9 + 4;
#pragma unroll
            for (int d = 0; d < 5; d++) acc[d] += w * sh[d];
        }
    }
    float* mr = g_m + (size_t)n * 576;
    if (t < 64) {
        mr[t] = acc[0];
    } else if (t < 128) {
        int c = t - 64;
#pragma unroll
        for (int d = 0; d < 3; d++) mr[64 + c * 3 + d] = acc[d];
    } else {
        int c = t - 128;
#pragma unroll
        for (int d = 0; d < 5; d++) mr[256 + c * 5 + d] = acc[d];
    }
}

// ---------------- apply Wo + residual: x += rs * (m @ Wo), 16 nodes/CTA ----------------
#define OUT_SMEM_BYTES (23552 * 4)
__global__ void __launch_bounds__(256) k_out(const float* __restrict__ Wo0b,
                                             const float* __restrict__ Wo1b,
                                             const float* __restrict__ Wo2b,
                                             const float* __restrict__ res_scale, int b) {
    extern __shared__ float sm[];
    float* sW0 = sm;
    float* sW1 = sm + 8192;
    float* sW2 = sm + 12288;
    float* sM  = sm + 14336;
    int t = threadIdx.x;
    int n0 = blockIdx.x * 16;

    for (int q = t; q < 2048; q += 256) ((float4*)sW0)[q] = ((const float4*)Wo0b)[q];
    for (int q = t; q < 1024; q += 256) ((float4*)sW1)[q] = ((const float4*)Wo1b)[q];
    for (int q = t; q < 512;  q += 256) ((float4*)sW2)[q] = ((const float4*)Wo2b)[q];
    {
        const float4* mg = (const float4*)(g_m + (size_t)n0 * 576);
        for (int q = t; q < 2304; q += 256) ((float4*)sM)[q] = mg[q];
    }
    __syncthreads();

    float rs = res_scale[b];
    for (int idx = t; idx < 16 * 480; idx += 256) {
        int nl = idx / 480, o = idx - nl * 480;
        const float* m = sM + nl * 576;
        float u = 0.f;
        if (o < 128) {
#pragma unroll 8
            for (int k = 0; k < 64; k++) u += m[k] * sW0[k * 128 + o];
        } else if (o < 320) {
            int q = o - 128;
            int c = q / 3, d = q - c * 3;
#pragma unroll 8
            for (int k = 0; k < 64; k++) u += m[64 + k * 3 + d] * sW1[k * 64 + c];
        } else {
            int q = o - 320;
            int c = q / 5, d = q - c * 5;
#pragma unroll 8
            for (int k = 0; k < 64; k++) u += m[256 + k * 5 + d] * sW2[k * 32 + c];
        }
        g_x[(size_t)(n0 + nl) * DIMN + o] += rs * u;
    }
}

// ---------------- irrep RMS norm + mask -> out ----------------
__global__ void __launch_bounds__(256) k_norm(const float* __restrict__ mask,
                                              float* __restrict__ out) {
    __shared__ float r0[256], r1[256], r2[256];
    int n = blockIdx.x, t = threadIdx.x;
    const float* xr = g_x + (size_t)n * DIMN;
    float p0 = 0.f, p1 = 0.f, p2 = 0.f;
    for (int o = t; o < DIMN; o += 256) {
        float v = xr[o];
        float v2 = v * v;
        if (o < 128) p0 += v2;
        else if (o < 320) p1 += v2;
        else p2 += v2;
    }
    r0[t] = p0; r1[t] = p1; r2[t] = p2;
    __syncthreads();
    for (int s = 128; s > 0; s >>= 1) {
        if (t < s) { r0[t] += r0[t + s]; r1[t] += r1[t + s]; r2[t] += r2[t + s]; }
        __syncthreads();
    }
    float inv0 = 1.f / sqrtf(r0[0] / 128.f + 1e-6f);
    float inv1 = 1.f / sqrtf(r1[0] / 64.f + 1e-6f);
    float inv2 = 1.f / sqrtf(r2[0] / 32.f + 1e-6f);
    float m = mask[n];
    for (int o = t; o < DIMN; o += 256) {
        float inv = (o < 128) ? inv0 : ((o < 320) ? inv1 : inv2);
        out[(size_t)n * DIMN + o] = xr[o] * inv * m;
    }
}

// ---------------- launch ----------------
extern "C" void kernel_launch(void* const* d_in, const int* in_sizes, int n_in,
                              void* d_out, int out_size) {
    const int*   z         = (const int*)d_in[0];
    const float* mask      = (const float*)d_in[1];
    const int*   edge_src  = (const int*)d_in[2];
    const int*   edge_dst  = (const int*)d_in[3];
    const float* edge_w    = (const float*)d_in[4];
    const float* edge_vec  = (const float*)d_in[5];
    const float* z_emb     = (const float*)d_in[6];
    const float* W_in      = (const float*)d_in[7];
    const float* Wp        = (const float*)d_in[8];
    const float* rW1       = (const float*)d_in[9];
    const float* rb1       = (const float*)d_in[10];
    const float* rW2       = (const float*)d_in[11];
    const float* rb2       = (const float*)d_in[12];
    const float* Wo0       = (const float*)d_in[13];
    const float* Wo1       = (const float*)d_in[14];
    const float* Wo2       = (const float*)d_in[15];
    const float* res_scale = (const float*)d_in[16];
    float* out = (float*)d_out;

    cudaFuncSetAttribute(k_projnode, cudaFuncAttributeMaxDynamicSharedMemorySize, PROJN_SMEM_BYTES);
    cudaFuncSetAttribute(k_edge, cudaFuncAttributeMaxDynamicSharedMemorySize, EDGE_SMEM_BYTES);
    cudaFuncSetAttribute(k_out, cudaFuncAttributeMaxDynamicSharedMemorySize, OUT_SMEM_BYTES);

    // launch order keeps k_edge at index 3 (where the ncu capture window lands).
    k_setup<<<G_INIT + G_GEO + G_CNT, 256>>>(z, mask, z_emb, W_in, edge_w, edge_vec, edge_dst); // 0
    k_scan<<<1, 1024>>>();                                                                       // 1
    k_projnode<<<BN / 64, 256, PROJN_SMEM_BYTES>>>(Wp);                                          // 2
    k_edge<<<NE / EDGE_TILE, 256, EDGE_SMEM_BYTES>>>(rW1, rb1, rW2, rb2, edge_src);              // 3 <- ncu
    k_fill<<<NE / 256, 256>>>(edge_dst);                                                         // 4
    k_sortseg<<<BN / 8, 256>>>();                                                                // 5
    k_seg<<<BN, 192>>>();                                                                        // 6
    k_out<<<BN / 16, 256, OUT_SMEM_BYTES>>>(Wo0, Wo1, Wo2, res_scale, 0);                        // 7

    for (int b = 1; b < 3; b++) {
        k_projnode<<<BN / 64, 256, PROJN_SMEM_BYTES>>>(Wp + b * 128 * 192);
        k_edge<<<NE / EDGE_TILE, 256, EDGE_SMEM_BYTES>>>(rW1 + b * 32 * 64, rb1 + b * 64,
                                                         rW2 + b * 64 * 192, rb2 + b * 192,
                                                         edge_src);
        k_seg<<<BN, 192>>>();
        k_out<<<BN / 16, 256, OUT_SMEM_BYTES>>>(Wo0 + b * 64 * 128, Wo1 + b * 64 * 64,
                                                Wo2 + b * 64 * 32, res_scale, b);
    }
    k_norm<<<BN, 256>>>(mask, out);
}

// round 10
// speedup vs baseline: 1.8234x; 1.7427x over previous
#include <cuda_runtime.h>
#include <cuda_bf16.h>
#include <math.h>
#include <stdint.h>

// ---------------- problem constants ----------------
#define BN    4096          // nodes (B*N)
#define NE    131072        // edges
#define DIMN  480           // 128 + 3*64 + 5*32
#define W3    192           // 3*MSG
#define RBFD  32
#define CUT   5.0f
#define NT    8192          // radial table resolution
#define TSTEP (CUT / (float)(NT - 1))
#define TSCALE ((float)(NT - 1) / CUT)

// ---------------- packed f32x2 helpers ----------------
__device__ __forceinline__ unsigned long long pack2(float lo, float hi) {
    unsigned long long r;
    asm("mov.b64 %0, {%1, %2};" : "=l"(r) : "f"(lo), "f"(hi));
    return r;
}
__device__ __forceinline__ void unpack2(unsigned long long v, float& lo, float& hi) {
    asm("mov.b64 {%0, %1}, %2;" : "=f"(lo), "=f"(hi) : "l"(v));
}
__device__ __forceinline__ void fma2(unsigned long long& d, unsigned long long a,
                                     unsigned long long b) {
    asm("fma.rn.f32x2 %0, %1, %2, %3;" : "=l"(d) : "l"(a), "l"(b), "l"(d));
}

// ---------------- scratch (device globals; no allocation) ----------------
__device__ float g_x[BN * DIMN];                 // node features
__device__ float g_P[BN * W3];                   // per-node projection x[:, :128] @ Wp
__device__ float g_m[BN * 576];                  // per-node segment sums
__device__ float g_sh[(size_t)NE * 9];           // per-edge sph harmonics
__device__ float g_table[(size_t)NT * W3];       // radial table F(d)=fcut*(r+rb2), per block
__device__ int   g_cnt[BN];                      // zero-init at load; re-zeroed by k_scan
__device__ int   g_off[BN + 1];
__device__ int   g_cur[BN];
__device__ int   g_perm[NE];

// ---------------- fused setup: init (32 nodes/CTA) + geometry (sh only) + count ----------------
#define G_INIT 128
#define G_GEO  512
#define G_CNT  512
__global__ void __launch_bounds__(256) k_setup(const int* __restrict__ z,
                                               const float* __restrict__ mask,
                                               const float* __restrict__ z_emb,
                                               const float* __restrict__ W_in,
                                               const float* __restrict__ ew,
                                               const float* __restrict__ evec,
                                               const int* __restrict__ dst) {
    int bx = blockIdx.x;
    int t = threadIdx.x;
    if (bx < G_INIT) {
        // ---- init: x0 = z_emb[z] @ W_in ----
        __shared__ float sZ[32 * 128];
        __shared__ int   sZi[32];
        __shared__ float sMk[32];
        int n0 = bx * 32;
        if (t < 32) { sZi[t] = z[n0 + t]; sMk[t] = mask[n0 + t]; }
        __syncthreads();
        for (int q = t; q < 32 * 128; q += 256) {
            int nl = q >> 7, k = q & 127;
            sZ[q] = z_emb[sZi[nl] * 128 + k];
        }
        __syncthreads();
        int j = t & 127, g = t >> 7;   // g in {0,1}: 16 nodes each
        float acc[16];
#pragma unroll
        for (int nn = 0; nn < 16; nn++) acc[nn] = 0.f;
#pragma unroll 4
        for (int k = 0; k < 128; k++) {
            float wv = W_in[k * 128 + j];
            const float* zr = &sZ[(g * 16) * 128 + k];
#pragma unroll
            for (int nn = 0; nn < 16; nn++) acc[nn] += zr[nn * 128] * wv;
        }
#pragma unroll
        for (int nn = 0; nn < 16; nn++) {
            int nl = g * 16 + nn;
            g_x[(size_t)(n0 + nl) * DIMN + j] = acc[nn] * sMk[nl];
        }
        for (int idx = t; idx < 32 * 352; idx += 256) {
            int nl = idx / 352, o = 128 + (idx - nl * 352);
            g_x[(size_t)(n0 + nl) * DIMN + o] = 0.f;
        }
    } else if (bx < G_INIT + G_GEO) {
        // ---- geometry: spherical harmonics only ----
        int e = (bx - G_INIT) * 256 + t;
        float len = ew[e];
        float inv = 1.f / fmaxf(len, 1e-8f);
        float x = evec[e * 3 + 0] * inv;
        float y = evec[e * 3 + 1] * inv;
        float zc = evec[e * 3 + 2] * inv;
        const float s3 = 1.7320508075688772f;
        const float s5 = 2.2360679774997896f;
        const float s15 = 3.872983346207417f;
        float sh[9];
        sh[0] = 1.f;
        sh[1] = s3 * x; sh[2] = s3 * y; sh[3] = s3 * zc;
        sh[4] = s15 * x * y; sh[5] = s15 * y * zc;
        sh[6] = 0.5f * s5 * (3.f * zc * zc - 1.f);
        sh[7] = s15 * x * zc; sh[8] = 0.5f * s15 * (x * x - y * y);
#pragma unroll
        for (int j2 = 0; j2 < 9; j2++) g_sh[(size_t)e * 9 + j2] = sh[j2];
    } else {
        // ---- count ----
        int e = (bx - G_INIT - G_GEO) * 256 + t;
        atomicAdd(&g_cnt[dst[e]], 1);
    }
}

// ---------------- scan (+ self-zero g_cnt for graph replay) ----------------
__global__ void k_scan() {
    __shared__ int part[1024];
    int t = threadIdx.x;
    int base = t * 4;
    int loc[4];
    int s = 0;
#pragma unroll
    for (int i = 0; i < 4; i++) { loc[i] = s; s += g_cnt[base + i]; }
    part[t] = s;
    __syncthreads();
    for (int off = 1; off < 1024; off <<= 1) {
        int v = (t >= off) ? part[t - off] : 0;
        __syncthreads();
        part[t] += v;
        __syncthreads();
    }
    int pre = (t == 0) ? 0 : part[t - 1];
#pragma unroll
    for (int i = 0; i < 4; i++) {
        g_off[base + i] = pre + loc[i];
        g_cur[base + i] = pre + loc[i];
        g_cnt[base + i] = 0;
    }
    if (t == 1023) g_off[BN] = part[1023];
}

__global__ void k_fill(const int* __restrict__ dst) {
    int e = blockIdx.x * 256 + threadIdx.x;
    if (e < NE) {
        int p = atomicAdd(&g_cur[dst[e]], 1);
        g_perm[p] = e;
    }
}

// ---------------- per-node deterministic sort (odd-even in smem, 1 warp/node) ----------------
#define SORT_CAP 1024
__global__ void __launch_bounds__(256) k_sortseg() {
    __shared__ int sbuf[8 * SORT_CAP];
    int warp = threadIdx.x >> 5, lane = threadIdx.x & 31;
    int n = blockIdx.x * 8 + warp;
    int lo = g_off[n], hi = g_off[n + 1];
    int len = hi - lo;
    int* buf = sbuf + warp * SORT_CAP;
    if (len <= 1) return;
    if (len <= SORT_CAP) {
        for (int i = lane; i < len; i += 32) buf[i] = g_perm[lo + i];
        __syncwarp();
        for (int r = 0; r < len; r++) {
            int st = r & 1;
            for (int i = st + 2 * lane; i + 1 < len; i += 64) {
                int a = buf[i], b = buf[i + 1];
                if (a > b) { buf[i] = b; buf[i + 1] = a; }
            }
            __syncwarp();
        }
        for (int i = lane; i < len; i += 32) g_perm[lo + i] = buf[i];
    } else if (lane == 0) {   // fallback (never expected at avg degree 32)
        for (int i = lo + 1; i < hi; i++) {
            int key = g_perm[i];
            int j = i - 1;
            while (j >= lo && g_perm[j] > key) { g_perm[j + 1] = g_perm[j]; j--; }
            g_perm[j + 1] = key;
        }
    }
}

// ---------------- per-node proj GEMM: g_P = x[:, :128] @ Wp[b]  (4096x192x128) ----------------
// Wp staged in smem with conflict-free swizzle (see k_table for read pattern).
#define PROJN_SMEM_BYTES (33280 * 4)
__global__ void __launch_bounds__(256) k_projnode(const float* __restrict__ Wpb) {
    extern __shared__ float sm[];
    float* sAT = sm;          // [128][68]
    float* sWp = sm + 8704;   // [128*192] swizzled
    int t = threadIdx.x;
    int n0 = blockIdx.x * 64;

    {
        int i = t >> 2, q = t & 3;
        const float* xr = g_x + (size_t)(n0 + i) * DIMN + q * 32;
#pragma unroll
        for (int r = 0; r < 8; r++) {
            float4 v = *(const float4*)(xr + r * 4);
            int k = q * 32 + r * 4;
            sAT[(k + 0) * 68 + i] = v.x;
            sAT[(k + 1) * 68 + i] = v.y;
            sAT[(k + 2) * 68 + i] = v.z;
            sAT[(k + 3) * 68 + i] = v.w;
        }
    }
    for (int q = t; q < 6144; q += 256) {
        int k = q / 48, j4 = q - k * 48;
        int txp = j4 / 3, g = j4 - txp * 3;
        ((float4*)sWp)[(k * 3 + g) * 16 + txp] = ((const float4*)Wpb)[q];
    }
    __syncthreads();

    int tx = t & 15, ty = t >> 4;
    int i0 = ty * 4;
    unsigned long long acc2[4][6];
#pragma unroll
    for (int a = 0; a < 4; a++)
#pragma unroll
        for (int b = 0; b < 6; b++) acc2[a][b] = 0ull;

#pragma unroll 4
    for (int k = 0; k < 128; k++) {
        float4 a0 = *(const float4*)&sAT[k * 68 + i0];
        const float4* bbase = (const float4*)sWp + k * 48 + tx;
        float4 f0 = bbase[0];
        float4 f1 = bbase[16];
        float4 f2 = bbase[32];
        unsigned long long bb2[6];
        bb2[0] = pack2(f0.x, f0.y); bb2[1] = pack2(f0.z, f0.w);
        bb2[2] = pack2(f1.x, f1.y); bb2[3] = pack2(f1.z, f1.w);
        bb2[4] = pack2(f2.x, f2.y); bb2[5] = pack2(f2.z, f2.w);
        float av[4] = {a0.x, a0.y, a0.z, a0.w};
#pragma unroll
        for (int a = 0; a < 4; a++) {
            unsigned long long aa = pack2(av[a], av[a]);
#pragma unroll
            for (int b = 0; b < 6; b++) fma2(acc2[a][b], aa, bb2[b]);
        }
    }
    int j0 = tx * 12;
#pragma unroll
    for (int a = 0; a < 4; a++) {
        float accs[12];
#pragma unroll
        for (int b = 0; b < 6; b++) unpack2(acc2[a][b], accs[2 * b], accs[2 * b + 1]);
        float* pr = g_P + (size_t)(n0 + i0 + a) * W3 + j0;
#pragma unroll
        for (int g = 0; g < 3; g++) {
            float4 v;
            v.x = accs[g * 4 + 0]; v.y = accs[g * 4 + 1];
            v.z = accs[g * 4 + 2]; v.w = accs[g * 4 + 3];
            *(float4*)(pr + g * 4) = v;
        }
    }
}

// ---------------- radial table: g_table[i] = fcut(d_i)*(silu(rbf(d_i)@rW1+rb1)@rW2 + rb2) ----
// 64 rows/CTA, 256 threads, grid NT/64 = 128. Same GEMM structure as the old k_edge.
#define TBL_SMEM_BYTES (21184 * 4)
__global__ void __launch_bounds__(256, 2) k_table(const float* __restrict__ rW1b,
                                                  const float* __restrict__ rb1b,
                                                  const float* __restrict__ rW2b,
                                                  const float* __restrict__ rb2b) {
    extern __shared__ float sm[];
    float* sRbfT = sm;           // [32][68]
    float* s_rW1 = sm + 2176;    // [32*64]
    float* sHT   = sm + 4224;    // [64][68]
    float* s_rW2 = sm + 8576;    // [64*192] swizzled
    float* sFcut = sm + 20864;   // [64]
    float* s_rb1 = sm + 20928;   // [64]
    float* s_rb2 = sm + 20992;   // [192]

    int t = threadIdx.x;
    int r0 = blockIdx.x * 64;    // table row base

    {   // rbf for 64 grid points, stored transposed
        int i = t >> 2, q = t & 3;
        float d = (float)(r0 + i) * TSTEP;
        float dm = fminf(d, CUT);
        const float width = CUT / 31.f;
#pragma unroll
        for (int r = 0; r < 8; r++) {
            int k = q * 8 + r;
            float c = CUT * (float)k / 31.f;
            float u = (dm - c) / width;
            sRbfT[k * 68 + i] = expf(-0.5f * u * u);
        }
    }
    for (int q = t; q < 512; q += 256)  ((float4*)s_rW1)[q] = ((const float4*)rW1b)[q];
    for (int q = t; q < 3072; q += 256) {   // swizzled rW2 store
        int k = q / 48, j4 = q - k * 48;
        int txp = j4 / 3, g = j4 - txp * 3;
        ((float4*)s_rW2)[(k * 3 + g) * 16 + txp] = ((const float4*)rW2b)[q];
    }
    if (t < 64) {
        float d = (float)(r0 + t) * TSTEP;
        float tt = fminf(d / CUT, 1.f);
        sFcut[t] = 0.5f * (cosf(3.14159265358979323846f * tt) + 1.f);
        s_rb1[t] = rb1b[t];
    }
    if (t >= 64 && t < 256) s_rb2[t - 64] = rb2b[t - 64];
    __syncthreads();

    int tx = t & 15, ty = t >> 4;
    int i0 = ty * 4;

    {   // h tile [64 rows][64 cols], thread 4x4 via f32x2
        int c0 = tx * 4;
        unsigned long long hh2[4][2];
#pragma unroll
        for (int a = 0; a < 4; a++) { hh2[a][0] = 0ull; hh2[a][1] = 0ull; }
#pragma unroll 4
        for (int k = 0; k < 32; k++) {
            float4 a0 = *(const float4*)&sRbfT[k * 68 + i0];
            ulonglong2 bq = *(const ulonglong2*)&s_rW1[k * 64 + c0];
            float av[4] = {a0.x, a0.y, a0.z, a0.w};
#pragma unroll
            for (int a = 0; a < 4; a++) {
                unsigned long long aa = pack2(av[a], av[a]);
                fma2(hh2[a][0], aa, bq.x);
                fma2(hh2[a][1], aa, bq.y);
            }
        }
#pragma unroll
        for (int a = 0; a < 4; a++) {
            float hv[4];
            unpack2(hh2[a][0], hv[0], hv[1]);
            unpack2(hh2[a][1], hv[2], hv[3]);
#pragma unroll
            for (int b = 0; b < 4; b++) {
                float v = hv[b] + s_rb1[c0 + b];
                v = v / (1.f + expf(-v));      // silu
                sHT[(c0 + b) * 68 + (i0 + a)] = v;
            }
        }
    }
    __syncthreads();

    {   // r tile [64][192], thread 4x12 via f32x2; write fcut*(r+rb2) to table
        unsigned long long acc2[4][6];
#pragma unroll
        for (int a = 0; a < 4; a++)
#pragma unroll
            for (int b = 0; b < 6; b++) acc2[a][b] = 0ull;
#pragma unroll 4
        for (int k = 0; k < 64; k++) {
            float4 a0 = *(const float4*)&sHT[k * 68 + i0];
            const float4* bbase = (const float4*)s_rW2 + k * 48 + tx;
            float4 f0 = bbase[0];
            float4 f1 = bbase[16];
            float4 f2 = bbase[32];
            unsigned long long bb2[6];
            bb2[0] = pack2(f0.x, f0.y); bb2[1] = pack2(f0.z, f0.w);
            bb2[2] = pack2(f1.x, f1.y); bb2[3] = pack2(f1.z, f1.w);
            bb2[4] = pack2(f2.x, f2.y); bb2[5] = pack2(f2.z, f2.w);
            float av[4] = {a0.x, a0.y, a0.z, a0.w};
#pragma unroll
            for (int a = 0; a < 4; a++) {
                unsigned long long aa = pack2(av[a], av[a]);
#pragma unroll
                for (int b = 0; b < 6; b++) fma2(acc2[a][b], aa, bb2[b]);
            }
        }
        int j0 = tx * 12;
        float rb[12];
#pragma unroll
        for (int b = 0; b < 12; b++) rb[b] = s_rb2[j0 + b];
#pragma unroll
        for (int a = 0; a < 4; a++) {
            float accs[12];
#pragma unroll
            for (int b = 0; b < 6; b++) unpack2(acc2[a][b], accs[2 * b], accs[2 * b + 1]);
            float fc = sFcut[i0 + a];
            float* outp = g_table + (size_t)(r0 + i0 + a) * W3 + j0;
#pragma unroll
            for (int g = 0; g < 3; g++) {
                float4 v;
                v.x = (accs[g * 4 + 0] + rb[g * 4 + 0]) * fc;
                v.y = (accs[g * 4 + 1] + rb[g * 4 + 1]) * fc;
                v.z = (accs[g * 4 + 2] + rb[g * 4 + 2]) * fc;
                v.w = (accs[g * 4 + 3] + rb[g * 4 + 3]) * fc;
                *(float4*)(outp + g * 4) = v;
            }
        }
    }
}

// ---------------- fused segment sum: w = P[src] * lerp(table, d); accumulate with sh -> g_m ----
__global__ void __launch_bounds__(192) k_seg(const float* __restrict__ ew,
                                             const int* __restrict__ esrc) {
    int n = blockIdx.x;
    int t = threadIdx.x;
    int lo = g_off[n], hi = g_off[n + 1];
    float acc[5] = {0.f, 0.f, 0.f, 0.f, 0.f};
    if (lo < hi) {
        int e = g_perm[lo];
        float d = ew[e];
        int src = esrc[e];
        for (int p = lo; p < hi; p++) {
            int e_cur = e;
            float d_cur = d;
            int src_cur = src;
            if (p + 1 < hi) {            // prefetch next edge's scalars
                e = g_perm[p + 1];
                d = ew[e];
                src = esrc[e];
            }
            float x = fminf(d_cur, CUT) * TSCALE;
            int i = (int)x;
            if (i > NT - 2) i = NT - 2;
            float f = x - (float)i;
            float T0 = g_table[(size_t)i * W3 + t];
            float T1 = g_table[(size_t)(i + 1) * W3 + t];
            float w = g_P[(size_t)src_cur * W3 + t] * (T0 + f * (T1 - T0));
            if (t < 64) {
                acc[0] += w;
            } else if (t < 128) {
                const float* sh = g_sh + (size_t)e_cur * 9 + 1;
#pragma unroll
                for (int dd = 0; dd < 3; dd++) acc[dd] += w * sh[dd];
            } else {
                const float* sh = g_sh + (size_t)e_cur * 9 + 4;
#pragma unroll
                for (int dd = 0; dd < 5; dd++) acc[dd] += w * sh[dd];
            }
        }
    }
    float* mr = g_m + (size_t)n * 576;
    if (t < 64) {
        mr[t] = acc[0];
    } else if (t < 128) {
        int c = t - 64;
#pragma unroll
        for (int d = 0; d < 3; d++) mr[64 + c * 3 + d] = acc[d];
    } else {
        int c = t - 128;
#pragma unroll
        for (int d = 0; d < 5; d++) mr[256 + c * 5 + d] = acc[d];
    }
}

// ---------------- apply Wo + residual: x += rs * (m @ Wo), 16 nodes/CTA ----------------
#define OUT_SMEM_BYTES (23552 * 4)
__global__ void __launch_bounds__(256) k_out(const float* __restrict__ Wo0b,
                                             const float* __restrict__ Wo1b,
                                             const float* __restrict__ Wo2b,
                                             const float* __restrict__ res_scale, int b) {
    extern __shared__ float sm[];
    float* sW0 = sm;
    float* sW1 = sm + 8192;
    float* sW2 = sm + 12288;
    float* sM  = sm + 14336;
    int t = threadIdx.x;
    int n0 = blockIdx.x * 16;

    for (int q = t; q < 2048; q += 256) ((float4*)sW0)[q] = ((const float4*)Wo0b)[q];
    for (int q = t; q < 1024; q += 256) ((float4*)sW1)[q] = ((const float4*)Wo1b)[q];
    for (int q = t; q < 512;  q += 256) ((float4*)sW2)[q] = ((const float4*)Wo2b)[q];
    {
        const float4* mg = (const float4*)(g_m + (size_t)n0 * 576);
        for (int q = t; q < 2304; q += 256) ((float4*)sM)[q] = mg[q];
    }
    __syncthreads();

    float rs = res_scale[b];
    for (int idx = t; idx < 16 * 480; idx += 256) {
        int nl = idx / 480, o = idx - nl * 480;
        const float* m = sM + nl * 576;
        float u = 0.f;
        if (o < 128) {
#pragma unroll 8
            for (int k = 0; k < 64; k++) u += m[k] * sW0[k * 128 + o];
        } else if (o < 320) {
            int q = o - 128;
            int c = q / 3, d = q - c * 3;
#pragma unroll 8
            for (int k = 0; k < 64; k++) u += m[64 + k * 3 + d] * sW1[k * 64 + c];
        } else {
            int q = o - 320;
            int c = q / 5, d = q - c * 5;
#pragma unroll 8
            for (int k = 0; k < 64; k++) u += m[256 + k * 5 + d] * sW2[k * 32 + c];
        }
        g_x[(size_t)(n0 + nl) * DIMN + o] += rs * u;
    }
}

// ---------------- irrep RMS norm + mask -> out ----------------
__global__ void __launch_bounds__(256) k_norm(const float* __restrict__ mask,
                                              float* __restrict__ out) {
    __shared__ float r0[256], r1[256], r2[256];
    int n = blockIdx.x, t = threadIdx.x;
    const float* xr = g_x + (size_t)n * DIMN;
    float p0 = 0.f, p1 = 0.f, p2 = 0.f;
    for (int o = t; o < DIMN; o += 256) {
        float v = xr[o];
        float v2 = v * v;
        if (o < 128) p0 += v2;
        else if (o < 320) p1 += v2;
        else p2 += v2;
    }
    r0[t] = p0; r1[t] = p1; r2[t] = p2;
    __syncthreads();
    for (int s = 128; s > 0; s >>= 1) {
        if (t < s) { r0[t] += r0[t + s]; r1[t] += r1[t + s]; r2[t] += r2[t + s]; }
        __syncthreads();
    }
    float inv0 = 1.f / sqrtf(r0[0] / 128.f + 1e-6f);
    float inv1 = 1.f / sqrtf(r1[0] / 64.f + 1e-6f);
    float inv2 = 1.f / sqrtf(r2[0] / 32.f + 1e-6f);
    float m = mask[n];
    for (int o = t; o < DIMN; o += 256) {
        float inv = (o < 128) ? inv0 : ((o < 320) ? inv1 : inv2);
        out[(size_t)n * DIMN + o] = xr[o] * inv * m;
    }
}

// ---------------- launch ----------------
extern "C" void kernel_launch(void* const* d_in, const int* in_sizes, int n_in,
                              void* d_out, int out_size) {
    const int*   z         = (const int*)d_in[0];
    const float* mask      = (const float*)d_in[1];
    const int*   edge_src  = (const int*)d_in[2];
    const int*   edge_dst  = (const int*)d_in[3];
    const float* edge_w    = (const float*)d_in[4];
    const float* edge_vec  = (const float*)d_in[5];
    const float* z_emb     = (const float*)d_in[6];
    const float* W_in      = (const float*)d_in[7];
    const float* Wp        = (const float*)d_in[8];
    const float* rW1       = (const float*)d_in[9];
    const float* rb1       = (const float*)d_in[10];
    const float* rW2       = (const float*)d_in[11];
    const float* rb2       = (const float*)d_in[12];
    const float* Wo0       = (const float*)d_in[13];
    const float* Wo1       = (const float*)d_in[14];
    const float* Wo2       = (const float*)d_in[15];
    const float* res_scale = (const float*)d_in[16];
    float* out = (float*)d_out;

    cudaFuncSetAttribute(k_projnode, cudaFuncAttributeMaxDynamicSharedMemorySize, PROJN_SMEM_BYTES);
    cudaFuncSetAttribute(k_table, cudaFuncAttributeMaxDynamicSharedMemorySize, TBL_SMEM_BYTES);
    cudaFuncSetAttribute(k_out, cudaFuncAttributeMaxDynamicSharedMemorySize, OUT_SMEM_BYTES);

    // index 3 = k_table (ncu capture window lands on launch index 3)
    k_setup<<<G_INIT + G_GEO + G_CNT, 256>>>(z, mask, z_emb, W_in, edge_w, edge_vec, edge_dst); // 0
    k_scan<<<1, 1024>>>();                                                                       // 1
    k_fill<<<NE / 256, 256>>>(edge_dst);                                                         // 2
    k_table<<<NT / 64, 256, TBL_SMEM_BYTES>>>(rW1, rb1, rW2, rb2);                               // 3 <- ncu
    k_sortseg<<<BN / 8, 256>>>();                                                                // 4
    k_projnode<<<BN / 64, 256, PROJN_SMEM_BYTES>>>(Wp);                                          // 5
    k_seg<<<BN, 192>>>(edge_w, edge_src);                                                        // 6
    k_out<<<BN / 16, 256, OUT_SMEM_BYTES>>>(Wo0, Wo1, Wo2, res_scale, 0);                        // 7

    for (int b = 1; b < 3; b++) {
        k_table<<<NT / 64, 256, TBL_SMEM_BYTES>>>(rW1 + b * 32 * 64, rb1 + b * 64,
                                                  rW2 + b * 64 * 192, rb2 + b * 192);
        k_projnode<<<BN / 64, 256, PROJN_SMEM_BYTES>>>(Wp + b * 128 * 192);
        k_seg<<<BN, 192>>>(edge_w, edge_src);
        k_out<<<BN / 16, 256, OUT_SMEM_BYTES>>>(Wo0 + b * 64 * 128, Wo1 + b * 64 * 64,
                                                Wo2 + b * 64 * 32, res_scale, b);
    }
    k_norm<<<BN, 256>>>(mask, out);
}

// round 11
// speedup vs baseline: 2.2533x; 1.2358x over previous
#include <cuda_runtime.h>
#include <cuda_bf16.h>
#include <math.h>
#include <stdint.h>

// ---------------- problem constants ----------------
#define BN    4096          // nodes (B*N)
#define NE    131072        // edges
#define DIMN  480           // 128 + 3*64 + 5*32
#define W3    192           // 3*MSG
#define RBFD  32
#define CUT   5.0f
#define NT    8192          // radial table resolution
#define TSTEP (CUT / (float)(NT - 1))
#define TSCALE ((float)(NT - 1) / CUT)

// ---------------- packed f32x2 helpers ----------------
__device__ __forceinline__ unsigned long long pack2(float lo, float hi) {
    unsigned long long r;
    asm("mov.b64 %0, {%1, %2};" : "=l"(r) : "f"(lo), "f"(hi));
    return r;
}
__device__ __forceinline__ void unpack2(unsigned long long v, float& lo, float& hi) {
    asm("mov.b64 {%0, %1}, %2;" : "=f"(lo), "=f"(hi) : "l"(v));
}
__device__ __forceinline__ void fma2(unsigned long long& d, unsigned long long a,
                                     unsigned long long b) {
    asm("fma.rn.f32x2 %0, %1, %2, %3;" : "=l"(d) : "l"(a), "l"(b), "l"(d));
}

// ---------------- scratch (device globals; no allocation) ----------------
__device__ float g_x[BN * DIMN];                   // node features
__device__ float g_P[BN * W3];                     // per-node projection x[:, :128] @ Wp
__device__ float g_m[BN * 576];                    // per-node segment sums
__device__ float g_sh[(size_t)NE * 9];             // per-edge sph harmonics
__device__ float g_table[(size_t)3 * NT * W3];     // radial tables for all 3 blocks
__device__ int   g_cnt[BN];                        // zero-init at load; re-zeroed by k_scan
__device__ int   g_off[BN + 1];
__device__ int   g_cur[BN];
__device__ int   g_perm[NE];

// ---------------- fused setup: init (32 nodes/CTA) + geometry (sh only) + count ----------------
#define G_INIT 128
#define G_GEO  512
#define G_CNT  512
__global__ void __launch_bounds__(256) k_setup(const int* __restrict__ z,
                                               const float* __restrict__ mask,
                                               const float* __restrict__ z_emb,
                                               const float* __restrict__ W_in,
                                               const float* __restrict__ ew,
                                               const float* __restrict__ evec,
                                               const int* __restrict__ dst) {
    int bx = blockIdx.x;
    int t = threadIdx.x;
    if (bx < G_INIT) {
        // ---- init: x0 = z_emb[z] @ W_in ----
        __shared__ float sZ[32 * 128];
        __shared__ int   sZi[32];
        __shared__ float sMk[32];
        int n0 = bx * 32;
        if (t < 32) { sZi[t] = z[n0 + t]; sMk[t] = mask[n0 + t]; }
        __syncthreads();
        for (int q = t; q < 32 * 128; q += 256) {
            int nl = q >> 7, k = q & 127;
            sZ[q] = z_emb[sZi[nl] * 128 + k];
        }
        __syncthreads();
        int j = t & 127, g = t >> 7;   // g in {0,1}: 16 nodes each
        float acc[16];
#pragma unroll
        for (int nn = 0; nn < 16; nn++) acc[nn] = 0.f;
#pragma unroll 4
        for (int k = 0; k < 128; k++) {
            float wv = W_in[k * 128 + j];
            const float* zr = &sZ[(g * 16) * 128 + k];
#pragma unroll
            for (int nn = 0; nn < 16; nn++) acc[nn] += zr[nn * 128] * wv;
        }
#pragma unroll
        for (int nn = 0; nn < 16; nn++) {
            int nl = g * 16 + nn;
            g_x[(size_t)(n0 + nl) * DIMN + j] = acc[nn] * sMk[nl];
        }
        for (int idx = t; idx < 32 * 352; idx += 256) {
            int nl = idx / 352, o = 128 + (idx - nl * 352);
            g_x[(size_t)(n0 + nl) * DIMN + o] = 0.f;
        }
    } else if (bx < G_INIT + G_GEO) {
        // ---- geometry: spherical harmonics only ----
        int e = (bx - G_INIT) * 256 + t;
        float len = ew[e];
        float inv = 1.f / fmaxf(len, 1e-8f);
        float x = evec[e * 3 + 0] * inv;
        float y = evec[e * 3 + 1] * inv;
        float zc = evec[e * 3 + 2] * inv;
        const float s3 = 1.7320508075688772f;
        const float s5 = 2.2360679774997896f;
        const float s15 = 3.872983346207417f;
        float sh[9];
        sh[0] = 1.f;
        sh[1] = s3 * x; sh[2] = s3 * y; sh[3] = s3 * zc;
        sh[4] = s15 * x * y; sh[5] = s15 * y * zc;
        sh[6] = 0.5f * s5 * (3.f * zc * zc - 1.f);
        sh[7] = s15 * x * zc; sh[8] = 0.5f * s15 * (x * x - y * y);
#pragma unroll
        for (int j2 = 0; j2 < 9; j2++) g_sh[(size_t)e * 9 + j2] = sh[j2];
    } else {
        // ---- count ----
        int e = (bx - G_INIT - G_GEO) * 256 + t;
        atomicAdd(&g_cnt[dst[e]], 1);
    }
}

// ---------------- scan (+ self-zero g_cnt for graph replay) ----------------
__global__ void k_scan() {
    __shared__ int part[1024];
    int t = threadIdx.x;
    int base = t * 4;
    int loc[4];
    int s = 0;
#pragma unroll
    for (int i = 0; i < 4; i++) { loc[i] = s; s += g_cnt[base + i]; }
    part[t] = s;
    __syncthreads();
    for (int off = 1; off < 1024; off <<= 1) {
        int v = (t >= off) ? part[t - off] : 0;
        __syncthreads();
        part[t] += v;
        __syncthreads();
    }
    int pre = (t == 0) ? 0 : part[t - 1];
#pragma unroll
    for (int i = 0; i < 4; i++) {
        g_off[base + i] = pre + loc[i];
        g_cur[base + i] = pre + loc[i];
        g_cnt[base + i] = 0;
    }
    if (t == 1023) g_off[BN] = part[1023];
}

__global__ void k_fill(const int* __restrict__ dst) {
    int e = blockIdx.x * 256 + threadIdx.x;
    if (e < NE) {
        int p = atomicAdd(&g_cur[dst[e]], 1);
        g_perm[p] = e;
    }
}

// ---------------- per-node deterministic sort (odd-even in smem, 1 warp/node) ----------------
#define SORT_CAP 1024
__global__ void __launch_bounds__(256) k_sortseg() {
    __shared__ int sbuf[8 * SORT_CAP];
    int warp = threadIdx.x >> 5, lane = threadIdx.x & 31;
    int n = blockIdx.x * 8 + warp;
    int lo = g_off[n], hi = g_off[n + 1];
    int len = hi - lo;
    int* buf = sbuf + warp * SORT_CAP;
    if (len <= 1) return;
    if (len <= SORT_CAP) {
        for (int i = lane; i < len; i += 32) buf[i] = g_perm[lo + i];
        __syncwarp();
        for (int r = 0; r < len; r++) {
            int st = r & 1;
            for (int i = st + 2 * lane; i + 1 < len; i += 64) {
                int a = buf[i], b = buf[i + 1];
                if (a > b) { buf[i] = b; buf[i + 1] = a; }
            }
            __syncwarp();
        }
        for (int i = lane; i < len; i += 32) g_perm[lo + i] = buf[i];
    } else if (lane == 0) {   // fallback (never expected at avg degree 32)
        for (int i = lo + 1; i < hi; i++) {
            int key = g_perm[i];
            int j = i - 1;
            while (j >= lo && g_perm[j] > key) { g_perm[j + 1] = g_perm[j]; j--; }
            g_perm[j + 1] = key;
        }
    }
}

// ---------------- per-node proj GEMM: g_P = x[:, :128] @ Wp[b]  (4096x192x128) ----------------
// Wp staged in smem with conflict-free swizzle (see k_table for read pattern).
#define PROJN_SMEM_BYTES (33280 * 4)
__global__ void __launch_bounds__(256) k_projnode(const float* __restrict__ Wpb) {
    extern __shared__ float sm[];
    float* sAT = sm;          // [128][68]
    float* sWp = sm + 8704;   // [128*192] swizzled
    int t = threadIdx.x;
    int n0 = blockIdx.x * 64;

    {
        int i = t >> 2, q = t & 3;
        const float* xr = g_x + (size_t)(n0 + i) * DIMN + q * 32;
#pragma unroll
        for (int r = 0; r < 8; r++) {
            float4 v = *(const float4*)(xr + r * 4);
            int k = q * 32 + r * 4;
            sAT[(k + 0) * 68 + i] = v.x;
            sAT[(k + 1) * 68 + i] = v.y;
            sAT[(k + 2) * 68 + i] = v.z;
            sAT[(k + 3) * 68 + i] = v.w;
        }
    }
    for (int q = t; q < 6144; q += 256) {
        int k = q / 48, j4 = q - k * 48;
        int txp = j4 / 3, g = j4 - txp * 3;
        ((float4*)sWp)[(k * 3 + g) * 16 + txp] = ((const float4*)Wpb)[q];
    }
    __syncthreads();

    int tx = t & 15, ty = t >> 4;
    int i0 = ty * 4;
    unsigned long long acc2[4][6];
#pragma unroll
    for (int a = 0; a < 4; a++)
#pragma unroll
        for (int b = 0; b < 6; b++) acc2[a][b] = 0ull;

#pragma unroll 4
    for (int k = 0; k < 128; k++) {
        float4 a0 = *(const float4*)&sAT[k * 68 + i0];
        const float4* bbase = (const float4*)sWp + k * 48 + tx;
        float4 f0 = bbase[0];
        float4 f1 = bbase[16];
        float4 f2 = bbase[32];
        unsigned long long bb2[6];
        bb2[0] = pack2(f0.x, f0.y); bb2[1] = pack2(f0.z, f0.w);
        bb2[2] = pack2(f1.x, f1.y); bb2[3] = pack2(f1.z, f1.w);
        bb2[4] = pack2(f2.x, f2.y); bb2[5] = pack2(f2.z, f2.w);
        float av[4] = {a0.x, a0.y, a0.z, a0.w};
#pragma unroll
        for (int a = 0; a < 4; a++) {
            unsigned long long aa = pack2(av[a], av[a]);
#pragma unroll
            for (int b = 0; b < 6; b++) fma2(acc2[a][b], aa, bb2[b]);
        }
    }
    int j0 = tx * 12;
#pragma unroll
    for (int a = 0; a < 4; a++) {
        float accs[12];
#pragma unroll
        for (int b = 0; b < 6; b++) unpack2(acc2[a][b], accs[2 * b], accs[2 * b + 1]);
        float* pr = g_P + (size_t)(n0 + i0 + a) * W3 + j0;
#pragma unroll
        for (int g = 0; g < 3; g++) {
            float4 v;
            v.x = accs[g * 4 + 0]; v.y = accs[g * 4 + 1];
            v.z = accs[g * 4 + 2]; v.w = accs[g * 4 + 3];
            *(float4*)(pr + g * 4) = v;
        }
    }
}

// ---------------- radial tables for ALL blocks: g_table[b][i] = fcut*(r+rb2) ----------------
// grid = 3*128; blockIdx.x>>7 selects the message block. 64 rows/CTA, 256 threads.
#define TBL_SMEM_BYTES (21184 * 4)
__global__ void __launch_bounds__(256, 2) k_table(const float* __restrict__ rW1,
                                                  const float* __restrict__ rb1,
                                                  const float* __restrict__ rW2,
                                                  const float* __restrict__ rb2) {
    extern __shared__ float sm[];
    float* sRbfT = sm;           // [32][68]
    float* s_rW1 = sm + 2176;    // [32*64]
    float* sHT   = sm + 4224;    // [64][68]
    float* s_rW2 = sm + 8576;    // [64*192] swizzled
    float* sFcut = sm + 20864;   // [64]
    float* s_rb1 = sm + 20928;   // [64]
    float* s_rb2 = sm + 20992;   // [192]

    int t = threadIdx.x;
    int blk = blockIdx.x >> 7;               // message block 0..2
    int r0 = (blockIdx.x & 127) * 64;        // table row base
    const float* rW1b = rW1 + blk * 32 * 64;
    const float* rb1b = rb1 + blk * 64;
    const float* rW2b = rW2 + blk * 64 * 192;
    const float* rb2b = rb2 + blk * 192;
    float* tbl = g_table + (size_t)blk * NT * W3;

    {   // rbf for 64 grid points, stored transposed
        int i = t >> 2, q = t & 3;
        float d = (float)(r0 + i) * TSTEP;
        float dm = fminf(d, CUT);
        const float width = CUT / 31.f;
#pragma unroll
        for (int r = 0; r < 8; r++) {
            int k = q * 8 + r;
            float c = CUT * (float)k / 31.f;
            float u = (dm - c) / width;
            sRbfT[k * 68 + i] = expf(-0.5f * u * u);
        }
    }
    for (int q = t; q < 512; q += 256)  ((float4*)s_rW1)[q] = ((const float4*)rW1b)[q];
    for (int q = t; q < 3072; q += 256) {   // swizzled rW2 store
        int k = q / 48, j4 = q - k * 48;
        int txp = j4 / 3, g = j4 - txp * 3;
        ((float4*)s_rW2)[(k * 3 + g) * 16 + txp] = ((const float4*)rW2b)[q];
    }
    if (t < 64) {
        float d = (float)(r0 + t) * TSTEP;
        float tt = fminf(d / CUT, 1.f);
        sFcut[t] = 0.5f * (cosf(3.14159265358979323846f * tt) + 1.f);
        s_rb1[t] = rb1b[t];
    }
    if (t >= 64 && t < 256) s_rb2[t - 64] = rb2b[t - 64];
    __syncthreads();

    int tx = t & 15, ty = t >> 4;
    int i0 = ty * 4;

    {   // h tile [64 rows][64 cols], thread 4x4 via f32x2
        int c0 = tx * 4;
        unsigned long long hh2[4][2];
#pragma unroll
        for (int a = 0; a < 4; a++) { hh2[a][0] = 0ull; hh2[a][1] = 0ull; }
#pragma unroll 4
        for (int k = 0; k < 32; k++) {
            float4 a0 = *(const float4*)&sRbfT[k * 68 + i0];
            ulonglong2 bq = *(const ulonglong2*)&s_rW1[k * 64 + c0];
            float av[4] = {a0.x, a0.y, a0.z, a0.w};
#pragma unroll
            for (int a = 0; a < 4; a++) {
                unsigned long long aa = pack2(av[a], av[a]);
                fma2(hh2[a][0], aa, bq.x);
                fma2(hh2[a][1], aa, bq.y);
            }
        }
#pragma unroll
        for (int a = 0; a < 4; a++) {
            float hv[4];
            unpack2(hh2[a][0], hv[0], hv[1]);
            unpack2(hh2[a][1], hv[2], hv[3]);
#pragma unroll
            for (int b = 0; b < 4; b++) {
                float v = hv[b] + s_rb1[c0 + b];
                v = v / (1.f + expf(-v));      // silu
                sHT[(c0 + b) * 68 + (i0 + a)] = v;
            }
        }
    }
    __syncthreads();

    {   // r tile [64][192], thread 4x12 via f32x2; write fcut*(r+rb2) to table
        unsigned long long acc2[4][6];
#pragma unroll
        for (int a = 0; a < 4; a++)
#pragma unroll
            for (int b = 0; b < 6; b++) acc2[a][b] = 0ull;
#pragma unroll 4
        for (int k = 0; k < 64; k++) {
            float4 a0 = *(const float4*)&sHT[k * 68 + i0];
            const float4* bbase = (const float4*)s_rW2 + k * 48 + tx;
            float4 f0 = bbase[0];
            float4 f1 = bbase[16];
            float4 f2 = bbase[32];
            unsigned long long bb2[6];
            bb2[0] = pack2(f0.x, f0.y); bb2[1] = pack2(f0.z, f0.w);
            bb2[2] = pack2(f1.x, f1.y); bb2[3] = pack2(f1.z, f1.w);
            bb2[4] = pack2(f2.x, f2.y); bb2[5] = pack2(f2.z, f2.w);
            float av[4] = {a0.x, a0.y, a0.z, a0.w};
#pragma unroll
            for (int a = 0; a < 4; a++) {
                unsigned long long aa = pack2(av[a], av[a]);
#pragma unroll
                for (int b = 0; b < 6; b++) fma2(acc2[a][b], aa, bb2[b]);
            }
        }
        int j0 = tx * 12;
        float rb[12];
#pragma unroll
        for (int b = 0; b < 12; b++) rb[b] = s_rb2[j0 + b];
#pragma unroll
        for (int a = 0; a < 4; a++) {
            float accs[12];
#pragma unroll
            for (int b = 0; b < 6; b++) unpack2(acc2[a][b], accs[2 * b], accs[2 * b + 1]);
            float fc = sFcut[i0 + a];
            float* outp = tbl + (size_t)(r0 + i0 + a) * W3 + j0;
#pragma unroll
            for (int g = 0; g < 3; g++) {
                float4 v;
                v.x = (accs[g * 4 + 0] + rb[g * 4 + 0]) * fc;
                v.y = (accs[g * 4 + 1] + rb[g * 4 + 1]) * fc;
                v.z = (accs[g * 4 + 2] + rb[g * 4 + 2]) * fc;
                v.w = (accs[g * 4 + 3] + rb[g * 4 + 3]) * fc;
                *(float4*)(outp + g * 4) = v;
            }
        }
    }
}

// ---------------- fused segment sum (vectorized, 4 edge-lanes x 48 col-lanes) ----------------
// w = P[src] * lerp(table, d); accumulate with sh -> g_m. One CTA per node.
__global__ void __launch_bounds__(192) k_seg(const float* __restrict__ ew,
                                             const int* __restrict__ esrc,
                                             const float* __restrict__ tbl) {
    __shared__ float sred[4 * 48 * 20];    // 15360 B
    int n = blockIdx.x;
    int t = threadIdx.x;
    int el = t / 48;          // edge lane 0..3
    int u  = t - el * 48;     // column lane: columns 4u..4u+3
    int lo = g_off[n], hi = g_off[n + 1];

    float acc[20];
#pragma unroll
    for (int i = 0; i < 20; i++) acc[i] = 0.f;

    const float4* tbl4 = (const float4*)tbl;
    for (int p = lo + el; p < hi; p += 4) {
        int e = g_perm[p];
        float d = ew[e];
        int src = esrc[e];
        float x = fminf(d, CUT) * TSCALE;
        int i = (int)x;
        if (i > NT - 2) i = NT - 2;
        float f = x - (float)i;
        float4 t0 = tbl4[(size_t)i * 48 + u];
        float4 t1 = tbl4[(size_t)(i + 1) * 48 + u];
        float4 pv = ((const float4*)(g_P + (size_t)src * W3))[u];
        float4 w;
        w.x = pv.x * (t0.x + f * (t1.x - t0.x));
        w.y = pv.y * (t0.y + f * (t1.y - t0.y));
        w.z = pv.z * (t0.z + f * (t1.z - t0.z));
        w.w = pv.w * (t0.w + f * (t1.w - t0.w));
        if (u < 16) {
            acc[0] += w.x; acc[1] += w.y; acc[2] += w.z; acc[3] += w.w;
        } else if (u < 32) {
            const float* sh = g_sh + (size_t)e * 9 + 1;
#pragma unroll
            for (int dd = 0; dd < 3; dd++) {
                float s = sh[dd];
                acc[dd * 4 + 0] += w.x * s;
                acc[dd * 4 + 1] += w.y * s;
                acc[dd * 4 + 2] += w.z * s;
                acc[dd * 4 + 3] += w.w * s;
            }
        } else {
            const float* sh = g_sh + (size_t)e * 9 + 4;
#pragma unroll
            for (int dd = 0; dd < 5; dd++) {
                float s = sh[dd];
                acc[dd * 4 + 0] += w.x * s;
                acc[dd * 4 + 1] += w.y * s;
                acc[dd * 4 + 2] += w.z * s;
                acc[dd * 4 + 3] += w.w * s;
            }
        }
    }

    float* my = sred + (size_t)t * 20;
#pragma unroll
    for (int i = 0; i < 20; i++) my[i] = acc[i];
    __syncthreads();

    if (el == 0) {
        float s[20];
#pragma unroll
        for (int i = 0; i < 20; i++)
            s[i] = sred[(size_t)u * 20 + i] + sred[(size_t)(48 + u) * 20 + i]
                 + sred[(size_t)(96 + u) * 20 + i] + sred[(size_t)(144 + u) * 20 + i];
        float* mr = g_m + (size_t)n * 576;
        if (u < 16) {
#pragma unroll
            for (int j = 0; j < 4; j++) mr[4 * u + j] = s[j];
        } else if (u < 32) {
            int c0 = 4 * u - 64;
#pragma unroll
            for (int j = 0; j < 4; j++)
#pragma unroll
                for (int dd = 0; dd < 3; dd++)
                    mr[64 + (c0 + j) * 3 + dd] = s[dd * 4 + j];
        } else {
            int c0 = 4 * u - 128;
#pragma unroll
            for (int j = 0; j < 4; j++)
#pragma unroll
                for (int dd = 0; dd < 5; dd++)
                    mr[256 + (c0 + j) * 5 + dd] = s[dd * 4 + j];
        }
    }
}

// ---------------- apply Wo + residual: x += rs * (m @ Wo), 16 nodes/CTA ----------------
#define OUT_SMEM_BYTES (23552 * 4)
__global__ void __launch_bounds__(256) k_out(const float* __restrict__ Wo0b,
                                             const float* __restrict__ Wo1b,
                                             const float* __restrict__ Wo2b,
                                             const float* __restrict__ res_scale, int b) {
    extern __shared__ float sm[];
    float* sW0 = sm;
    float* sW1 = sm + 8192;
    float* sW2 = sm + 12288;
    float* sM  = sm + 14336;
    int t = threadIdx.x;
    int n0 = blockIdx.x * 16;

    for (int q = t; q < 2048; q += 256) ((float4*)sW0)[q] = ((const float4*)Wo0b)[q];
    for (int q = t; q < 1024; q += 256) ((float4*)sW1)[q] = ((const float4*)Wo1b)[q];
    for (int q = t; q < 512;  q += 256) ((float4*)sW2)[q] = ((const float4*)Wo2b)[q];
    {
        const float4* mg = (const float4*)(g_m + (size_t)n0 * 576);
        for (int q = t; q < 2304; q += 256) ((float4*)sM)[q] = mg[q];
    }
    __syncthreads();

    float rs = res_scale[b];
    for (int idx = t; idx < 16 * 480; idx += 256) {
        int nl = idx / 480, o = idx - nl * 480;
        const float* m = sM + nl * 576;
        float u = 0.f;
        if (o < 128) {
#pragma unroll 8
            for (int k = 0; k < 64; k++) u += m[k] * sW0[k * 128 + o];
        } else if (o < 320) {
            int q = o - 128;
            int c = q / 3, d = q - c * 3;
#pragma unroll 8
            for (int k = 0; k < 64; k++) u += m[64 + k * 3 + d] * sW1[k * 64 + c];
        } else {
            int q = o - 320;
            int c = q / 5, d = q - c * 5;
#pragma unroll 8
            for (int k = 0; k < 64; k++) u += m[256 + k * 5 + d] * sW2[k * 32 + c];
        }
        g_x[(size_t)(n0 + nl) * DIMN + o] += rs * u;
    }
}

// ---------------- irrep RMS norm + mask -> out ----------------
__global__ void __launch_bounds__(256) k_norm(const float* __restrict__ mask,
                                              float* __restrict__ out) {
    __shared__ float r0[256], r1[256], r2[256];
    int n = blockIdx.x, t = threadIdx.x;
    const float* xr = g_x + (size_t)n * DIMN;
    float p0 = 0.f, p1 = 0.f, p2 = 0.f;
    for (int o = t; o < DIMN; o += 256) {
        float v = xr[o];
        float v2 = v * v;
        if (o < 128) p0 += v2;
        else if (o < 320) p1 += v2;
        else p2 += v2;
    }
    r0[t] = p0; r1[t] = p1; r2[t] = p2;
    __syncthreads();
    for (int s = 128; s > 0; s >>= 1) {
        if (t < s) { r0[t] += r0[t + s]; r1[t] += r1[t + s]; r2[t] += r2[t + s]; }
        __syncthreads();
    }
    float inv0 = 1.f / sqrtf(r0[0] / 128.f + 1e-6f);
    float inv1 = 1.f / sqrtf(r1[0] / 64.f + 1e-6f);
    float inv2 = 1.f / sqrtf(r2[0] / 32.f + 1e-6f);
    float m = mask[n];
    for (int o = t; o < DIMN; o += 256) {
        float inv = (o < 128) ? inv0 : ((o < 320) ? inv1 : inv2);
        out[(size_t)n * DIMN + o] = xr[o] * inv * m;
    }
}

// ---------------- launch ----------------
extern "C" void kernel_launch(void* const* d_in, const int* in_sizes, int n_in,
                              void* d_out, int out_size) {
    const int*   z         = (const int*)d_in[0];
    const float* mask      = (const float*)d_in[1];
    const int*   edge_src  = (const int*)d_in[2];
    const int*   edge_dst  = (const int*)d_in[3];
    const float* edge_w    = (const float*)d_in[4];
    const float* edge_vec  = (const float*)d_in[5];
    const float* z_emb     = (const float*)d_in[6];
    const float* W_in      = (const float*)d_in[7];
    const float* Wp        = (const float*)d_in[8];
    const float* rW1       = (const float*)d_in[9];
    const float* rb1       = (const float*)d_in[10];
    const float* rW2       = (const float*)d_in[11];
    const float* rb2       = (const float*)d_in[12];
    const float* Wo0       = (const float*)d_in[13];
    const float* Wo1       = (const float*)d_in[14];
    const float* Wo2       = (const float*)d_in[15];
    const float* res_scale = (const float*)d_in[16];
    float* out = (float*)d_out;

    cudaFuncSetAttribute(k_projnode, cudaFuncAttributeMaxDynamicSharedMemorySize, PROJN_SMEM_BYTES);
    cudaFuncSetAttribute(k_table, cudaFuncAttributeMaxDynamicSharedMemorySize, TBL_SMEM_BYTES);
    cudaFuncSetAttribute(k_out, cudaFuncAttributeMaxDynamicSharedMemorySize, OUT_SMEM_BYTES);

    float* tbl_dev;
    cudaGetSymbolAddress((void**)&tbl_dev, g_table);

    k_setup<<<G_INIT + G_GEO + G_CNT, 256>>>(z, mask, z_emb, W_in, edge_w, edge_vec, edge_dst); // 0
    k_scan<<<1, 1024>>>();                                                                       // 1
    k_fill<<<NE / 256, 256>>>(edge_dst);                                                         // 2
    k_table<<<3 * 128, 256, TBL_SMEM_BYTES>>>(rW1, rb1, rW2, rb2);                               // 3 <- ncu
    k_sortseg<<<BN / 8, 256>>>();                                                                // 4

    for (int b = 0; b < 3; b++) {
        k_projnode<<<BN / 64, 256, PROJN_SMEM_BYTES>>>(Wp + b * 128 * 192);
        k_seg<<<BN, 192>>>(edge_w, edge_src, tbl_dev + (size_t)b * NT * W3);
        k_out<<<BN / 16, 256, OUT_SMEM_BYTES>>>(Wo0 + b * 64 * 128, Wo1 + b * 64 * 64,
                                                Wo2 + b * 64 * 32, res_scale, b);
    }
    k_norm<<<BN, 256>>>(mask, out);
}

// round 12
// speedup vs baseline: 2.2540x; 1.0003x over previous
#include <cuda_runtime.h>
#include <cuda_bf16.h>
#include <math.h>
#include <stdint.h>

// ---------------- problem constants ----------------
#define BN    4096          // nodes (B*N)
#define NE    131072        // edges
#define DIMN  480           // 128 + 3*64 + 5*32
#define W3    192           // 3*MSG
#define RBFD  32
#define CUT   5.0f
#define NT    2048          // radial table resolution
#define TSTEP (CUT / (float)(NT - 1))
#define TSCALE ((float)(NT - 1) / CUT)

// ---------------- packed f32x2 helpers ----------------
__device__ __forceinline__ unsigned long long pack2(float lo, float hi) {
    unsigned long long r;
    asm("mov.b64 %0, {%1, %2};" : "=l"(r) : "f"(lo), "f"(hi));
    return r;
}
__device__ __forceinline__ void unpack2(unsigned long long v, float& lo, float& hi) {
    asm("mov.b64 {%0, %1}, %2;" : "=f"(lo), "=f"(hi) : "l"(v));
}
__device__ __forceinline__ void fma2(unsigned long long& d, unsigned long long a,
                                     unsigned long long b) {
    asm("fma.rn.f32x2 %0, %1, %2, %3;" : "=l"(d) : "l"(a), "l"(b), "l"(d));
}

// ---------------- scratch (device globals; no allocation) ----------------
__device__ float g_x[BN * DIMN];                   // node features
__device__ float g_P[BN * W3];                     // per-node projection x[:, :128] @ Wp
__device__ float g_m[BN * 576];                    // per-node segment sums
__device__ float g_sh[(size_t)NE * 9];             // per-edge sph harmonics
__device__ float g_table[(size_t)3 * NT * W3];     // radial tables for all 3 blocks
__device__ int   g_cnt[BN];                        // zero-init at load; re-zeroed by k_scan
__device__ int   g_off[BN + 1];
__device__ int   g_cur[BN];
__device__ int   g_perm[NE];

// ---------------- fused setup: init (32 nodes/CTA) + geometry (sh only) + count ----------------
#define G_INIT 128
#define G_GEO  512
#define G_CNT  512
__global__ void __launch_bounds__(256) k_setup(const int* __restrict__ z,
                                               const float* __restrict__ mask,
                                               const float* __restrict__ z_emb,
                                               const float* __restrict__ W_in,
                                               const float* __restrict__ ew,
                                               const float* __restrict__ evec,
                                               const int* __restrict__ dst) {
    int bx = blockIdx.x;
    int t = threadIdx.x;
    if (bx < G_INIT) {
        // ---- init: x0 = z_emb[z] @ W_in ----
        __shared__ float sZ[32 * 128];
        __shared__ int   sZi[32];
        __shared__ float sMk[32];
        int n0 = bx * 32;
        if (t < 32) { sZi[t] = z[n0 + t]; sMk[t] = mask[n0 + t]; }
        __syncthreads();
        for (int q = t; q < 32 * 128; q += 256) {
            int nl = q >> 7, k = q & 127;
            sZ[q] = z_emb[sZi[nl] * 128 + k];
        }
        __syncthreads();
        int j = t & 127, g = t >> 7;   // g in {0,1}: 16 nodes each
        float acc[16];
#pragma unroll
        for (int nn = 0; nn < 16; nn++) acc[nn] = 0.f;
#pragma unroll 4
        for (int k = 0; k < 128; k++) {
            float wv = W_in[k * 128 + j];
            const float* zr = &sZ[(g * 16) * 128 + k];
#pragma unroll
            for (int nn = 0; nn < 16; nn++) acc[nn] += zr[nn * 128] * wv;
        }
#pragma unroll
        for (int nn = 0; nn < 16; nn++) {
            int nl = g * 16 + nn;
            g_x[(size_t)(n0 + nl) * DIMN + j] = acc[nn] * sMk[nl];
        }
        for (int idx = t; idx < 32 * 352; idx += 256) {
            int nl = idx / 352, o = 128 + (idx - nl * 352);
            g_x[(size_t)(n0 + nl) * DIMN + o] = 0.f;
        }
    } else if (bx < G_INIT + G_GEO) {
        // ---- geometry: spherical harmonics only ----
        int e = (bx - G_INIT) * 256 + t;
        float len = ew[e];
        float inv = 1.f / fmaxf(len, 1e-8f);
        float x = evec[e * 3 + 0] * inv;
        float y = evec[e * 3 + 1] * inv;
        float zc = evec[e * 3 + 2] * inv;
        const float s3 = 1.7320508075688772f;
        const float s5 = 2.2360679774997896f;
        const float s15 = 3.872983346207417f;
        float sh[9];
        sh[0] = 1.f;
        sh[1] = s3 * x; sh[2] = s3 * y; sh[3] = s3 * zc;
        sh[4] = s15 * x * y; sh[5] = s15 * y * zc;
        sh[6] = 0.5f * s5 * (3.f * zc * zc - 1.f);
        sh[7] = s15 * x * zc; sh[8] = 0.5f * s15 * (x * x - y * y);
#pragma unroll
        for (int j2 = 0; j2 < 9; j2++) g_sh[(size_t)e * 9 + j2] = sh[j2];
    } else {
        // ---- count ----
        int e = (bx - G_INIT - G_GEO) * 256 + t;
        atomicAdd(&g_cnt[dst[e]], 1);
    }
}

// ---------------- scan (+ self-zero g_cnt for graph replay) ----------------
__global__ void k_scan() {
    __shared__ int part[1024];
    int t = threadIdx.x;
    int base = t * 4;
    int loc[4];
    int s = 0;
#pragma unroll
    for (int i = 0; i < 4; i++) { loc[i] = s; s += g_cnt[base + i]; }
    part[t] = s;
    __syncthreads();
    for (int off = 1; off < 1024; off <<= 1) {
        int v = (t >= off) ? part[t - off] : 0;
        __syncthreads();
        part[t] += v;
        __syncthreads();
    }
    int pre = (t == 0) ? 0 : part[t - 1];
#pragma unroll
    for (int i = 0; i < 4; i++) {
        g_off[base + i] = pre + loc[i];
        g_cur[base + i] = pre + loc[i];
        g_cnt[base + i] = 0;
    }
    if (t == 1023) g_off[BN] = part[1023];
}

__global__ void k_fill(const int* __restrict__ dst) {
    int e = blockIdx.x * 256 + threadIdx.x;
    if (e < NE) {
        int p = atomicAdd(&g_cur[dst[e]], 1);
        g_perm[p] = e;
    }
}

// ---------------- per-node deterministic sort (odd-even in smem, 1 warp/node) ----------------
#define SORT_CAP 1024
__global__ void __launch_bounds__(256) k_sortseg() {
    __shared__ int sbuf[8 * SORT_CAP];
    int warp = threadIdx.x >> 5, lane = threadIdx.x & 31;
    int n = blockIdx.x * 8 + warp;
    int lo = g_off[n], hi = g_off[n + 1];
    int len = hi - lo;
    int* buf = sbuf + warp * SORT_CAP;
    if (len <= 1) return;
    if (len <= SORT_CAP) {
        for (int i = lane; i < len; i += 32) buf[i] = g_perm[lo + i];
        __syncwarp();
        for (int r = 0; r < len; r++) {
            int st = r & 1;
            for (int i = st + 2 * lane; i + 1 < len; i += 64) {
                int a = buf[i], b = buf[i + 1];
                if (a > b) { buf[i] = b; buf[i + 1] = a; }
            }
            __syncwarp();
        }
        for (int i = lane; i < len; i += 32) g_perm[lo + i] = buf[i];
    } else if (lane == 0) {   // fallback (never expected at avg degree 32)
        for (int i = lo + 1; i < hi; i++) {
            int key = g_perm[i];
            int j = i - 1;
            while (j >= lo && g_perm[j] > key) { g_perm[j + 1] = g_perm[j]; j--; }
            g_perm[j + 1] = key;
        }
    }
}

// ---------------- per-node proj GEMM: g_P = x[:, :128] @ Wp[b]  (4096x192x128) ----------------
#define PROJN_SMEM_BYTES (33280 * 4)
__global__ void __launch_bounds__(256) k_projnode(const float* __restrict__ Wpb) {
    extern __shared__ float sm[];
    float* sAT = sm;          // [128][68]
    float* sWp = sm + 8704;   // [128*192] swizzled
    int t = threadIdx.x;
    int n0 = blockIdx.x * 64;

    {
        int i = t >> 2, q = t & 3;
        const float* xr = g_x + (size_t)(n0 + i) * DIMN + q * 32;
#pragma unroll
        for (int r = 0; r < 8; r++) {
            float4 v = *(const float4*)(xr + r * 4);
            int k = q * 32 + r * 4;
            sAT[(k + 0) * 68 + i] = v.x;
            sAT[(k + 1) * 68 + i] = v.y;
            sAT[(k + 2) * 68 + i] = v.z;
            sAT[(k + 3) * 68 + i] = v.w;
        }
    }
    for (int q = t; q < 6144; q += 256) {
        int k = q / 48, j4 = q - k * 48;
        int txp = j4 / 3, g = j4 - txp * 3;
        ((float4*)sWp)[(k * 3 + g) * 16 + txp] = ((const float4*)Wpb)[q];
    }
    __syncthreads();

    int tx = t & 15, ty = t >> 4;
    int i0 = ty * 4;
    unsigned long long acc2[4][6];
#pragma unroll
    for (int a = 0; a < 4; a++)
#pragma unroll
        for (int b = 0; b < 6; b++) acc2[a][b] = 0ull;

#pragma unroll 4
    for (int k = 0; k < 128; k++) {
        float4 a0 = *(const float4*)&sAT[k * 68 + i0];
        const float4* bbase = (const float4*)sWp + k * 48 + tx;
        float4 f0 = bbase[0];
        float4 f1 = bbase[16];
        float4 f2 = bbase[32];
        unsigned long long bb2[6];
        bb2[0] = pack2(f0.x, f0.y); bb2[1] = pack2(f0.z, f0.w);
        bb2[2] = pack2(f1.x, f1.y); bb2[3] = pack2(f1.z, f1.w);
        bb2[4] = pack2(f2.x, f2.y); bb2[5] = pack2(f2.z, f2.w);
        float av[4] = {a0.x, a0.y, a0.z, a0.w};
#pragma unroll
        for (int a = 0; a < 4; a++) {
            unsigned long long aa = pack2(av[a], av[a]);
#pragma unroll
            for (int b = 0; b < 6; b++) fma2(acc2[a][b], aa, bb2[b]);
        }
    }
    int j0 = tx * 12;
#pragma unroll
    for (int a = 0; a < 4; a++) {
        float accs[12];
#pragma unroll
        for (int b = 0; b < 6; b++) unpack2(acc2[a][b], accs[2 * b], accs[2 * b + 1]);
        float* pr = g_P + (size_t)(n0 + i0 + a) * W3 + j0;
#pragma unroll
        for (int g = 0; g < 3; g++) {
            float4 v;
            v.x = accs[g * 4 + 0]; v.y = accs[g * 4 + 1];
            v.z = accs[g * 4 + 2]; v.w = accs[g * 4 + 3];
            *(float4*)(pr + g * 4) = v;
        }
    }
}

// ---------------- radial tables for ALL blocks: g_table[b][i] = fcut*(r+rb2) ----------------
// grid = 3*(NT/64); blockIdx.x/(NT/64) selects the message block. 64 rows/CTA.
#define TBL_GRID_PER_BLK (NT / 64)
#define TBL_SMEM_BYTES (21184 * 4)
__global__ void __launch_bounds__(256, 2) k_table(const float* __restrict__ rW1,
                                                  const float* __restrict__ rb1,
                                                  const float* __restrict__ rW2,
                                                  const float* __restrict__ rb2) {
    extern __shared__ float sm[];
    float* sRbfT = sm;           // [32][68]
    float* s_rW1 = sm + 2176;    // [32*64]
    float* sHT   = sm + 4224;    // [64][68]
    float* s_rW2 = sm + 8576;    // [64*192] swizzled
    float* sFcut = sm + 20864;   // [64]
    float* s_rb1 = sm + 20928;   // [64]
    float* s_rb2 = sm + 20992;   // [192]

    int t = threadIdx.x;
    int blk = blockIdx.x / TBL_GRID_PER_BLK;
    int r0 = (blockIdx.x % TBL_GRID_PER_BLK) * 64;
    const float* rW1b = rW1 + blk * 32 * 64;
    const float* rb1b = rb1 + blk * 64;
    const float* rW2b = rW2 + blk * 64 * 192;
    const float* rb2b = rb2 + blk * 192;
    float* tbl = g_table + (size_t)blk * NT * W3;

    {   // rbf for 64 grid points, stored transposed
        int i = t >> 2, q = t & 3;
        float d = (float)(r0 + i) * TSTEP;
        float dm = fminf(d, CUT);
        const float width = CUT / 31.f;
#pragma unroll
        for (int r = 0; r < 8; r++) {
            int k = q * 8 + r;
            float c = CUT * (float)k / 31.f;
            float u = (dm - c) / width;
            sRbfT[k * 68 + i] = expf(-0.5f * u * u);
        }
    }
    for (int q = t; q < 512; q += 256)  ((float4*)s_rW1)[q] = ((const float4*)rW1b)[q];
    for (int q = t; q < 3072; q += 256) {   // swizzled rW2 store
        int k = q / 48, j4 = q - k * 48;
        int txp = j4 / 3, g = j4 - txp * 3;
        ((float4*)s_rW2)[(k * 3 + g) * 16 + txp] = ((const float4*)rW2b)[q];
    }
    if (t < 64) {
        float d = (float)(r0 + t) * TSTEP;
        float tt = fminf(d / CUT, 1.f);
        sFcut[t] = 0.5f * (cosf(3.14159265358979323846f * tt) + 1.f);
        s_rb1[t] = rb1b[t];
    }
    if (t >= 64 && t < 256) s_rb2[t - 64] = rb2b[t - 64];
    __syncthreads();

    int tx = t & 15, ty = t >> 4;
    int i0 = ty * 4;

    {   // h tile [64 rows][64 cols], thread 4x4 via f32x2
        int c0 = tx * 4;
        unsigned long long hh2[4][2];
#pragma unroll
        for (int a = 0; a < 4; a++) { hh2[a][0] = 0ull; hh2[a][1] = 0ull; }
#pragma unroll 4
        for (int k = 0; k < 32; k++) {
            float4 a0 = *(const float4*)&sRbfT[k * 68 + i0];
            ulonglong2 bq = *(const ulonglong2*)&s_rW1[k * 64 + c0];
            float av[4] = {a0.x, a0.y, a0.z, a0.w};
#pragma unroll
            for (int a = 0; a < 4; a++) {
                unsigned long long aa = pack2(av[a], av[a]);
                fma2(hh2[a][0], aa, bq.x);
                fma2(hh2[a][1], aa, bq.y);
            }
        }
#pragma unroll
        for (int a = 0; a < 4; a++) {
            float hv[4];
            unpack2(hh2[a][0], hv[0], hv[1]);
            unpack2(hh2[a][1], hv[2], hv[3]);
#pragma unroll
            for (int b = 0; b < 4; b++) {
                float v = hv[b] + s_rb1[c0 + b];
                v = v / (1.f + expf(-v));      // silu
                sHT[(c0 + b) * 68 + (i0 + a)] = v;
            }
        }
    }
    __syncthreads();

    {   // r tile [64][192], thread 4x12 via f32x2; write fcut*(r+rb2) to table
        unsigned long long acc2[4][6];
#pragma unroll
        for (int a = 0; a < 4; a++)
#pragma unroll
            for (int b = 0; b < 6; b++) acc2[a][b] = 0ull;
#pragma unroll 4
        for (int k = 0; k < 64; k++) {
            float4 a0 = *(const float4*)&sHT[k * 68 + i0];
            const float4* bbase = (const float4*)s_rW2 + k * 48 + tx;
            float4 f0 = bbase[0];
            float4 f1 = bbase[16];
            float4 f2 = bbase[32];
            unsigned long long bb2[6];
            bb2[0] = pack2(f0.x, f0.y); bb2[1] = pack2(f0.z, f0.w);
            bb2[2] = pack2(f1.x, f1.y); bb2[3] = pack2(f1.z, f1.w);
            bb2[4] = pack2(f2.x, f2.y); bb2[5] = pack2(f2.z, f2.w);
            float av[4] = {a0.x, a0.y, a0.z, a0.w};
#pragma unroll
            for (int a = 0; a < 4; a++) {
                unsigned long long aa = pack2(av[a], av[a]);
#pragma unroll
                for (int b = 0; b < 6; b++) fma2(acc2[a][b], aa, bb2[b]);
            }
        }
        int j0 = tx * 12;
        float rb[12];
#pragma unroll
        for (int b = 0; b < 12; b++) rb[b] = s_rb2[j0 + b];
#pragma unroll
        for (int a = 0; a < 4; a++) {
            float accs[12];
#pragma unroll
            for (int b = 0; b < 6; b++) unpack2(acc2[a][b], accs[2 * b], accs[2 * b + 1]);
            float fc = sFcut[i0 + a];
            float* outp = tbl + (size_t)(r0 + i0 + a) * W3 + j0;
#pragma unroll
            for (int g = 0; g < 3; g++) {
                float4 v;
                v.x = (accs[g * 4 + 0] + rb[g * 4 + 0]) * fc;
                v.y = (accs[g * 4 + 1] + rb[g * 4 + 1]) * fc;
                v.z = (accs[g * 4 + 2] + rb[g * 4 + 2]) * fc;
                v.w = (accs[g * 4 + 3] + rb[g * 4 + 3]) * fc;
                *(float4*)(outp + g * 4) = v;
            }
        }
    }
}

// ---------------- fused segment sum (8 edge-lanes x 48 col-lanes, 384 threads) ----------------
// w = P[src] * lerp(table, d); accumulate with sh -> g_m. One CTA per node.
__global__ void __launch_bounds__(384) k_seg(const float* __restrict__ ew,
                                             const int* __restrict__ esrc,
                                             const float* __restrict__ tbl) {
    __shared__ float sred[8 * 48 * 20];    // 30720 B
    int n = blockIdx.x;
    int t = threadIdx.x;
    int el = t / 48;          // edge lane 0..7
    int u  = t - el * 48;     // column lane: columns 4u..4u+3
    int lo = g_off[n], hi = g_off[n + 1];

    float acc[20];
#pragma unroll
    for (int i = 0; i < 20; i++) acc[i] = 0.f;

    const float4* tbl4 = (const float4*)tbl;
    for (int p = lo + el; p < hi; p += 8) {
        int e = g_perm[p];
        float d = ew[e];
        int src = esrc[e];
        float x = fminf(d, CUT) * TSCALE;
        int i = (int)x;
        if (i > NT - 2) i = NT - 2;
        float f = x - (float)i;
        float4 t0 = tbl4[(size_t)i * 48 + u];
        float4 t1 = tbl4[(size_t)(i + 1) * 48 + u];
        float4 pv = ((const float4*)(g_P + (size_t)src * W3))[u];
        float4 w;
        w.x = pv.x * (t0.x + f * (t1.x - t0.x));
        w.y = pv.y * (t0.y + f * (t1.y - t0.y));
        w.z = pv.z * (t0.z + f * (t1.z - t0.z));
        w.w = pv.w * (t0.w + f * (t1.w - t0.w));
        if (u < 16) {
            acc[0] += w.x; acc[1] += w.y; acc[2] += w.z; acc[3] += w.w;
        } else if (u < 32) {
            const float* sh = g_sh + (size_t)e * 9 + 1;
#pragma unroll
            for (int dd = 0; dd < 3; dd++) {
                float s = sh[dd];
                acc[dd * 4 + 0] += w.x * s;
                acc[dd * 4 + 1] += w.y * s;
                acc[dd * 4 + 2] += w.z * s;
                acc[dd * 4 + 3] += w.w * s;
            }
        } else {
            const float* sh = g_sh + (size_t)e * 9 + 4;
#pragma unroll
            for (int dd = 0; dd < 5; dd++) {
                float s = sh[dd];
                acc[dd * 4 + 0] += w.x * s;
                acc[dd * 4 + 1] += w.y * s;
                acc[dd * 4 + 2] += w.z * s;
                acc[dd * 4 + 3] += w.w * s;
            }
        }
    }

    float* my = sred + (size_t)t * 20;
#pragma unroll
    for (int i = 0; i < 20; i++) my[i] = acc[i];
    __syncthreads();

    if (el == 0) {
        float s[20];
#pragma unroll
        for (int i = 0; i < 20; i++) {
            float v = sred[(size_t)u * 20 + i];
#pragma unroll
            for (int l = 1; l < 8; l++) v += sred[(size_t)(l * 48 + u) * 20 + i];
            s[i] = v;
        }
        float* mr = g_m + (size_t)n * 576;
        if (u < 16) {
#pragma unroll
            for (int j = 0; j < 4; j++) mr[4 * u + j] = s[j];
        } else if (u < 32) {
            int c0 = 4 * u - 64;
#pragma unroll
            for (int j = 0; j < 4; j++)
#pragma unroll
                for (int dd = 0; dd < 3; dd++)
                    mr[64 + (c0 + j) * 3 + dd] = s[dd * 4 + j];
        } else {
            int c0 = 4 * u - 128;
#pragma unroll
            for (int j = 0; j < 4; j++)
#pragma unroll
                for (int dd = 0; dd < 5; dd++)
                    mr[256 + (c0 + j) * 5 + dd] = s[dd * 4 + j];
        }
    }
}

// ---------------- apply Wo + residual: x += rs * (m @ Wo), 16 nodes/CTA ----------------
#define OUT_SMEM_BYTES (23552 * 4)
__global__ void __launch_bounds__(256) k_out(const float* __restrict__ Wo0b,
                                             const float* __restrict__ Wo1b,
                                             const float* __restrict__ Wo2b,
                                             const float* __restrict__ res_scale, int b) {
    extern __shared__ float sm[];
    float* sW0 = sm;
    float* sW1 = sm + 8192;
    float* sW2 = sm + 12288;
    float* sM  = sm + 14336;
    int t = threadIdx.x;
    int n0 = blockIdx.x * 16;

    for (int q = t; q < 2048; q += 256) ((float4*)sW0)[q] = ((const float4*)Wo0b)[q];
    for (int q = t; q < 1024; q += 256) ((float4*)sW1)[q] = ((const float4*)Wo1b)[q];
    for (int q = t; q < 512;  q += 256) ((float4*)sW2)[q] = ((const float4*)Wo2b)[q];
    {
        const float4* mg = (const float4*)(g_m + (size_t)n0 * 576);
        for (int q = t; q < 2304; q += 256) ((float4*)sM)[q] = mg[q];
    }
    __syncthreads();

    float rs = res_scale[b];
    for (int idx = t; idx < 16 * 480; idx += 256) {
        int nl = idx / 480, o = idx - nl * 480;
        const float* m = sM + nl * 576;
        float u = 0.f;
        if (o < 128) {
#pragma unroll 8
            for (int k = 0; k < 64; k++) u += m[k] * sW0[k * 128 + o];
        } else if (o < 320) {
            int q = o - 128;
            int c = q / 3, d = q - c * 3;
#pragma unroll 8
            for (int k = 0; k < 64; k++) u += m[64 + k * 3 + d] * sW1[k * 64 + c];
        } else {
            int q = o - 320;
            int c = q / 5, d = q - c * 5;
#pragma unroll 8
            for (int k = 0; k < 64; k++) u += m[256 + k * 5 + d] * sW2[k * 32 + c];
        }
        g_x[(size_t)(n0 + nl) * DIMN + o] += rs * u;
    }
}

// ---------------- irrep RMS norm + mask -> out ----------------
__global__ void __launch_bounds__(256) k_norm(const float* __restrict__ mask,
                                              float* __restrict__ out) {
    __shared__ float r0[256], r1[256], r2[256];
    int n = blockIdx.x, t = threadIdx.x;
    const float* xr = g_x + (size_t)n * DIMN;
    float p0 = 0.f, p1 = 0.f, p2 = 0.f;
    for (int o = t; o < DIMN; o += 256) {
        float v = xr[o];
        float v2 = v * v;
        if (o < 128) p0 += v2;
        else if (o < 320) p1 += v2;
        else p2 += v2;
    }
    r0[t] = p0; r1[t] = p1; r2[t] = p2;
    __syncthreads();
    for (int s = 128; s > 0; s >>= 1) {
        if (t < s) { r0[t] += r0[t + s]; r1[t] += r1[t + s]; r2[t] += r2[t + s]; }
        __syncthreads();
    }
    float inv0 = 1.f / sqrtf(r0[0] / 128.f + 1e-6f);
    float inv1 = 1.f / sqrtf(r1[0] / 64.f + 1e-6f);
    float inv2 = 1.f / sqrtf(r2[0] / 32.f + 1e-6f);
    float m = mask[n];
    for (int o = t; o < DIMN; o += 256) {
        float inv = (o < 128) ? inv0 : ((o < 320) ? inv1 : inv2);
        out[(size_t)n * DIMN + o] = xr[o] * inv * m;
    }
}

// ---------------- launch ----------------
extern "C" void kernel_launch(void* const* d_in, const int* in_sizes, int n_in,
                              void* d_out, int out_size) {
    const int*   z         = (const int*)d_in[0];
    const float* mask      = (const float*)d_in[1];
    const int*   edge_src  = (const int*)d_in[2];
    const int*   edge_dst  = (const int*)d_in[3];
    const float* edge_w    = (const float*)d_in[4];
    const float* edge_vec  = (const float*)d_in[5];
    const float* z_emb     = (const float*)d_in[6];
    const float* W_in      = (const float*)d_in[7];
    const float* Wp        = (const float*)d_in[8];
    const float* rW1       = (const float*)d_in[9];
    const float* rb1       = (const float*)d_in[10];
    const float* rW2       = (const float*)d_in[11];
    const float* rb2       = (const float*)d_in[12];
    const float* Wo0       = (const float*)d_in[13];
    const float* Wo1       = (const float*)d_in[14];
    const float* Wo2       = (const float*)d_in[15];
    const float* res_scale = (const float*)d_in[16];
    float* out = (float*)d_out;

    cudaFuncSetAttribute(k_projnode, cudaFuncAttributeMaxDynamicSharedMemorySize, PROJN_SMEM_BYTES);
    cudaFuncSetAttribute(k_table, cudaFuncAttributeMaxDynamicSharedMemorySize, TBL_SMEM_BYTES);
    cudaFuncSetAttribute(k_out, cudaFuncAttributeMaxDynamicSharedMemorySize, OUT_SMEM_BYTES);

    float* tbl_dev;
    cudaGetSymbolAddress((void**)&tbl_dev, g_table);

    k_setup<<<G_INIT + G_GEO + G_CNT, 256>>>(z, mask, z_emb, W_in, edge_w, edge_vec, edge_dst); // 0
    k_scan<<<1, 1024>>>();                                                                       // 1
    k_fill<<<NE / 256, 256>>>(edge_dst);                                                         // 2
    k_table<<<3 * TBL_GRID_PER_BLK, 256, TBL_SMEM_BYTES>>>(rW1, rb1, rW2, rb2);                  // 3 <- ncu
    k_sortseg<<<BN / 8, 256>>>();                                                                // 4

    for (int b = 0; b < 3; b++) {
        k_projnode<<<BN / 64, 256, PROJN_SMEM_BYTES>>>(Wp + b * 128 * 192);
        k_seg<<<BN, 384>>>(edge_w, edge_src, tbl_dev + (size_t)b * NT * W3);
        k_out<<<BN / 16, 256, OUT_SMEM_BYTES>>>(Wo0 + b * 64 * 128, Wo1 + b * 64 * 64,
                                                Wo2 + b * 64 * 32, res_scale, b);
    }
    k_norm<<<BN, 256>>>(mask, out);
}

// round 13
// speedup vs baseline: 2.3577x; 1.0460x over previous
#include <cuda_runtime.h>
#include <cuda_bf16.h>
#include <math.h>
#include <stdint.h>

// ---------------- problem constants ----------------
#define BN    4096          // nodes (B*N)
#define NE    131072        // edges
#define DIMN  480           // 128 + 3*64 + 5*32
#define W3    192           // 3*MSG
#define RBFD  32
#define CUT   5.0f
#define NT    2048          // radial table resolution
#define TSTEP (CUT / (float)(NT - 1))
#define TSCALE ((float)(NT - 1) / CUT)

// ---------------- packed f32x2 helpers ----------------
__device__ __forceinline__ unsigned long long pack2(float lo, float hi) {
    unsigned long long r;
    asm("mov.b64 %0, {%1, %2};" : "=l"(r) : "f"(lo), "f"(hi));
    return r;
}
__device__ __forceinline__ void unpack2(unsigned long long v, float& lo, float& hi) {
    asm("mov.b64 {%0, %1}, %2;" : "=f"(lo), "=f"(hi) : "l"(v));
}
__device__ __forceinline__ void fma2(unsigned long long& d, unsigned long long a,
                                     unsigned long long b) {
    asm("fma.rn.f32x2 %0, %1, %2, %3;" : "=l"(d) : "l"(a), "l"(b), "l"(d));
}

// ---------------- scratch (device globals; no allocation) ----------------
__device__ float g_x[BN * DIMN];                   // node features
__device__ float g_P[BN * W3];                     // per-node projection x[:, :128] @ Wp
__device__ float g_m[BN * 576];                    // per-node segment sums
__device__ float g_sh[(size_t)NE * 9];             // per-edge sph harmonics
__device__ float g_table[(size_t)3 * NT * W3];     // radial tables for all 3 blocks
__device__ int   g_cnt[BN];                        // zero-init at load; re-zeroed by scan
__device__ int   g_off[BN + 1];
__device__ int   g_cur[BN];
__device__ int   g_perm[NE];

// ---------------- fused setup: init (32 nodes/CTA) + geometry (sh only) + count ----------------
#define G_INIT 128
#define G_GEO  512
#define G_CNT  512
__global__ void __launch_bounds__(256) k_setup(const int* __restrict__ z,
                                               const float* __restrict__ mask,
                                               const float* __restrict__ z_emb,
                                               const float* __restrict__ W_in,
                                               const float* __restrict__ ew,
                                               const float* __restrict__ evec,
                                               const int* __restrict__ dst) {
    int bx = blockIdx.x;
    int t = threadIdx.x;
    if (bx < G_INIT) {
        __shared__ float sZ[32 * 128];
        __shared__ int   sZi[32];
        __shared__ float sMk[32];
        int n0 = bx * 32;
        if (t < 32) { sZi[t] = z[n0 + t]; sMk[t] = mask[n0 + t]; }
        __syncthreads();
        for (int q = t; q < 32 * 128; q += 256) {
            int nl = q >> 7, k = q & 127;
            sZ[q] = z_emb[sZi[nl] * 128 + k];
        }
        __syncthreads();
        int j = t & 127, g = t >> 7;
        float acc[16];
#pragma unroll
        for (int nn = 0; nn < 16; nn++) acc[nn] = 0.f;
#pragma unroll 4
        for (int k = 0; k < 128; k++) {
            float wv = W_in[k * 128 + j];
            const float* zr = &sZ[(g * 16) * 128 + k];
#pragma unroll
            for (int nn = 0; nn < 16; nn++) acc[nn] += zr[nn * 128] * wv;
        }
#pragma unroll
        for (int nn = 0; nn < 16; nn++) {
            int nl = g * 16 + nn;
            g_x[(size_t)(n0 + nl) * DIMN + j] = acc[nn] * sMk[nl];
        }
        for (int idx = t; idx < 32 * 352; idx += 256) {
            int nl = idx / 352, o = 128 + (idx - nl * 352);
            g_x[(size_t)(n0 + nl) * DIMN + o] = 0.f;
        }
    } else if (bx < G_INIT + G_GEO) {
        int e = (bx - G_INIT) * 256 + t;
        float len = ew[e];
        float inv = 1.f / fmaxf(len, 1e-8f);
        float x = evec[e * 3 + 0] * inv;
        float y = evec[e * 3 + 1] * inv;
        float zc = evec[e * 3 + 2] * inv;
        const float s3 = 1.7320508075688772f;
        const float s5 = 2.2360679774997896f;
        const float s15 = 3.872983346207417f;
        float sh[9];
        sh[0] = 1.f;
        sh[1] = s3 * x; sh[2] = s3 * y; sh[3] = s3 * zc;
        sh[4] = s15 * x * y; sh[5] = s15 * y * zc;
        sh[6] = 0.5f * s5 * (3.f * zc * zc - 1.f);
        sh[7] = s15 * x * zc; sh[8] = 0.5f * s15 * (x * x - y * y);
#pragma unroll
        for (int j2 = 0; j2 < 9; j2++) g_sh[(size_t)e * 9 + j2] = sh[j2];
    } else {
        int e = (bx - G_INIT - G_GEO) * 256 + t;
        atomicAdd(&g_cnt[dst[e]], 1);
    }
}

// ---------------- projnode body: g_P[n0+*] = x[:, :128] @ Wpb ----------------
// smem layout: sAT [128][68] @0, sWp [128*192] swizzled @8704; 33280 floats total.
__device__ __forceinline__ void projnode_body(float* sm, int cta, const float* __restrict__ Wpb) {
    float* sAT = sm;
    float* sWp = sm + 8704;
    int t = threadIdx.x;
    int n0 = cta * 64;

    {
        int i = t >> 2, q = t & 3;
        const float* xr = g_x + (size_t)(n0 + i) * DIMN + q * 32;
#pragma unroll
        for (int r = 0; r < 8; r++) {
            float4 v = *(const float4*)(xr + r * 4);
            int k = q * 32 + r * 4;
            sAT[(k + 0) * 68 + i] = v.x;
            sAT[(k + 1) * 68 + i] = v.y;
            sAT[(k + 2) * 68 + i] = v.z;
            sAT[(k + 3) * 68 + i] = v.w;
        }
    }
    for (int q = t; q < 6144; q += 256) {
        int k = q / 48, j4 = q - k * 48;
        int txp = j4 / 3, g = j4 - txp * 3;
        ((float4*)sWp)[(k * 3 + g) * 16 + txp] = ((const float4*)Wpb)[q];
    }
    __syncthreads();

    int tx = t & 15, ty = t >> 4;
    int i0 = ty * 4;
    unsigned long long acc2[4][6];
#pragma unroll
    for (int a = 0; a < 4; a++)
#pragma unroll
        for (int b = 0; b < 6; b++) acc2[a][b] = 0ull;

#pragma unroll 4
    for (int k = 0; k < 128; k++) {
        float4 a0 = *(const float4*)&sAT[k * 68 + i0];
        const float4* bbase = (const float4*)sWp + k * 48 + tx;
        float4 f0 = bbase[0];
        float4 f1 = bbase[16];
        float4 f2 = bbase[32];
        unsigned long long bb2[6];
        bb2[0] = pack2(f0.x, f0.y); bb2[1] = pack2(f0.z, f0.w);
        bb2[2] = pack2(f1.x, f1.y); bb2[3] = pack2(f1.z, f1.w);
        bb2[4] = pack2(f2.x, f2.y); bb2[5] = pack2(f2.z, f2.w);
        float av[4] = {a0.x, a0.y, a0.z, a0.w};
#pragma unroll
        for (int a = 0; a < 4; a++) {
            unsigned long long aa = pack2(av[a], av[a]);
#pragma unroll
            for (int b = 0; b < 6; b++) fma2(acc2[a][b], aa, bb2[b]);
        }
    }
    int j0 = tx * 12;
#pragma unroll
    for (int a = 0; a < 4; a++) {
        float accs[12];
#pragma unroll
        for (int b = 0; b < 6; b++) unpack2(acc2[a][b], accs[2 * b], accs[2 * b + 1]);
        float* pr = g_P + (size_t)(n0 + i0 + a) * W3 + j0;
#pragma unroll
        for (int g = 0; g < 3; g++) {
            float4 v;
            v.x = accs[g * 4 + 0]; v.y = accs[g * 4 + 1];
            v.z = accs[g * 4 + 2]; v.w = accs[g * 4 + 3];
            *(float4*)(pr + g * 4) = v;
        }
    }
}

// ---------------- table body: g_table[blk][r0+*] = fcut*(r+rb2) ----------------
// smem: sRbfT 2176@0, s_rW1 2048@2176, sHT 4352@4224, s_rW2 12288@8576,
//       sFcut 64@20864, s_rb1 64@20928, s_rb2 192@20992 (21184 floats)
__device__ __forceinline__ void table_body(float* sm, int cta,
                                           const float* __restrict__ rW1,
                                           const float* __restrict__ rb1,
                                           const float* __restrict__ rW2,
                                           const float* __restrict__ rb2) {
    float* sRbfT = sm;
    float* s_rW1 = sm + 2176;
    float* sHT   = sm + 4224;
    float* s_rW2 = sm + 8576;
    float* sFcut = sm + 20864;
    float* s_rb1 = sm + 20928;
    float* s_rb2 = sm + 20992;

    int t = threadIdx.x;
    const int per_blk = NT / 64;
    int blk = cta / per_blk;
    int r0 = (cta % per_blk) * 64;
    const float* rW1b = rW1 + blk * 32 * 64;
    const float* rb1b = rb1 + blk * 64;
    const float* rW2b = rW2 + blk * 64 * 192;
    const float* rb2b = rb2 + blk * 192;
    float* tbl = g_table + (size_t)blk * NT * W3;

    {
        int i = t >> 2, q = t & 3;
        float d = (float)(r0 + i) * TSTEP;
        float dm = fminf(d, CUT);
        const float width = CUT / 31.f;
#pragma unroll
        for (int r = 0; r < 8; r++) {
            int k = q * 8 + r;
            float c = CUT * (float)k / 31.f;
            float u = (dm - c) / width;
            sRbfT[k * 68 + i] = expf(-0.5f * u * u);
        }
    }
    for (int q = t; q < 512; q += 256)  ((float4*)s_rW1)[q] = ((const float4*)rW1b)[q];
    for (int q = t; q < 3072; q += 256) {
        int k = q / 48, j4 = q - k * 48;
        int txp = j4 / 3, g = j4 - txp * 3;
        ((float4*)s_rW2)[(k * 3 + g) * 16 + txp] = ((const float4*)rW2b)[q];
    }
    if (t < 64) {
        float d = (float)(r0 + t) * TSTEP;
        float tt = fminf(d / CUT, 1.f);
        sFcut[t] = 0.5f * (cosf(3.14159265358979323846f * tt) + 1.f);
        s_rb1[t] = rb1b[t];
    }
    if (t >= 64 && t < 256) s_rb2[t - 64] = rb2b[t - 64];
    __syncthreads();

    int tx = t & 15, ty = t >> 4;
    int i0 = ty * 4;

    {
        int c0 = tx * 4;
        unsigned long long hh2[4][2];
#pragma unroll
        for (int a = 0; a < 4; a++) { hh2[a][0] = 0ull; hh2[a][1] = 0ull; }
#pragma unroll 4
        for (int k = 0; k < 32; k++) {
            float4 a0 = *(const float4*)&sRbfT[k * 68 + i0];
            ulonglong2 bq = *(const ulonglong2*)&s_rW1[k * 64 + c0];
            float av[4] = {a0.x, a0.y, a0.z, a0.w};
#pragma unroll
            for (int a = 0; a < 4; a++) {
                unsigned long long aa = pack2(av[a], av[a]);
                fma2(hh2[a][0], aa, bq.x);
                fma2(hh2[a][1], aa, bq.y);
            }
        }
#pragma unroll
        for (int a = 0; a < 4; a++) {
            float hv[4];
            unpack2(hh2[a][0], hv[0], hv[1]);
            unpack2(hh2[a][1], hv[2], hv[3]);
#pragma unroll
            for (int b = 0; b < 4; b++) {
                float v = hv[b] + s_rb1[c0 + b];
                v = v / (1.f + expf(-v));      // silu
                sHT[(c0 + b) * 68 + (i0 + a)] = v;
            }
        }
    }
    __syncthreads();

    {
        unsigned long long acc2[4][6];
#pragma unroll
        for (int a = 0; a < 4; a++)
#pragma unroll
            for (int b = 0; b < 6; b++) acc2[a][b] = 0ull;
#pragma unroll 4
        for (int k = 0; k < 64; k++) {
            float4 a0 = *(const float4*)&sHT[k * 68 + i0];
            const float4* bbase = (const float4*)s_rW2 + k * 48 + tx;
            float4 f0 = bbase[0];
            float4 f1 = bbase[16];
            float4 f2 = bbase[32];
            unsigned long long bb2[6];
            bb2[0] = pack2(f0.x, f0.y); bb2[1] = pack2(f0.z, f0.w);
            bb2[2] = pack2(f1.x, f1.y); bb2[3] = pack2(f1.z, f1.w);
            bb2[4] = pack2(f2.x, f2.y); bb2[5] = pack2(f2.z, f2.w);
            float av[4] = {a0.x, a0.y, a0.z, a0.w};
#pragma unroll
            for (int a = 0; a < 4; a++) {
                unsigned long long aa = pack2(av[a], av[a]);
#pragma unroll
                for (int b = 0; b < 6; b++) fma2(acc2[a][b], aa, bb2[b]);
            }
        }
        int j0 = tx * 12;
        float rb[12];
#pragma unroll
        for (int b = 0; b < 12; b++) rb[b] = s_rb2[j0 + b];
#pragma unroll
        for (int a = 0; a < 4; a++) {
            float accs[12];
#pragma unroll
            for (int b = 0; b < 6; b++) unpack2(acc2[a][b], accs[2 * b], accs[2 * b + 1]);
            float fc = sFcut[i0 + a];
            float* outp = tbl + (size_t)(r0 + i0 + a) * W3 + j0;
#pragma unroll
            for (int g = 0; g < 3; g++) {
                float4 v;
                v.x = (accs[g * 4 + 0] + rb[g * 4 + 0]) * fc;
                v.y = (accs[g * 4 + 1] + rb[g * 4 + 1]) * fc;
                v.z = (accs[g * 4 + 2] + rb[g * 4 + 2]) * fc;
                v.w = (accs[g * 4 + 3] + rb[g * 4 + 3]) * fc;
                *(float4*)(outp + g * 4) = v;
            }
        }
    }
}

// ---------------- aux launch: CTA 0 scan, CTAs 1..96 table, CTAs 97..160 proj block 0 ----
#define TBL_CTAS (3 * (NT / 64))
#define AUX_SMEM_BYTES (33280 * 4)
__global__ void __launch_bounds__(256) k_aux(const float* __restrict__ Wp0,
                                             const float* __restrict__ rW1,
                                             const float* __restrict__ rb1,
                                             const float* __restrict__ rW2,
                                             const float* __restrict__ rb2) {
    extern __shared__ float sm[];
    int bx = blockIdx.x;
    int t = threadIdx.x;
    if (bx == 0) {
        // scan over 4096 counts with 256 threads (16 each) + self-zero g_cnt
        __shared__ int part[256];
        int base = t * 16;
        int loc[16];
        int s = 0;
#pragma unroll
        for (int i = 0; i < 16; i++) { loc[i] = s; s += g_cnt[base + i]; }
        part[t] = s;
        __syncthreads();
        for (int off = 1; off < 256; off <<= 1) {
            int v = (t >= off) ? part[t - off] : 0;
            __syncthreads();
            part[t] += v;
            __syncthreads();
        }
        int pre = (t == 0) ? 0 : part[t - 1];
#pragma unroll
        for (int i = 0; i < 16; i++) {
            g_off[base + i] = pre + loc[i];
            g_cur[base + i] = pre + loc[i];
            g_cnt[base + i] = 0;
        }
        if (t == 255) g_off[BN] = part[255];
    } else if (bx <= TBL_CTAS) {
        table_body(sm, bx - 1, rW1, rb1, rW2, rb2);
    } else {
        projnode_body(sm, bx - 1 - TBL_CTAS, Wp0);
    }
}

// standalone projnode for blocks 1,2
#define PROJN_SMEM_BYTES (33280 * 4)
__global__ void __launch_bounds__(256) k_projnode(const float* __restrict__ Wpb) {
    extern __shared__ float sm[];
    projnode_body(sm, blockIdx.x, Wpb);
}

__global__ void k_fill(const int* __restrict__ dst) {
    int e = blockIdx.x * 256 + threadIdx.x;
    if (e < NE) {
        int p = atomicAdd(&g_cur[dst[e]], 1);
        g_perm[p] = e;
    }
}

// ---------------- fused segment sum (4 edge-lanes x 48 col-lanes, 192 threads) ----------------
// DOSORT: sort this node's segment (warp 0, odd-even, smem) and write back for later blocks.
template <bool DOSORT>
__device__ __forceinline__ void seg_body(const float* __restrict__ ew,
                                         const int* __restrict__ esrc,
                                         const float* __restrict__ tbl) {
    __shared__ float sred[4 * 48 * 20];    // 15360 B
    __shared__ int sperm[512];
    int n = blockIdx.x;
    int t = threadIdx.x;
    int el = t / 48;
    int u  = t - el * 48;
    int lo = g_off[n], hi = g_off[n + 1];
    int len = hi - lo;

    if (DOSORT && len > 1) {
        if (len <= 512) {
            int lane = t & 31, warp = t >> 5;
            if (warp == 0) {
                for (int i = lane; i < len; i += 32) sperm[i] = g_perm[lo + i];
                __syncwarp();
                for (int r = 0; r < len; r++) {
                    int st = r & 1;
                    for (int i = st + 2 * lane; i + 1 < len; i += 64) {
                        int a = sperm[i], b = sperm[i + 1];
                        if (a > b) { sperm[i] = b; sperm[i + 1] = a; }
                    }
                    __syncwarp();
                }
                for (int i = lane; i < len; i += 32) g_perm[lo + i] = sperm[i];
            }
        } else if (t == 0) {   // fallback, practically unreachable at Poisson(32)
            for (int i = lo + 1; i < hi; i++) {
                int key = g_perm[i];
                int j = i - 1;
                while (j >= lo && g_perm[j] > key) { g_perm[j + 1] = g_perm[j]; j--; }
                g_perm[j + 1] = key;
            }
        }
        __syncthreads();
    }

    float acc[20];
#pragma unroll
    for (int i = 0; i < 20; i++) acc[i] = 0.f;

    const float4* tbl4 = (const float4*)tbl;
    for (int p = lo + el; p < hi; p += 4) {
        int e = g_perm[p];
        float d = ew[e];
        int src = esrc[e];
        float x = fminf(d, CUT) * TSCALE;
        int i = (int)x;
        if (i > NT - 2) i = NT - 2;
        float f = x - (float)i;
        float4 t0 = tbl4[(size_t)i * 48 + u];
        float4 t1 = tbl4[(size_t)(i + 1) * 48 + u];
        float4 pv = ((const float4*)(g_P + (size_t)src * W3))[u];
        float4 w;
        w.x = pv.x * (t0.x + f * (t1.x - t0.x));
        w.y = pv.y * (t0.y + f * (t1.y - t0.y));
        w.z = pv.z * (t0.z + f * (t1.z - t0.z));
        w.w = pv.w * (t0.w + f * (t1.w - t0.w));
        if (u < 16) {
            acc[0] += w.x; acc[1] += w.y; acc[2] += w.z; acc[3] += w.w;
        } else if (u < 32) {
            const float* sh = g_sh + (size_t)e * 9 + 1;
#pragma unroll
            for (int dd = 0; dd < 3; dd++) {
                float s = sh[dd];
                acc[dd * 4 + 0] += w.x * s;
                acc[dd * 4 + 1] += w.y * s;
                acc[dd * 4 + 2] += w.z * s;
                acc[dd * 4 + 3] += w.w * s;
            }
        } else {
            const float* sh = g_sh + (size_t)e * 9 + 4;
#pragma unroll
            for (int dd = 0; dd < 5; dd++) {
                float s = sh[dd];
                acc[dd * 4 + 0] += w.x * s;
                acc[dd * 4 + 1] += w.y * s;
                acc[dd * 4 + 2] += w.z * s;
                acc[dd * 4 + 3] += w.w * s;
            }
        }
    }

    float* my = sred + (size_t)t * 20;
#pragma unroll
    for (int i = 0; i < 20; i++) my[i] = acc[i];
    __syncthreads();

    if (el == 0) {
        float s[20];
#pragma unroll
        for (int i = 0; i < 20; i++)
            s[i] = sred[(size_t)u * 20 + i] + sred[(size_t)(48 + u) * 20 + i]
                 + sred[(size_t)(96 + u) * 20 + i] + sred[(size_t)(144 + u) * 20 + i];
        float* mr = g_m + (size_t)n * 576;
        if (u < 16) {
#pragma unroll
            for (int j = 0; j < 4; j++) mr[4 * u + j] = s[j];
        } else if (u < 32) {
            int c0 = 4 * u - 64;
#pragma unroll
            for (int j = 0; j < 4; j++)
#pragma unroll
                for (int dd = 0; dd < 3; dd++)
                    mr[64 + (c0 + j) * 3 + dd] = s[dd * 4 + j];
        } else {
            int c0 = 4 * u - 128;
#pragma unroll
            for (int j = 0; j < 4; j++)
#pragma unroll
                for (int dd = 0; dd < 5; dd++)
                    mr[256 + (c0 + j) * 5 + dd] = s[dd * 4 + j];
        }
    }
}

__global__ void __launch_bounds__(192) k_seg_sort(const float* __restrict__ ew,
                                                  const int* __restrict__ esrc,
                                                  const float* __restrict__ tbl) {
    seg_body<true>(ew, esrc, tbl);
}
__global__ void __launch_bounds__(192) k_seg(const float* __restrict__ ew,
                                             const int* __restrict__ esrc,
                                             const float* __restrict__ tbl) {
    seg_body<false>(ew, esrc, tbl);
}

// ---------------- apply Wo + residual: x += rs * (m @ Wo), 16 nodes/CTA ----------------
#define OUT_SMEM_BYTES (23552 * 4)
__global__ void __launch_bounds__(256) k_out(const float* __restrict__ Wo0b,
                                             const float* __restrict__ Wo1b,
                                             const float* __restrict__ Wo2b,
                                             const float* __restrict__ res_scale, int b) {
    extern __shared__ float sm[];
    float* sW0 = sm;
    float* sW1 = sm + 8192;
    float* sW2 = sm + 12288;
    float* sM  = sm + 14336;
    int t = threadIdx.x;
    int n0 = blockIdx.x * 16;

    for (int q = t; q < 2048; q += 256) ((float4*)sW0)[q] = ((const float4*)Wo0b)[q];
    for (int q = t; q < 1024; q += 256) ((float4*)sW1)[q] = ((const float4*)Wo1b)[q];
    for (int q = t; q < 512;  q += 256) ((float4*)sW2)[q] = ((const float4*)Wo2b)[q];
    {
        const float4* mg = (const float4*)(g_m + (size_t)n0 * 576);
        for (int q = t; q < 2304; q += 256) ((float4*)sM)[q] = mg[q];
    }
    __syncthreads();

    float rs = res_scale[b];
    for (int idx = t; idx < 16 * 480; idx += 256) {
        int nl = idx / 480, o = idx - nl * 480;
        const float* m = sM + nl * 576;
        float u = 0.f;
        if (o < 128) {
#pragma unroll 8
            for (int k = 0; k < 64; k++) u += m[k] * sW0[k * 128 + o];
        } else if (o < 320) {
            int q = o - 128;
            int c = q / 3, d = q - c * 3;
#pragma unroll 8
            for (int k = 0; k < 64; k++) u += m[64 + k * 3 + d] * sW1[k * 64 + c];
        } else {
            int q = o - 320;
            int c = q / 5, d = q - c * 5;
#pragma unroll 8
            for (int k = 0; k < 64; k++) u += m[256 + k * 5 + d] * sW2[k * 32 + c];
        }
        g_x[(size_t)(n0 + nl) * DIMN + o] += rs * u;
    }
}

// ---------------- irrep RMS norm + mask -> out ----------------
__global__ void __launch_bounds__(256) k_norm(const float* __restrict__ mask,
                                              float* __restrict__ out) {
    __shared__ float r0[256], r1[256], r2[256];
    int n = blockIdx.x, t = threadIdx.x;
    const float* xr = g_x + (size_t)n * DIMN;
    float p0 = 0.f, p1 = 0.f, p2 = 0.f;
    for (int o = t; o < DIMN; o += 256) {
        float v = xr[o];
        float v2 = v * v;
        if (o < 128) p0 += v2;
        else if (o < 320) p1 += v2;
        else p2 += v2;
    }
    r0[t] = p0; r1[t] = p1; r2[t] = p2;
    __syncthreads();
    for (int s = 128; s > 0; s >>= 1) {
        if (t < s) { r0[t] += r0[t + s]; r1[t] += r1[t + s]; r2[t] += r2[t + s]; }
        __syncthreads();
    }
    float inv0 = 1.f / sqrtf(r0[0] / 128.f + 1e-6f);
    float inv1 = 1.f / sqrtf(r1[0] / 64.f + 1e-6f);
    float inv2 = 1.f / sqrtf(r2[0] / 32.f + 1e-6f);
    float m = mask[n];
    for (int o = t; o < DIMN; o += 256) {
        float inv = (o < 128) ? inv0 : ((o < 320) ? inv1 : inv2);
        out[(size_t)n * DIMN + o] = xr[o] * inv * m;
    }
}

// ---------------- launch ----------------
extern "C" void kernel_launch(void* const* d_in, const int* in_sizes, int n_in,
                              void* d_out, int out_size) {
    const int*   z         = (const int*)d_in[0];
    const float* mask      = (const float*)d_in[1];
    const int*   edge_src  = (const int*)d_in[2];
    const int*   edge_dst  = (const int*)d_in[3];
    const float* edge_w    = (const float*)d_in[4];
    const float* edge_vec  = (const float*)d_in[5];
    const float* z_emb     = (const float*)d_in[6];
    const float* W_in      = (const float*)d_in[7];
    const float* Wp        = (const float*)d_in[8];
    const float* rW1       = (const float*)d_in[9];
    const float* rb1       = (const float*)d_in[10];
    const float* rW2       = (const float*)d_in[11];
    const float* rb2       = (const float*)d_in[12];
    const float* Wo0       = (const float*)d_in[13];
    const float* Wo1       = (const float*)d_in[14];
    const float* Wo2       = (const float*)d_in[15];
    const float* res_scale = (const float*)d_in[16];
    float* out = (float*)d_out;

    cudaFuncSetAttribute(k_aux, cudaFuncAttributeMaxDynamicSharedMemorySize, AUX_SMEM_BYTES);
    cudaFuncSetAttribute(k_projnode, cudaFuncAttributeMaxDynamicSharedMemorySize, PROJN_SMEM_BYTES);
    cudaFuncSetAttribute(k_out, cudaFuncAttributeMaxDynamicSharedMemorySize, OUT_SMEM_BYTES);

    float* tbl_dev;
    cudaGetSymbolAddress((void**)&tbl_dev, g_table);

    k_setup<<<G_INIT + G_GEO + G_CNT, 256>>>(z, mask, z_emb, W_in, edge_w, edge_vec, edge_dst); // 0
    k_aux<<<1 + TBL_CTAS + 64, 256, AUX_SMEM_BYTES>>>(Wp, rW1, rb1, rW2, rb2);                   // 1
    k_fill<<<NE / 256, 256>>>(edge_dst);                                                         // 2
    k_seg_sort<<<BN, 192>>>(edge_w, edge_src, tbl_dev);                                          // 3 <- ncu
    k_out<<<BN / 16, 256, OUT_SMEM_BYTES>>>(Wo0, Wo1, Wo2, res_scale, 0);                        // 4

    for (int b = 1; b < 3; b++) {
        k_projnode<<<BN / 64, 256, PROJN_SMEM_BYTES>>>(Wp + b * 128 * 192);
        k_seg<<<BN, 192>>>(edge_w, edge_src, tbl_dev + (size_t)b * NT * W3);
        k_out<<<BN / 16, 256, OUT_SMEM_BYTES>>>(Wo0 + b * 64 * 128, Wo1 + b * 64 * 64,
                                                Wo2 + b * 64 * 32, res_scale, b);
    }
    k_norm<<<BN, 256>>>(mask, out);
}

// round 14
// speedup vs baseline: 2.4428x; 1.0361x over previous
#include <cuda_runtime.h>
#include <cuda_bf16.h>
#include <math.h>
#include <stdint.h>

// ---------------- problem constants ----------------
#define BN    4096          // nodes (B*N)
#define NE    131072        // edges
#define DIMN  480           // 128 + 3*64 + 5*32
#define W3    192           // 3*MSG
#define RBFD  32
#define CUT   5.0f
#define NT    2048          // radial table resolution
#define TSTEP (CUT / (float)(NT - 1))
#define TSCALE ((float)(NT - 1) / CUT)

// ---------------- packed f32x2 helpers ----------------
__device__ __forceinline__ unsigned long long pack2(float lo, float hi) {
    unsigned long long r;
    asm("mov.b64 %0, {%1, %2};" : "=l"(r) : "f"(lo), "f"(hi));
    return r;
}
__device__ __forceinline__ void unpack2(unsigned long long v, float& lo, float& hi) {
    asm("mov.b64 {%0, %1}, %2;" : "=f"(lo), "=f"(hi) : "l"(v));
}
__device__ __forceinline__ void fma2(unsigned long long& d, unsigned long long a,
                                     unsigned long long b) {
    asm("fma.rn.f32x2 %0, %1, %2, %3;" : "=l"(d) : "l"(a), "l"(b), "l"(d));
}

// ---------------- scratch (device globals; no allocation) ----------------
__device__ float g_x[BN * DIMN];                   // node features
__device__ float g_P[BN * W3];                     // per-node projection x[:, :128] @ Wp
__device__ float g_m[BN * 576];                    // per-node segment sums
__device__ float g_sh[(size_t)NE * 9];             // per-edge sph harmonics (edge order)
__device__ float g_table[(size_t)3 * NT * W3];     // radial tables for all 3 blocks
__device__ float g_px[NE];                         // position-ordered table coordinate
__device__ int   g_psrc[NE];                       // position-ordered src node
__device__ float g_psh[(size_t)NE * 9];            // position-ordered sph harmonics
__device__ int   g_cnt[BN];                        // zero-init at load; re-zeroed by scan
__device__ int   g_off[BN + 1];
__device__ int   g_cur[BN];
__device__ int   g_perm[NE];

// ---------------- fused setup: init (32 nodes/CTA) + geometry (sh only) + count ----------------
#define G_INIT 128
#define G_GEO  512
#define G_CNT  512
__global__ void __launch_bounds__(256) k_setup(const int* __restrict__ z,
                                               const float* __restrict__ mask,
                                               const float* __restrict__ z_emb,
                                               const float* __restrict__ W_in,
                                               const float* __restrict__ ew,
                                               const float* __restrict__ evec,
                                               const int* __restrict__ dst) {
    int bx = blockIdx.x;
    int t = threadIdx.x;
    if (bx < G_INIT) {
        __shared__ float sZ[32 * 128];
        __shared__ int   sZi[32];
        __shared__ float sMk[32];
        int n0 = bx * 32;
        if (t < 32) { sZi[t] = z[n0 + t]; sMk[t] = mask[n0 + t]; }
        __syncthreads();
        for (int q = t; q < 32 * 128; q += 256) {
            int nl = q >> 7, k = q & 127;
            sZ[q] = z_emb[sZi[nl] * 128 + k];
        }
        __syncthreads();
        int j = t & 127, g = t >> 7;
        float acc[16];
#pragma unroll
        for (int nn = 0; nn < 16; nn++) acc[nn] = 0.f;
#pragma unroll 4
        for (int k = 0; k < 128; k++) {
            float wv = W_in[k * 128 + j];
            const float* zr = &sZ[(g * 16) * 128 + k];
#pragma unroll
            for (int nn = 0; nn < 16; nn++) acc[nn] += zr[nn * 128] * wv;
        }
#pragma unroll
        for (int nn = 0; nn < 16; nn++) {
            int nl = g * 16 + nn;
            g_x[(size_t)(n0 + nl) * DIMN + j] = acc[nn] * sMk[nl];
        }
        for (int idx = t; idx < 32 * 352; idx += 256) {
            int nl = idx / 352, o = 128 + (idx - nl * 352);
            g_x[(size_t)(n0 + nl) * DIMN + o] = 0.f;
        }
    } else if (bx < G_INIT + G_GEO) {
        int e = (bx - G_INIT) * 256 + t;
        float len = ew[e];
        float inv = 1.f / fmaxf(len, 1e-8f);
        float x = evec[e * 3 + 0] * inv;
        float y = evec[e * 3 + 1] * inv;
        float zc = evec[e * 3 + 2] * inv;
        const float s3 = 1.7320508075688772f;
        const float s5 = 2.2360679774997896f;
        const float s15 = 3.872983346207417f;
        float sh[9];
        sh[0] = 1.f;
        sh[1] = s3 * x; sh[2] = s3 * y; sh[3] = s3 * zc;
        sh[4] = s15 * x * y; sh[5] = s15 * y * zc;
        sh[6] = 0.5f * s5 * (3.f * zc * zc - 1.f);
        sh[7] = s15 * x * zc; sh[8] = 0.5f * s15 * (x * x - y * y);
#pragma unroll
        for (int j2 = 0; j2 < 9; j2++) g_sh[(size_t)e * 9 + j2] = sh[j2];
    } else {
        int e = (bx - G_INIT - G_GEO) * 256 + t;
        atomicAdd(&g_cnt[dst[e]], 1);
    }
}

// ---------------- projnode body: g_P[n0+*] = x[:, :128] @ Wpb ----------------
__device__ __forceinline__ void projnode_body(float* sm, int cta, const float* __restrict__ Wpb) {
    float* sAT = sm;
    float* sWp = sm + 8704;
    int t = threadIdx.x;
    int n0 = cta * 64;

    {
        int i = t >> 2, q = t & 3;
        const float* xr = g_x + (size_t)(n0 + i) * DIMN + q * 32;
#pragma unroll
        for (int r = 0; r < 8; r++) {
            float4 v = *(const float4*)(xr + r * 4);
            int k = q * 32 + r * 4;
            sAT[(k + 0) * 68 + i] = v.x;
            sAT[(k + 1) * 68 + i] = v.y;
            sAT[(k + 2) * 68 + i] = v.z;
            sAT[(k + 3) * 68 + i] = v.w;
        }
    }
    for (int q = t; q < 6144; q += 256) {
        int k = q / 48, j4 = q - k * 48;
        int txp = j4 / 3, g = j4 - txp * 3;
        ((float4*)sWp)[(k * 3 + g) * 16 + txp] = ((const float4*)Wpb)[q];
    }
    __syncthreads();

    int tx = t & 15, ty = t >> 4;
    int i0 = ty * 4;
    unsigned long long acc2[4][6];
#pragma unroll
    for (int a = 0; a < 4; a++)
#pragma unroll
        for (int b = 0; b < 6; b++) acc2[a][b] = 0ull;

#pragma unroll 4
    for (int k = 0; k < 128; k++) {
        float4 a0 = *(const float4*)&sAT[k * 68 + i0];
        const float4* bbase = (const float4*)sWp + k * 48 + tx;
        float4 f0 = bbase[0];
        float4 f1 = bbase[16];
        float4 f2 = bbase[32];
        unsigned long long bb2[6];
        bb2[0] = pack2(f0.x, f0.y); bb2[1] = pack2(f0.z, f0.w);
        bb2[2] = pack2(f1.x, f1.y); bb2[3] = pack2(f1.z, f1.w);
        bb2[4] = pack2(f2.x, f2.y); bb2[5] = pack2(f2.z, f2.w);
        float av[4] = {a0.x, a0.y, a0.z, a0.w};
#pragma unroll
        for (int a = 0; a < 4; a++) {
            unsigned long long aa = pack2(av[a], av[a]);
#pragma unroll
            for (int b = 0; b < 6; b++) fma2(acc2[a][b], aa, bb2[b]);
        }
    }
    int j0 = tx * 12;
#pragma unroll
    for (int a = 0; a < 4; a++) {
        float accs[12];
#pragma unroll
        for (int b = 0; b < 6; b++) unpack2(acc2[a][b], accs[2 * b], accs[2 * b + 1]);
        float* pr = g_P + (size_t)(n0 + i0 + a) * W3 + j0;
#pragma unroll
        for (int g = 0; g < 3; g++) {
            float4 v;
            v.x = accs[g * 4 + 0]; v.y = accs[g * 4 + 1];
            v.z = accs[g * 4 + 2]; v.w = accs[g * 4 + 3];
            *(float4*)(pr + g * 4) = v;
        }
    }
}

// ---------------- table body: g_table[blk][r0+*] = fcut*(r+rb2) ----------------
__device__ __forceinline__ void table_body(float* sm, int cta,
                                           const float* __restrict__ rW1,
                                           const float* __restrict__ rb1,
                                           const float* __restrict__ rW2,
                                           const float* __restrict__ rb2) {
    float* sRbfT = sm;
    float* s_rW1 = sm + 2176;
    float* sHT   = sm + 4224;
    float* s_rW2 = sm + 8576;
    float* sFcut = sm + 20864;
    float* s_rb1 = sm + 20928;
    float* s_rb2 = sm + 20992;

    int t = threadIdx.x;
    const int per_blk = NT / 64;
    int blk = cta / per_blk;
    int r0 = (cta % per_blk) * 64;
    const float* rW1b = rW1 + blk * 32 * 64;
    const float* rb1b = rb1 + blk * 64;
    const float* rW2b = rW2 + blk * 64 * 192;
    const float* rb2b = rb2 + blk * 192;
    float* tbl = g_table + (size_t)blk * NT * W3;

    {
        int i = t >> 2, q = t & 3;
        float d = (float)(r0 + i) * TSTEP;
        float dm = fminf(d, CUT);
        const float width = CUT / 31.f;
#pragma unroll
        for (int r = 0; r < 8; r++) {
            int k = q * 8 + r;
            float c = CUT * (float)k / 31.f;
            float u = (dm - c) / width;
            sRbfT[k * 68 + i] = expf(-0.5f * u * u);
        }
    }
    for (int q = t; q < 512; q += 256)  ((float4*)s_rW1)[q] = ((const float4*)rW1b)[q];
    for (int q = t; q < 3072; q += 256) {
        int k = q / 48, j4 = q - k * 48;
        int txp = j4 / 3, g = j4 - txp * 3;
        ((float4*)s_rW2)[(k * 3 + g) * 16 + txp] = ((const float4*)rW2b)[q];
    }
    if (t < 64) {
        float d = (float)(r0 + t) * TSTEP;
        float tt = fminf(d / CUT, 1.f);
        sFcut[t] = 0.5f * (cosf(3.14159265358979323846f * tt) + 1.f);
        s_rb1[t] = rb1b[t];
    }
    if (t >= 64 && t < 256) s_rb2[t - 64] = rb2b[t - 64];
    __syncthreads();

    int tx = t & 15, ty = t >> 4;
    int i0 = ty * 4;

    {
        int c0 = tx * 4;
        unsigned long long hh2[4][2];
#pragma unroll
        for (int a = 0; a < 4; a++) { hh2[a][0] = 0ull; hh2[a][1] = 0ull; }
#pragma unroll 4
        for (int k = 0; k < 32; k++) {
            float4 a0 = *(const float4*)&sRbfT[k * 68 + i0];
            ulonglong2 bq = *(const ulonglong2*)&s_rW1[k * 64 + c0];
            float av[4] = {a0.x, a0.y, a0.z, a0.w};
#pragma unroll
            for (int a = 0; a < 4; a++) {
                unsigned long long aa = pack2(av[a], av[a]);
                fma2(hh2[a][0], aa, bq.x);
                fma2(hh2[a][1], aa, bq.y);
            }
        }
#pragma unroll
        for (int a = 0; a < 4; a++) {
            float hv[4];
            unpack2(hh2[a][0], hv[0], hv[1]);
            unpack2(hh2[a][1], hv[2], hv[3]);
#pragma unroll
            for (int b = 0; b < 4; b++) {
                float v = hv[b] + s_rb1[c0 + b];
                v = v / (1.f + expf(-v));      // silu
                sHT[(c0 + b) * 68 + (i0 + a)] = v;
            }
        }
    }
    __syncthreads();

    {
        unsigned long long acc2[4][6];
#pragma unroll
        for (int a = 0; a < 4; a++)
#pragma unroll
            for (int b = 0; b < 6; b++) acc2[a][b] = 0ull;
#pragma unroll 4
        for (int k = 0; k < 64; k++) {
            float4 a0 = *(const float4*)&sHT[k * 68 + i0];
            const float4* bbase = (const float4*)s_rW2 + k * 48 + tx;
            float4 f0 = bbase[0];
            float4 f1 = bbase[16];
            float4 f2 = bbase[32];
            unsigned long long bb2[6];
            bb2[0] = pack2(f0.x, f0.y); bb2[1] = pack2(f0.z, f0.w);
            bb2[2] = pack2(f1.x, f1.y); bb2[3] = pack2(f1.z, f1.w);
            bb2[4] = pack2(f2.x, f2.y); bb2[5] = pack2(f2.z, f2.w);
            float av[4] = {a0.x, a0.y, a0.z, a0.w};
#pragma unroll
            for (int a = 0; a < 4; a++) {
                unsigned long long aa = pack2(av[a], av[a]);
#pragma unroll
                for (int b = 0; b < 6; b++) fma2(acc2[a][b], aa, bb2[b]);
            }
        }
        int j0 = tx * 12;
        float rb[12];
#pragma unroll
        for (int b = 0; b < 12; b++) rb[b] = s_rb2[j0 + b];
#pragma unroll
        for (int a = 0; a < 4; a++) {
            float accs[12];
#pragma unroll
            for (int b = 0; b < 6; b++) unpack2(acc2[a][b], accs[2 * b], accs[2 * b + 1]);
            float fc = sFcut[i0 + a];
            float* outp = tbl + (size_t)(r0 + i0 + a) * W3 + j0;
#pragma unroll
            for (int g = 0; g < 3; g++) {
                float4 v;
                v.x = (accs[g * 4 + 0] + rb[g * 4 + 0]) * fc;
                v.y = (accs[g * 4 + 1] + rb[g * 4 + 1]) * fc;
                v.z = (accs[g * 4 + 2] + rb[g * 4 + 2]) * fc;
                v.w = (accs[g * 4 + 3] + rb[g * 4 + 3]) * fc;
                *(float4*)(outp + g * 4) = v;
            }
        }
    }
}

// ---------------- aux launch: CTA 0 scan, CTAs 1..96 table, CTAs 97..160 proj block 0 ----
#define TBL_CTAS (3 * (NT / 64))
#define AUX_SMEM_BYTES (33280 * 4)
__global__ void __launch_bounds__(256) k_aux(const float* __restrict__ Wp0,
                                             const float* __restrict__ rW1,
                                             const float* __restrict__ rb1,
                                             const float* __restrict__ rW2,
                                             const float* __restrict__ rb2) {
    extern __shared__ float sm[];
    int bx = blockIdx.x;
    int t = threadIdx.x;
    if (bx == 0) {
        __shared__ int part[256];
        int base = t * 16;
        int loc[16];
        int s = 0;
#pragma unroll
        for (int i = 0; i < 16; i++) { loc[i] = s; s += g_cnt[base + i]; }
        part[t] = s;
        __syncthreads();
        for (int off = 1; off < 256; off <<= 1) {
            int v = (t >= off) ? part[t - off] : 0;
            __syncthreads();
            part[t] += v;
            __syncthreads();
        }
        int pre = (t == 0) ? 0 : part[t - 1];
#pragma unroll
        for (int i = 0; i < 16; i++) {
            g_off[base + i] = pre + loc[i];
            g_cur[base + i] = pre + loc[i];
            g_cnt[base + i] = 0;
        }
        if (t == 255) g_off[BN] = part[255];
    } else if (bx <= TBL_CTAS) {
        table_body(sm, bx - 1, rW1, rb1, rW2, rb2);
    } else {
        projnode_body(sm, bx - 1 - TBL_CTAS, Wp0);
    }
}

#define PROJN_SMEM_BYTES (33280 * 4)
__global__ void __launch_bounds__(256) k_projnode(const float* __restrict__ Wpb) {
    extern __shared__ float sm[];
    projnode_body(sm, blockIdx.x, Wpb);
}

__global__ void k_fill(const int* __restrict__ dst) {
    int e = blockIdx.x * 256 + threadIdx.x;
    if (e < NE) {
        int p = atomicAdd(&g_cur[dst[e]], 1);
        g_perm[p] = e;
    }
}

// ---------------- sort + gather: per-node warp sorts segment, then writes
// position-ordered (x, src, sh) so k_seg streams with chain depth 1. ----------
#define SORT_CAP 512
__global__ void __launch_bounds__(256) k_sortgather(const float* __restrict__ ew,
                                                    const int* __restrict__ esrc) {
    __shared__ int sbuf[8 * SORT_CAP];
    int warp = threadIdx.x >> 5, lane = threadIdx.x & 31;
    int n = blockIdx.x * 8 + warp;
    int lo = g_off[n], hi = g_off[n + 1];
    int len = hi - lo;
    int* buf = sbuf + warp * SORT_CAP;
    if (len == 0) return;
    bool in_smem = (len <= SORT_CAP);
    if (len > 1) {
        if (in_smem) {
            for (int i = lane; i < len; i += 32) buf[i] = g_perm[lo + i];
            __syncwarp();
            for (int r = 0; r < len; r++) {
                int st = r & 1;
                for (int i = st + 2 * lane; i + 1 < len; i += 64) {
                    int a = buf[i], b = buf[i + 1];
                    if (a > b) { buf[i] = b; buf[i + 1] = a; }
                }
                __syncwarp();
            }
        } else if (lane == 0) {   // fallback, practically unreachable at Poisson(32)
            for (int i = lo + 1; i < hi; i++) {
                int key = g_perm[i];
                int j = i - 1;
                while (j >= lo && g_perm[j] > key) { g_perm[j + 1] = g_perm[j]; j--; }
                g_perm[j + 1] = key;
            }
        }
        __syncwarp();
    } else if (in_smem) {
        if (lane == 0) buf[0] = g_perm[lo];
        __syncwarp();
    }
    for (int i = lane; i < len; i += 32) {
        int e = in_smem ? buf[i] : g_perm[lo + i];
        int p = lo + i;
        g_px[p] = fminf(ew[e], CUT) * TSCALE;
        g_psrc[p] = esrc[e];
        const float* shs = g_sh + (size_t)e * 9;
        float* shd = g_psh + (size_t)p * 9;
#pragma unroll
        for (int j = 0; j < 9; j++) shd[j] = shs[j];
    }
}

// ---------------- fused segment sum (4 edge-lanes x 48 col-lanes, 192 threads) ----------------
// streams position-ordered (x, src, sh); w = P[src] * lerp(table, x) -> g_m
__global__ void __launch_bounds__(192) k_seg(const float* __restrict__ tbl) {
    __shared__ float sred[4 * 48 * 20];    // 15360 B
    int n = blockIdx.x;
    int t = threadIdx.x;
    int el = t / 48;
    int u  = t - el * 48;
    int lo = g_off[n], hi = g_off[n + 1];

    float acc[20];
#pragma unroll
    for (int i = 0; i < 20; i++) acc[i] = 0.f;

    const float4* tbl4 = (const float4*)tbl;
    for (int p = lo + el; p < hi; p += 4) {
        float x = g_px[p];
        int src = g_psrc[p];
        int i = (int)x;
        if (i > NT - 2) i = NT - 2;
        float f = x - (float)i;
        float4 t0 = tbl4[(size_t)i * 48 + u];
        float4 t1 = tbl4[(size_t)(i + 1) * 48 + u];
        float4 pv = ((const float4*)(g_P + (size_t)src * W3))[u];
        float4 w;
        w.x = pv.x * (t0.x + f * (t1.x - t0.x));
        w.y = pv.y * (t0.y + f * (t1.y - t0.y));
        w.z = pv.z * (t0.z + f * (t1.z - t0.z));
        w.w = pv.w * (t0.w + f * (t1.w - t0.w));
        if (u < 16) {
            acc[0] += w.x; acc[1] += w.y; acc[2] += w.z; acc[3] += w.w;
        } else if (u < 32) {
            const float* sh = g_psh + (size_t)p * 9 + 1;
#pragma unroll
            for (int dd = 0; dd < 3; dd++) {
                float s = sh[dd];
                acc[dd * 4 + 0] += w.x * s;
                acc[dd * 4 + 1] += w.y * s;
                acc[dd * 4 + 2] += w.z * s;
                acc[dd * 4 + 3] += w.w * s;
            }
        } else {
            const float* sh = g_psh + (size_t)p * 9 + 4;
#pragma unroll
            for (int dd = 0; dd < 5; dd++) {
                float s = sh[dd];
                acc[dd * 4 + 0] += w.x * s;
                acc[dd * 4 + 1] += w.y * s;
                acc[dd * 4 + 2] += w.z * s;
                acc[dd * 4 + 3] += w.w * s;
            }
        }
    }

    float* my = sred + (size_t)t * 20;
#pragma unroll
    for (int i = 0; i < 20; i++) my[i] = acc[i];
    __syncthreads();

    if (el == 0) {
        float s[20];
#pragma unroll
        for (int i = 0; i < 20; i++)
            s[i] = sred[(size_t)u * 20 + i] + sred[(size_t)(48 + u) * 20 + i]
                 + sred[(size_t)(96 + u) * 20 + i] + sred[(size_t)(144 + u) * 20 + i];
        float* mr = g_m + (size_t)n * 576;
        if (u < 16) {
#pragma unroll
            for (int j = 0; j < 4; j++) mr[4 * u + j] = s[j];
        } else if (u < 32) {
            int c0 = 4 * u - 64;
#pragma unroll
            for (int j = 0; j < 4; j++)
#pragma unroll
                for (int dd = 0; dd < 3; dd++)
                    mr[64 + (c0 + j) * 3 + dd] = s[dd * 4 + j];
        } else {
            int c0 = 4 * u - 128;
#pragma unroll
            for (int j = 0; j < 4; j++)
#pragma unroll
                for (int dd = 0; dd < 5; dd++)
                    mr[256 + (c0 + j) * 5 + dd] = s[dd * 4 + j];
        }
    }
}

// ---------------- apply Wo + residual: x += rs * (m @ Wo), 16 nodes/CTA ----------------
#define OUT_SMEM_BYTES (23552 * 4)
__global__ void __launch_bounds__(256) k_out(const float* __restrict__ Wo0b,
                                             const float* __restrict__ Wo1b,
                                             const float* __restrict__ Wo2b,
                                             const float* __restrict__ res_scale, int b) {
    extern __shared__ float sm[];
    float* sW0 = sm;
    float* sW1 = sm + 8192;
    float* sW2 = sm + 12288;
    float* sM  = sm + 14336;
    int t = threadIdx.x;
    int n0 = blockIdx.x * 16;

    for (int q = t; q < 2048; q += 256) ((float4*)sW0)[q] = ((const float4*)Wo0b)[q];
    for (int q = t; q < 1024; q += 256) ((float4*)sW1)[q] = ((const float4*)Wo1b)[q];
    for (int q = t; q < 512;  q += 256) ((float4*)sW2)[q] = ((const float4*)Wo2b)[q];
    {
        const float4* mg = (const float4*)(g_m + (size_t)n0 * 576);
        for (int q = t; q < 2304; q += 256) ((float4*)sM)[q] = mg[q];
    }
    __syncthreads();

    float rs = res_scale[b];
    for (int idx = t; idx < 16 * 480; idx += 256) {
        int nl = idx / 480, o = idx - nl * 480;
        const float* m = sM + nl * 576;
        float u = 0.f;
        if (o < 128) {
#pragma unroll 8
            for (int k = 0; k < 64; k++) u += m[k] * sW0[k * 128 + o];
        } else if (o < 320) {
            int q = o - 128;
            int c = q / 3, d = q - c * 3;
#pragma unroll 8
            for (int k = 0; k < 64; k++) u += m[64 + k * 3 + d] * sW1[k * 64 + c];
        } else {
            int q = o - 320;
            int c = q / 5, d = q - c * 5;
#pragma unroll 8
            for (int k = 0; k < 64; k++) u += m[256 + k * 5 + d] * sW2[k * 32 + c];
        }
        g_x[(size_t)(n0 + nl) * DIMN + o] += rs * u;
    }
}

// ---------------- irrep RMS norm + mask -> out ----------------
__global__ void __launch_bounds__(256) k_norm(const float* __restrict__ mask,
                                              float* __restrict__ out) {
    __shared__ float r0[256], r1[256], r2[256];
    int n = blockIdx.x, t = threadIdx.x;
    const float* xr = g_x + (size_t)n * DIMN;
    float p0 = 0.f, p1 = 0.f, p2 = 0.f;
    for (int o = t; o < DIMN; o += 256) {
        float v = xr[o];
        float v2 = v * v;
        if (o < 128) p0 += v2;
        else if (o < 320) p1 += v2;
        else p2 += v2;
    }
    r0[t] = p0; r1[t] = p1; r2[t] = p2;
    __syncthreads();
    for (int s = 128; s > 0; s >>= 1) {
        if (t < s) { r0[t] += r0[t + s]; r1[t] += r1[t + s]; r2[t] += r2[t + s]; }
        __syncthreads();
    }
    float inv0 = 1.f / sqrtf(r0[0] / 128.f + 1e-6f);
    float inv1 = 1.f / sqrtf(r1[0] / 64.f + 1e-6f);
    float inv2 = 1.f / sqrtf(r2[0] / 32.f + 1e-6f);
    float m = mask[n];
    for (int o = t; o < DIMN; o += 256) {
        float inv = (o < 128) ? inv0 : ((o < 320) ? inv1 : inv2);
        out[(size_t)n * DIMN + o] = xr[o] * inv * m;
    }
}

// ---------------- launch ----------------
extern "C" void kernel_launch(void* const* d_in, const int* in_sizes, int n_in,
                              void* d_out, int out_size) {
    const int*   z         = (const int*)d_in[0];
    const float* mask      = (const float*)d_in[1];
    const int*   edge_src  = (const int*)d_in[2];
    const int*   edge_dst  = (const int*)d_in[3];
    const float* edge_w    = (const float*)d_in[4];
    const float* edge_vec  = (const float*)d_in[5];
    const float* z_emb     = (const float*)d_in[6];
    const float* W_in      = (const float*)d_in[7];
    const float* Wp        = (const float*)d_in[8];
    const float* rW1       = (const float*)d_in[9];
    const float* rb1       = (const float*)d_in[10];
    const float* rW2       = (const float*)d_in[11];
    const float* rb2       = (const float*)d_in[12];
    const float* Wo0       = (const float*)d_in[13];
    const float* Wo1       = (const float*)d_in[14];
    const float* Wo2       = (const float*)d_in[15];
    const float* res_scale = (const float*)d_in[16];
    float* out = (float*)d_out;

    cudaFuncSetAttribute(k_aux, cudaFuncAttributeMaxDynamicSharedMemorySize, AUX_SMEM_BYTES);
    cudaFuncSetAttribute(k_projnode, cudaFuncAttributeMaxDynamicSharedMemorySize, PROJN_SMEM_BYTES);
    cudaFuncSetAttribute(k_out, cudaFuncAttributeMaxDynamicSharedMemorySize, OUT_SMEM_BYTES);

    float* tbl_dev;
    cudaGetSymbolAddress((void**)&tbl_dev, g_table);

    k_setup<<<G_INIT + G_GEO + G_CNT, 256>>>(z, mask, z_emb, W_in, edge_w, edge_vec, edge_dst); // 0
    k_aux<<<1 + TBL_CTAS + 64, 256, AUX_SMEM_BYTES>>>(Wp, rW1, rb1, rW2, rb2);                   // 1
    k_fill<<<NE / 256, 256>>>(edge_dst);                                                         // 2
    k_sortgather<<<BN / 8, 256>>>(edge_w, edge_src);                                             // 3 <- ncu
    k_seg<<<BN, 192>>>(tbl_dev);                                                                 // 4
    k_out<<<BN / 16, 256, OUT_SMEM_BYTES>>>(Wo0, Wo1, Wo2, res_scale, 0);                        // 5

    for (int b = 1; b < 3; b++) {
        k_projnode<<<BN / 64, 256, PROJN_SMEM_BYTES>>>(Wp + b * 128 * 192);
        k_seg<<<BN, 192>>>(tbl_dev + (size_t)b * NT * W3);
        k_out<<<BN / 16, 256, OUT_SMEM_BYTES>>>(Wo0 + b * 64 * 128, Wo1 + b * 64 * 64,
                                                Wo2 + b * 64 * 32, res_scale, b);
    }
    k_norm<<<BN, 256>>>(mask, out);
}

// round 15
// speedup vs baseline: 2.5321x; 1.0366x over previous
#include <cuda_runtime.h>
#include <cuda_bf16.h>
#include <math.h>
#include <stdint.h>

// ---------------- problem constants ----------------
#define BN    4096          // nodes (B*N)
#define NE    131072        // edges
#define DIMN  480           // 128 + 3*64 + 5*32
#define W3    192           // 3*MSG
#define RBFD  32
#define CUT   5.0f
#define NT    2048          // radial table resolution
#define TSTEP (CUT / (float)(NT - 1))
#define TSCALE ((float)(NT - 1) / CUT)

// ---------------- packed f32x2 helpers ----------------
__device__ __forceinline__ unsigned long long pack2(float lo, float hi) {
    unsigned long long r;
    asm("mov.b64 %0, {%1, %2};" : "=l"(r) : "f"(lo), "f"(hi));
    return r;
}
__device__ __forceinline__ void unpack2(unsigned long long v, float& lo, float& hi) {
    asm("mov.b64 {%0, %1}, %2;" : "=f"(lo), "=f"(hi) : "l"(v));
}
__device__ __forceinline__ void fma2(unsigned long long& d, unsigned long long a,
                                     unsigned long long b) {
    asm("fma.rn.f32x2 %0, %1, %2, %3;" : "=l"(d) : "l"(a), "l"(b), "l"(d));
}

// ---------------- scratch (device globals; no allocation) ----------------
__device__ float g_x[BN * DIMN];                   // node features
__device__ float g_P[BN * W3];                     // per-node projection x[:, :128] @ Wp
__device__ float g_m[BN * 576];                    // per-node segment sums
__device__ float g_sh[(size_t)NE * 9];             // per-edge sph harmonics (edge order)
__device__ float g_table[(size_t)3 * NT * W3];     // radial tables for all 3 blocks
__device__ float g_px[NE];                         // position-ordered table coordinate
__device__ int   g_psrc[NE];                       // position-ordered src node
__device__ float g_psh[(size_t)NE * 9];            // position-ordered sph harmonics
__device__ int   g_cnt[BN];                        // zero-init at load; re-zeroed by scan
__device__ int   g_off[BN + 1];
__device__ int   g_cur[BN];
__device__ int   g_perm[NE];

// ---------------- fused setup: init (32 nodes/CTA) + geometry (sh only) + count ----------------
#define G_INIT 128
#define G_GEO  512
#define G_CNT  512
__global__ void __launch_bounds__(256) k_setup(const int* __restrict__ z,
                                               const float* __restrict__ mask,
                                               const float* __restrict__ z_emb,
                                               const float* __restrict__ W_in,
                                               const float* __restrict__ ew,
                                               const float* __restrict__ evec,
                                               const int* __restrict__ dst) {
    int bx = blockIdx.x;
    int t = threadIdx.x;
    if (bx < G_INIT) {
        __shared__ float sZ[32 * 128];
        __shared__ int   sZi[32];
        __shared__ float sMk[32];
        int n0 = bx * 32;
        if (t < 32) { sZi[t] = z[n0 + t]; sMk[t] = mask[n0 + t]; }
        __syncthreads();
        for (int q = t; q < 32 * 128; q += 256) {
            int nl = q >> 7, k = q & 127;
            sZ[q] = z_emb[sZi[nl] * 128 + k];
        }
        __syncthreads();
        int j = t & 127, g = t >> 7;
        float acc[16];
#pragma unroll
        for (int nn = 0; nn < 16; nn++) acc[nn] = 0.f;
#pragma unroll 4
        for (int k = 0; k < 128; k++) {
            float wv = W_in[k * 128 + j];
            const float* zr = &sZ[(g * 16) * 128 + k];
#pragma unroll
            for (int nn = 0; nn < 16; nn++) acc[nn] += zr[nn * 128] * wv;
        }
#pragma unroll
        for (int nn = 0; nn < 16; nn++) {
            int nl = g * 16 + nn;
            g_x[(size_t)(n0 + nl) * DIMN + j] = acc[nn] * sMk[nl];
        }
        for (int idx = t; idx < 32 * 352; idx += 256) {
            int nl = idx / 352, o = 128 + (idx - nl * 352);
            g_x[(size_t)(n0 + nl) * DIMN + o] = 0.f;
        }
    } else if (bx < G_INIT + G_GEO) {
        int e = (bx - G_INIT) * 256 + t;
        float len = ew[e];
        float inv = 1.f / fmaxf(len, 1e-8f);
        float x = evec[e * 3 + 0] * inv;
        float y = evec[e * 3 + 1] * inv;
        float zc = evec[e * 3 + 2] * inv;
        const float s3 = 1.7320508075688772f;
        const float s5 = 2.2360679774997896f;
        const float s15 = 3.872983346207417f;
        float sh[9];
        sh[0] = 1.f;
        sh[1] = s3 * x; sh[2] = s3 * y; sh[3] = s3 * zc;
        sh[4] = s15 * x * y; sh[5] = s15 * y * zc;
        sh[6] = 0.5f * s5 * (3.f * zc * zc - 1.f);
        sh[7] = s15 * x * zc; sh[8] = 0.5f * s15 * (x * x - y * y);
#pragma unroll
        for (int j2 = 0; j2 < 9; j2++) g_sh[(size_t)e * 9 + j2] = sh[j2];
    } else {
        int e = (bx - G_INIT - G_GEO) * 256 + t;
        atomicAdd(&g_cnt[dst[e]], 1);
    }
}

// ---------------- projnode body: g_P[n0+*] = x[:, :128] @ Wpb ----------------
__device__ __forceinline__ void projnode_body(float* sm, int cta, const float* __restrict__ Wpb) {
    float* sAT = sm;
    float* sWp = sm + 8704;
    int t = threadIdx.x;
    int n0 = cta * 64;

    {
        int i = t >> 2, q = t & 3;
        const float* xr = g_x + (size_t)(n0 + i) * DIMN + q * 32;
#pragma unroll
        for (int r = 0; r < 8; r++) {
            float4 v = *(const float4*)(xr + r * 4);
            int k = q * 32 + r * 4;
            sAT[(k + 0) * 68 + i] = v.x;
            sAT[(k + 1) * 68 + i] = v.y;
            sAT[(k + 2) * 68 + i] = v.z;
            sAT[(k + 3) * 68 + i] = v.w;
        }
    }
    for (int q = t; q < 6144; q += 256) {
        int k = q / 48, j4 = q - k * 48;
        int txp = j4 / 3, g = j4 - txp * 3;
        ((float4*)sWp)[(k * 3 + g) * 16 + txp] = ((const float4*)Wpb)[q];
    }
    __syncthreads();

    int tx = t & 15, ty = t >> 4;
    int i0 = ty * 4;
    unsigned long long acc2[4][6];
#pragma unroll
    for (int a = 0; a < 4; a++)
#pragma unroll
        for (int b = 0; b < 6; b++) acc2[a][b] = 0ull;

#pragma unroll 4
    for (int k = 0; k < 128; k++) {
        float4 a0 = *(const float4*)&sAT[k * 68 + i0];
        const float4* bbase = (const float4*)sWp + k * 48 + tx;
        float4 f0 = bbase[0];
        float4 f1 = bbase[16];
        float4 f2 = bbase[32];
        unsigned long long bb2[6];
        bb2[0] = pack2(f0.x, f0.y); bb2[1] = pack2(f0.z, f0.w);
        bb2[2] = pack2(f1.x, f1.y); bb2[3] = pack2(f1.z, f1.w);
        bb2[4] = pack2(f2.x, f2.y); bb2[5] = pack2(f2.z, f2.w);
        float av[4] = {a0.x, a0.y, a0.z, a0.w};
#pragma unroll
        for (int a = 0; a < 4; a++) {
            unsigned long long aa = pack2(av[a], av[a]);
#pragma unroll
            for (int b = 0; b < 6; b++) fma2(acc2[a][b], aa, bb2[b]);
        }
    }
    int j0 = tx * 12;
#pragma unroll
    for (int a = 0; a < 4; a++) {
        float accs[12];
#pragma unroll
        for (int b = 0; b < 6; b++) unpack2(acc2[a][b], accs[2 * b], accs[2 * b + 1]);
        float* pr = g_P + (size_t)(n0 + i0 + a) * W3 + j0;
#pragma unroll
        for (int g = 0; g < 3; g++) {
            float4 v;
            v.x = accs[g * 4 + 0]; v.y = accs[g * 4 + 1];
            v.z = accs[g * 4 + 2]; v.w = accs[g * 4 + 3];
            *(float4*)(pr + g * 4) = v;
        }
    }
}

// ---------------- table body: g_table[blk][r0+*] = fcut*(r+rb2) ----------------
__device__ __forceinline__ void table_body(float* sm, int cta,
                                           const float* __restrict__ rW1,
                                           const float* __restrict__ rb1,
                                           const float* __restrict__ rW2,
                                           const float* __restrict__ rb2) {
    float* sRbfT = sm;
    float* s_rW1 = sm + 2176;
    float* sHT   = sm + 4224;
    float* s_rW2 = sm + 8576;
    float* sFcut = sm + 20864;
    float* s_rb1 = sm + 20928;
    float* s_rb2 = sm + 20992;

    int t = threadIdx.x;
    const int per_blk = NT / 64;
    int blk = cta / per_blk;
    int r0 = (cta % per_blk) * 64;
    const float* rW1b = rW1 + blk * 32 * 64;
    const float* rb1b = rb1 + blk * 64;
    const float* rW2b = rW2 + blk * 64 * 192;
    const float* rb2b = rb2 + blk * 192;
    float* tbl = g_table + (size_t)blk * NT * W3;

    {
        int i = t >> 2, q = t & 3;
        float d = (float)(r0 + i) * TSTEP;
        float dm = fminf(d, CUT);
        const float width = CUT / 31.f;
#pragma unroll
        for (int r = 0; r < 8; r++) {
            int k = q * 8 + r;
            float c = CUT * (float)k / 31.f;
            float u = (dm - c) / width;
            sRbfT[k * 68 + i] = expf(-0.5f * u * u);
        }
    }
    for (int q = t; q < 512; q += 256)  ((float4*)s_rW1)[q] = ((const float4*)rW1b)[q];
    for (int q = t; q < 3072; q += 256) {
        int k = q / 48, j4 = q - k * 48;
        int txp = j4 / 3, g = j4 - txp * 3;
        ((float4*)s_rW2)[(k * 3 + g) * 16 + txp] = ((const float4*)rW2b)[q];
    }
    if (t < 64) {
        float d = (float)(r0 + t) * TSTEP;
        float tt = fminf(d / CUT, 1.f);
        sFcut[t] = 0.5f * (cosf(3.14159265358979323846f * tt) + 1.f);
        s_rb1[t] = rb1b[t];
    }
    if (t >= 64 && t < 256) s_rb2[t - 64] = rb2b[t - 64];
    __syncthreads();

    int tx = t & 15, ty = t >> 4;
    int i0 = ty * 4;

    {
        int c0 = tx * 4;
        unsigned long long hh2[4][2];
#pragma unroll
        for (int a = 0; a < 4; a++) { hh2[a][0] = 0ull; hh2[a][1] = 0ull; }
#pragma unroll 4
        for (int k = 0; k < 32; k++) {
            float4 a0 = *(const float4*)&sRbfT[k * 68 + i0];
            ulonglong2 bq = *(const ulonglong2*)&s_rW1[k * 64 + c0];
            float av[4] = {a0.x, a0.y, a0.z, a0.w};
#pragma unroll
            for (int a = 0; a < 4; a++) {
                unsigned long long aa = pack2(av[a], av[a]);
                fma2(hh2[a][0], aa, bq.x);
                fma2(hh2[a][1], aa, bq.y);
            }
        }
#pragma unroll
        for (int a = 0; a < 4; a++) {
            float hv[4];
            unpack2(hh2[a][0], hv[0], hv[1]);
            unpack2(hh2[a][1], hv[2], hv[3]);
#pragma unroll
            for (int b = 0; b < 4; b++) {
                float v = hv[b] + s_rb1[c0 + b];
                v = v / (1.f + expf(-v));      // silu
                sHT[(c0 + b) * 68 + (i0 + a)] = v;
            }
        }
    }
    __syncthreads();

    {
        unsigned long long acc2[4][6];
#pragma unroll
        for (int a = 0; a < 4; a++)
#pragma unroll
            for (int b = 0; b < 6; b++) acc2[a][b] = 0ull;
#pragma unroll 4
        for (int k = 0; k < 64; k++) {
            float4 a0 = *(const float4*)&sHT[k * 68 + i0];
            const float4* bbase = (const float4*)s_rW2 + k * 48 + tx;
            float4 f0 = bbase[0];
            float4 f1 = bbase[16];
            float4 f2 = bbase[32];
            unsigned long long bb2[6];
            bb2[0] = pack2(f0.x, f0.y); bb2[1] = pack2(f0.z, f0.w);
            bb2[2] = pack2(f1.x, f1.y); bb2[3] = pack2(f1.z, f1.w);
            bb2[4] = pack2(f2.x, f2.y); bb2[5] = pack2(f2.z, f2.w);
            float av[4] = {a0.x, a0.y, a0.z, a0.w};
#pragma unroll
            for (int a = 0; a < 4; a++) {
                unsigned long long aa = pack2(av[a], av[a]);
#pragma unroll
                for (int b = 0; b < 6; b++) fma2(acc2[a][b], aa, bb2[b]);
            }
        }
        int j0 = tx * 12;
        float rb[12];
#pragma unroll
        for (int b = 0; b < 12; b++) rb[b] = s_rb2[j0 + b];
#pragma unroll
        for (int a = 0; a < 4; a++) {
            float accs[12];
#pragma unroll
            for (int b = 0; b < 6; b++) unpack2(acc2[a][b], accs[2 * b], accs[2 * b + 1]);
            float fc = sFcut[i0 + a];
            float* outp = tbl + (size_t)(r0 + i0 + a) * W3 + j0;
#pragma unroll
            for (int g = 0; g < 3; g++) {
                float4 v;
                v.x = (accs[g * 4 + 0] + rb[g * 4 + 0]) * fc;
                v.y = (accs[g * 4 + 1] + rb[g * 4 + 1]) * fc;
                v.z = (accs[g * 4 + 2] + rb[g * 4 + 2]) * fc;
                v.w = (accs[g * 4 + 3] + rb[g * 4 + 3]) * fc;
                *(float4*)(outp + g * 4) = v;
            }
        }
    }
}

// ---------------- aux launch: CTA 0 scan, CTAs 1..96 table, CTAs 97..160 proj block 0 ----
#define TBL_CTAS (3 * (NT / 64))
#define AUX_SMEM_BYTES (33280 * 4)
__global__ void __launch_bounds__(256) k_aux(const float* __restrict__ Wp0,
                                             const float* __restrict__ rW1,
                                             const float* __restrict__ rb1,
                                             const float* __restrict__ rW2,
                                             const float* __restrict__ rb2) {
    extern __shared__ float sm[];
    int bx = blockIdx.x;
    int t = threadIdx.x;
    if (bx == 0) {
        __shared__ int part[256];
        int base = t * 16;
        int loc[16];
        int s = 0;
#pragma unroll
        for (int i = 0; i < 16; i++) { loc[i] = s; s += g_cnt[base + i]; }
        part[t] = s;
        __syncthreads();
        for (int off = 1; off < 256; off <<= 1) {
            int v = (t >= off) ? part[t - off] : 0;
            __syncthreads();
            part[t] += v;
            __syncthreads();
        }
        int pre = (t == 0) ? 0 : part[t - 1];
#pragma unroll
        for (int i = 0; i < 16; i++) {
            g_off[base + i] = pre + loc[i];
            g_cur[base + i] = pre + loc[i];
            g_cnt[base + i] = 0;
        }
        if (t == 255) g_off[BN] = part[255];
    } else if (bx <= TBL_CTAS) {
        table_body(sm, bx - 1, rW1, rb1, rW2, rb2);
    } else {
        projnode_body(sm, bx - 1 - TBL_CTAS, Wp0);
    }
}

#define PROJN_SMEM_BYTES (33280 * 4)
__global__ void __launch_bounds__(256) k_projnode(const float* __restrict__ Wpb) {
    extern __shared__ float sm[];
    projnode_body(sm, blockIdx.x, Wpb);
}

__global__ void k_fill(const int* __restrict__ dst) {
    int e = blockIdx.x * 256 + threadIdx.x;
    if (e < NE) {
        int p = atomicAdd(&g_cur[dst[e]], 1);
        g_perm[p] = e;
    }
}

// ---------------- sort + gather: per-node warp sorts segment, then writes
// position-ordered (x, src, sh) so k_seg streams with chain depth 1. ----------
#define SORT_CAP 512
__global__ void __launch_bounds__(256) k_sortgather(const float* __restrict__ ew,
                                                    const int* __restrict__ esrc) {
    __shared__ int sbuf[8 * SORT_CAP];
    int warp = threadIdx.x >> 5, lane = threadIdx.x & 31;
    int n = blockIdx.x * 8 + warp;
    int lo = g_off[n], hi = g_off[n + 1];
    int len = hi - lo;
    int* buf = sbuf + warp * SORT_CAP;
    if (len == 0) return;
    bool in_smem = (len <= SORT_CAP);
    if (len > 1) {
        if (in_smem) {
            for (int i = lane; i < len; i += 32) buf[i] = g_perm[lo + i];
            __syncwarp();
            for (int r = 0; r < len; r++) {
                int st = r & 1;
                for (int i = st + 2 * lane; i + 1 < len; i += 64) {
                    int a = buf[i], b = buf[i + 1];
                    if (a > b) { buf[i] = b; buf[i + 1] = a; }
                }
                __syncwarp();
            }
        } else if (lane == 0) {   // fallback, practically unreachable at Poisson(32)
            for (int i = lo + 1; i < hi; i++) {
                int key = g_perm[i];
                int j = i - 1;
                while (j >= lo && g_perm[j] > key) { g_perm[j + 1] = g_perm[j]; j--; }
                g_perm[j + 1] = key;
            }
        }
        __syncwarp();
    } else if (in_smem) {
        if (lane == 0) buf[0] = g_perm[lo];
        __syncwarp();
    }
    for (int i = lane; i < len; i += 32) {
        int e = in_smem ? buf[i] : g_perm[lo + i];
        int p = lo + i;
        g_px[p] = fminf(ew[e], CUT) * TSCALE;
        g_psrc[p] = esrc[e];
        const float* shs = g_sh + (size_t)e * 9;
        float* shd = g_psh + (size_t)p * 9;
#pragma unroll
        for (int j = 0; j < 9; j++) shd[j] = shs[j];
    }
}

// ---------------- fused segment sum (4 edge-lanes x 48 col-lanes, 2-way pipelined) --------
// streams position-ordered (x, src, sh); w = P[src] * lerp(table, x) -> g_m
__global__ void __launch_bounds__(192) k_seg(const float* __restrict__ tbl) {
    __shared__ float sred[4 * 48 * 20];    // 15360 B
    int n = blockIdx.x;
    int t = threadIdx.x;
    int el = t / 48;
    int u  = t - el * 48;
    int lo = g_off[n], hi = g_off[n + 1];

    float acc[20];
#pragma unroll
    for (int i = 0; i < 20; i++) acc[i] = 0.f;

    const float4* tbl4 = (const float4*)tbl;
    const float4* P4 = (const float4*)g_P;

    // accumulate one edge's w into acc (position order preserved by call order)
    auto accum = [&](int p, float4 w) {
        if (u < 16) {
            acc[0] += w.x; acc[1] += w.y; acc[2] += w.z; acc[3] += w.w;
        } else if (u < 32) {
            const float* sh = g_psh + (size_t)p * 9 + 1;
#pragma unroll
            for (int dd = 0; dd < 3; dd++) {
                float s = sh[dd];
                acc[dd * 4 + 0] += w.x * s;
                acc[dd * 4 + 1] += w.y * s;
                acc[dd * 4 + 2] += w.z * s;
                acc[dd * 4 + 3] += w.w * s;
            }
        } else {
            const float* sh = g_psh + (size_t)p * 9 + 4;
#pragma unroll
            for (int dd = 0; dd < 5; dd++) {
                float s = sh[dd];
                acc[dd * 4 + 0] += w.x * s;
                acc[dd * 4 + 1] += w.y * s;
                acc[dd * 4 + 2] += w.z * s;
                acc[dd * 4 + 3] += w.w * s;
            }
        }
    };

    int p = lo + el;
    // 2-way pipelined main loop: issue both iterations' loads before accumulating
    for (; p + 4 < hi; p += 8) {
        float x0 = g_px[p],     x1 = g_px[p + 4];
        int  s0 = g_psrc[p],    s1 = g_psrc[p + 4];
        int i0 = (int)x0; if (i0 > NT - 2) i0 = NT - 2;
        int i1 = (int)x1; if (i1 > NT - 2) i1 = NT - 2;
        float f0 = x0 - (float)i0;
        float f1 = x1 - (float)i1;
        float4 t00 = tbl4[(size_t)i0 * 48 + u];
        float4 t01 = tbl4[(size_t)(i0 + 1) * 48 + u];
        float4 pv0 = P4[(size_t)s0 * 48 + u];
        float4 t10 = tbl4[(size_t)i1 * 48 + u];
        float4 t11 = tbl4[(size_t)(i1 + 1) * 48 + u];
        float4 pv1 = P4[(size_t)s1 * 48 + u];
        float4 w0, w1;
        w0.x = pv0.x * (t00.x + f0 * (t01.x - t00.x));
        w0.y = pv0.y * (t00.y + f0 * (t01.y - t00.y));
        w0.z = pv0.z * (t00.z + f0 * (t01.z - t00.z));
        w0.w = pv0.w * (t00.w + f0 * (t01.w - t00.w));
        w1.x = pv1.x * (t10.x + f1 * (t11.x - t10.x));
        w1.y = pv1.y * (t10.y + f1 * (t11.y - t10.y));
        w1.z = pv1.z * (t10.z + f1 * (t11.z - t10.z));
        w1.w = pv1.w * (t10.w + f1 * (t11.w - t10.w));
        accum(p, w0);
        accum(p + 4, w1);
    }
    // tail
    if (p < hi) {
        float x = g_px[p];
        int src = g_psrc[p];
        int i = (int)x; if (i > NT - 2) i = NT - 2;
        float f = x - (float)i;
        float4 t0 = tbl4[(size_t)i * 48 + u];
        float4 t1 = tbl4[(size_t)(i + 1) * 48 + u];
        float4 pv = P4[(size_t)src * 48 + u];
        float4 w;
        w.x = pv.x * (t0.x + f * (t1.x - t0.x));
        w.y = pv.y * (t0.y + f * (t1.y - t0.y));
        w.z = pv.z * (t0.z + f * (t1.z - t0.z));
        w.w = pv.w * (t0.w + f * (t1.w - t0.w));
        accum(p, w);
    }

    float* my = sred + (size_t)t * 20;
#pragma unroll
    for (int i = 0; i < 20; i++) my[i] = acc[i];
    __syncthreads();

    if (el == 0) {
        float s[20];
#pragma unroll
        for (int i = 0; i < 20; i++)
            s[i] = sred[(size_t)u * 20 + i] + sred[(size_t)(48 + u) * 20 + i]
                 + sred[(size_t)(96 + u) * 20 + i] + sred[(size_t)(144 + u) * 20 + i];
        float* mr = g_m + (size_t)n * 576;
        if (u < 16) {
#pragma unroll
            for (int j = 0; j < 4; j++) mr[4 * u + j] = s[j];
        } else if (u < 32) {
            int c0 = 4 * u - 64;
#pragma unroll
            for (int j = 0; j < 4; j++)
#pragma unroll
                for (int dd = 0; dd < 3; dd++)
                    mr[64 + (c0 + j) * 3 + dd] = s[dd * 4 + j];
        } else {
            int c0 = 4 * u - 128;
#pragma unroll
            for (int j = 0; j < 4; j++)
#pragma unroll
                for (int dd = 0; dd < 5; dd++)
                    mr[256 + (c0 + j) * 5 + dd] = s[dd * 4 + j];
        }
    }
}

// ---------------- apply Wo + residual: x += rs * (m @ Wo), 16 nodes/CTA ----------------
#define OUT_SMEM_BYTES (23552 * 4)
__global__ void __launch_bounds__(256) k_out(const float* __restrict__ Wo0b,
                                             const float* __restrict__ Wo1b,
                                             const float* __restrict__ Wo2b,
                                             const float* __restrict__ res_scale, int b) {
    extern __shared__ float sm[];
    float* sW0 = sm;
    float* sW1 = sm + 8192;
    float* sW2 = sm + 12288;
    float* sM  = sm + 14336;
    int t = threadIdx.x;
    int n0 = blockIdx.x * 16;

    for (int q = t; q < 2048; q += 256) ((float4*)sW0)[q] = ((const float4*)Wo0b)[q];
    for (int q = t; q < 1024; q += 256) ((float4*)sW1)[q] = ((const float4*)Wo1b)[q];
    for (int q = t; q < 512;  q += 256) ((float4*)sW2)[q] = ((const float4*)Wo2b)[q];
    {
        const float4* mg = (const float4*)(g_m + (size_t)n0 * 576);
        for (int q = t; q < 2304; q += 256) ((float4*)sM)[q] = mg[q];
    }
    __syncthreads();

    float rs = res_scale[b];
    for (int idx = t; idx < 16 * 480; idx += 256) {
        int nl = idx / 480, o = idx - nl * 480;
        const float* m = sM + nl * 576;
        float u = 0.f;
        if (o < 128) {
#pragma unroll 8
            for (int k = 0; k < 64; k++) u += m[k] * sW0[k * 128 + o];
        } else if (o < 320) {
            int q = o - 128;
            int c = q / 3, d = q - c * 3;
#pragma unroll 8
            for (int k = 0; k < 64; k++) u += m[64 + k * 3 + d] * sW1[k * 64 + c];
        } else {
            int q = o - 320;
            int c = q / 5, d = q - c * 5;
#pragma unroll 8
            for (int k = 0; k < 64; k++) u += m[256 + k * 5 + d] * sW2[k * 32 + c];
        }
        g_x[(size_t)(n0 + nl) * DIMN + o] += rs * u;
    }
}

// ---------------- irrep RMS norm + mask -> out ----------------
__global__ void __launch_bounds__(256) k_norm(const float* __restrict__ mask,
                                              float* __restrict__ out) {
    __shared__ float r0[256], r1[256], r2[256];
    int n = blockIdx.x, t = threadIdx.x;
    const float* xr = g_x + (size_t)n * DIMN;
    float p0 = 0.f, p1 = 0.f, p2 = 0.f;
    for (int o = t; o < DIMN; o += 256) {
        float v = xr[o];
        float v2 = v * v;
        if (o < 128) p0 += v2;
        else if (o < 320) p1 += v2;
        else p2 += v2;
    }
    r0[t] = p0; r1[t] = p1; r2[t] = p2;
    __syncthreads();
    for (int s = 128; s > 0; s >>= 1) {
        if (t < s) { r0[t] += r0[t + s]; r1[t] += r1[t + s]; r2[t] += r2[t + s]; }
        __syncthreads();
    }
    float inv0 = 1.f / sqrtf(r0[0] / 128.f + 1e-6f);
    float inv1 = 1.f / sqrtf(r1[0] / 64.f + 1e-6f);
    float inv2 = 1.f / sqrtf(r2[0] / 32.f + 1e-6f);
    float m = mask[n];
    for (int o = t; o < DIMN; o += 256) {
        float inv = (o < 128) ? inv0 : ((o < 320) ? inv1 : inv2);
        out[(size_t)n * DIMN + o] = xr[o] * inv * m;
    }
}

// ---------------- launch ----------------
extern "C" void kernel_launch(void* const* d_in, const int* in_sizes, int n_in,
                              void* d_out, int out_size) {
    const int*   z         = (const int*)d_in[0];
    const float* mask      = (const float*)d_in[1];
    const int*   edge_src  = (const int*)d_in[2];
    const int*   edge_dst  = (const int*)d_in[3];
    const float* edge_w    = (const float*)d_in[4];
    const float* edge_vec  = (const float*)d_in[5];
    const float* z_emb     = (const float*)d_in[6];
    const float* W_in      = (const float*)d_in[7];
    const float* Wp        = (const float*)d_in[8];
    const float* rW1       = (const float*)d_in[9];
    const float* rb1       = (const float*)d_in[10];
    const float* rW2       = (const float*)d_in[11];
    const float* rb2       = (const float*)d_in[12];
    const float* Wo0       = (const float*)d_in[13];
    const float* Wo1       = (const float*)d_in[14];
    const float* Wo2       = (const float*)d_in[15];
    const float* res_scale = (const float*)d_in[16];
    float* out = (float*)d_out;

    cudaFuncSetAttribute(k_aux, cudaFuncAttributeMaxDynamicSharedMemorySize, AUX_SMEM_BYTES);
    cudaFuncSetAttribute(k_projnode, cudaFuncAttributeMaxDynamicSharedMemorySize, PROJN_SMEM_BYTES);
    cudaFuncSetAttribute(k_out, cudaFuncAttributeMaxDynamicSharedMemorySize, OUT_SMEM_BYTES);

    float* tbl_dev;
    cudaGetSymbolAddress((void**)&tbl_dev, g_table);

    k_setup<<<G_INIT + G_GEO + G_CNT, 256>>>(z, mask, z_emb, W_in, edge_w, edge_vec, edge_dst); // 0
    k_aux<<<1 + TBL_CTAS + 64, 256, AUX_SMEM_BYTES>>>(Wp, rW1, rb1, rW2, rb2);                   // 1
    k_fill<<<NE / 256, 256>>>(edge_dst);                                                         // 2
    k_sortgather<<<BN / 8, 256>>>(edge_w, edge_src);                                             // 3 <- ncu
    k_seg<<<BN, 192>>>(tbl_dev);                                                                 // 4
    k_out<<<BN / 16, 256, OUT_SMEM_BYTES>>>(Wo0, Wo1, Wo2, res_scale, 0);                        // 5

    for (int b = 1; b < 3; b++) {
        k_projnode<<<BN / 64, 256, PROJN_SMEM_BYTES>>>(Wp + b * 128 * 192);
        k_seg<<<BN, 192>>>(tbl_dev + (size_t)b * NT * W3);
        k_out<<<BN / 16, 256, OUT_SMEM_BYTES>>>(Wo0 + b * 64 * 128, Wo1 + b * 64 * 64,
                                                Wo2 + b * 64 * 32, res_scale, b);
    }
    k_norm<<<BN, 256>>>(mask, out);
}

// round 16
// speedup vs baseline: 2.6981x; 1.0656x over previous
#include <cuda_runtime.h>
#include <cuda_bf16.h>
#include <math.h>
#include <stdint.h>

// ---------------- problem constants ----------------
#define BN    4096          // nodes (B*N)
#define NE    131072        // edges
#define DIMN  480           // 128 + 3*64 + 5*32
#define W3    192           // 3*MSG
#define RBFD  32
#define CUT   5.0f
#define NT    1024          // radial table resolution
#define TSTEP (CUT / (float)(NT - 1))
#define TSCALE ((float)(NT - 1) / CUT)

// ---------------- packed f32x2 helpers ----------------
__device__ __forceinline__ unsigned long long pack2(float lo, float hi) {
    unsigned long long r;
    asm("mov.b64 %0, {%1, %2};" : "=l"(r) : "f"(lo), "f"(hi));
    return r;
}
__device__ __forceinline__ void unpack2(unsigned long long v, float& lo, float& hi) {
    asm("mov.b64 {%0, %1}, %2;" : "=f"(lo), "=f"(hi) : "l"(v));
}
__device__ __forceinline__ void fma2(unsigned long long& d, unsigned long long a,
                                     unsigned long long b) {
    asm("fma.rn.f32x2 %0, %1, %2, %3;" : "=l"(d) : "l"(a), "l"(b), "l"(d));
}

// ---------------- scratch (device globals; no allocation) ----------------
__device__ float g_x[BN * DIMN];                   // node features
__device__ float g_P[BN * W3];                     // per-node projection x[:, :128] @ Wp
__device__ float g_m[BN * 576];                    // per-node segment sums
__device__ float g_sh8[(size_t)NE * 8];            // per-edge sh[1..8] (edge order, aligned)
__device__ float g_table[(size_t)3 * NT * W3];     // radial tables for all 3 blocks
__device__ float g_px[NE];                         // position-ordered table coordinate
__device__ int   g_psrc[NE];                       // position-ordered src node
__device__ float g_psh[(size_t)NE * 8];            // position-ordered sh[1..8]
__device__ int   g_cnt[BN];                        // zero-init at load; re-zeroed by scan
__device__ int   g_off[BN + 1];
__device__ int   g_cur[BN];
__device__ int   g_perm[NE];

// ---------------- fused setup: init (32 nodes/CTA) + geometry (sh only) + count ----------------
#define G_INIT 128
#define G_GEO  512
#define G_CNT  512
__global__ void __launch_bounds__(256) k_setup(const int* __restrict__ z,
                                               const float* __restrict__ mask,
                                               const float* __restrict__ z_emb,
                                               const float* __restrict__ W_in,
                                               const float* __restrict__ ew,
                                               const float* __restrict__ evec,
                                               const int* __restrict__ dst) {
    int bx = blockIdx.x;
    int t = threadIdx.x;
    if (bx < G_INIT) {
        __shared__ float sZ[32 * 128];
        __shared__ int   sZi[32];
        __shared__ float sMk[32];
        int n0 = bx * 32;
        if (t < 32) { sZi[t] = z[n0 + t]; sMk[t] = mask[n0 + t]; }
        __syncthreads();
        for (int q = t; q < 32 * 128; q += 256) {
            int nl = q >> 7, k = q & 127;
            sZ[q] = z_emb[sZi[nl] * 128 + k];
        }
        __syncthreads();
        int j = t & 127, g = t >> 7;
        float acc[16];
#pragma unroll
        for (int nn = 0; nn < 16; nn++) acc[nn] = 0.f;
#pragma unroll 4
        for (int k = 0; k < 128; k++) {
            float wv = W_in[k * 128 + j];
            const float* zr = &sZ[(g * 16) * 128 + k];
#pragma unroll
            for (int nn = 0; nn < 16; nn++) acc[nn] += zr[nn * 128] * wv;
        }
#pragma unroll
        for (int nn = 0; nn < 16; nn++) {
            int nl = g * 16 + nn;
            g_x[(size_t)(n0 + nl) * DIMN + j] = acc[nn] * sMk[nl];
        }
        for (int idx = t; idx < 32 * 352; idx += 256) {
            int nl = idx / 352, o = 128 + (idx - nl * 352);
            g_x[(size_t)(n0 + nl) * DIMN + o] = 0.f;
        }
    } else if (bx < G_INIT + G_GEO) {
        int e = (bx - G_INIT) * 256 + t;
        float len = ew[e];
        float inv = 1.f / fmaxf(len, 1e-8f);
        float x = evec[e * 3 + 0] * inv;
        float y = evec[e * 3 + 1] * inv;
        float zc = evec[e * 3 + 2] * inv;
        const float s3 = 1.7320508075688772f;
        const float s5 = 2.2360679774997896f;
        const float s15 = 3.872983346207417f;
        float4 f0, f1;
        f0.x = s3 * x; f0.y = s3 * y; f0.z = s3 * zc;
        f0.w = s15 * x * y;
        f1.x = s15 * y * zc;
        f1.y = 0.5f * s5 * (3.f * zc * zc - 1.f);
        f1.z = s15 * x * zc;
        f1.w = 0.5f * s15 * (x * x - y * y);
        float4* shp = (float4*)(g_sh8 + (size_t)e * 8);
        shp[0] = f0;
        shp[1] = f1;
    } else {
        int e = (bx - G_INIT - G_GEO) * 256 + t;
        atomicAdd(&g_cnt[dst[e]], 1);
    }
}

// ---------------- projnode body: g_P[n0+*] = x[:, :128] @ Wpb ----------------
__device__ __forceinline__ void projnode_body(float* sm, int cta, const float* __restrict__ Wpb) {
    float* sAT = sm;
    float* sWp = sm + 8704;
    int t = threadIdx.x;
    int n0 = cta * 64;

    {
        int i = t >> 2, q = t & 3;
        const float* xr = g_x + (size_t)(n0 + i) * DIMN + q * 32;
#pragma unroll
        for (int r = 0; r < 8; r++) {
            float4 v = *(const float4*)(xr + r * 4);
            int k = q * 32 + r * 4;
            sAT[(k + 0) * 68 + i] = v.x;
            sAT[(k + 1) * 68 + i] = v.y;
            sAT[(k + 2) * 68 + i] = v.z;
            sAT[(k + 3) * 68 + i] = v.w;
        }
    }
    for (int q = t; q < 6144; q += 256) {
        int k = q / 48, j4 = q - k * 48;
        int txp = j4 / 3, g = j4 - txp * 3;
        ((float4*)sWp)[(k * 3 + g) * 16 + txp] = ((const float4*)Wpb)[q];
    }
    __syncthreads();

    int tx = t & 15, ty = t >> 4;
    int i0 = ty * 4;
    unsigned long long acc2[4][6];
#pragma unroll
    for (int a = 0; a < 4; a++)
#pragma unroll
        for (int b = 0; b < 6; b++) acc2[a][b] = 0ull;

#pragma unroll 4
    for (int k = 0; k < 128; k++) {
        float4 a0 = *(const float4*)&sAT[k * 68 + i0];
        const float4* bbase = (const float4*)sWp + k * 48 + tx;
        float4 f0 = bbase[0];
        float4 f1 = bbase[16];
        float4 f2 = bbase[32];
        unsigned long long bb2[6];
        bb2[0] = pack2(f0.x, f0.y); bb2[1] = pack2(f0.z, f0.w);
        bb2[2] = pack2(f1.x, f1.y); bb2[3] = pack2(f1.z, f1.w);
        bb2[4] = pack2(f2.x, f2.y); bb2[5] = pack2(f2.z, f2.w);
        float av[4] = {a0.x, a0.y, a0.z, a0.w};
#pragma unroll
        for (int a = 0; a < 4; a++) {
            unsigned long long aa = pack2(av[a], av[a]);
#pragma unroll
            for (int b = 0; b < 6; b++) fma2(acc2[a][b], aa, bb2[b]);
        }
    }
    int j0 = tx * 12;
#pragma unroll
    for (int a = 0; a < 4; a++) {
        float accs[12];
#pragma unroll
        for (int b = 0; b < 6; b++) unpack2(acc2[a][b], accs[2 * b], accs[2 * b + 1]);
        float* pr = g_P + (size_t)(n0 + i0 + a) * W3 + j0;
#pragma unroll
        for (int g = 0; g < 3; g++) {
            float4 v;
            v.x = accs[g * 4 + 0]; v.y = accs[g * 4 + 1];
            v.z = accs[g * 4 + 2]; v.w = accs[g * 4 + 3];
            *(float4*)(pr + g * 4) = v;
        }
    }
}

// ---------------- table body: g_table[blk][r0+*] = fcut*(r+rb2) ----------------
__device__ __forceinline__ void table_body(float* sm, int cta,
                                           const float* __restrict__ rW1,
                                           const float* __restrict__ rb1,
                                           const float* __restrict__ rW2,
                                           const float* __restrict__ rb2) {
    float* sRbfT = sm;
    float* s_rW1 = sm + 2176;
    float* sHT   = sm + 4224;
    float* s_rW2 = sm + 8576;
    float* sFcut = sm + 20864;
    float* s_rb1 = sm + 20928;
    float* s_rb2 = sm + 20992;

    int t = threadIdx.x;
    const int per_blk = NT / 64;
    int blk = cta / per_blk;
    int r0 = (cta % per_blk) * 64;
    const float* rW1b = rW1 + blk * 32 * 64;
    const float* rb1b = rb1 + blk * 64;
    const float* rW2b = rW2 + blk * 64 * 192;
    const float* rb2b = rb2 + blk * 192;
    float* tbl = g_table + (size_t)blk * NT * W3;

    {
        int i = t >> 2, q = t & 3;
        float d = (float)(r0 + i) * TSTEP;
        float dm = fminf(d, CUT);
        const float width = CUT / 31.f;
#pragma unroll
        for (int r = 0; r < 8; r++) {
            int k = q * 8 + r;
            float c = CUT * (float)k / 31.f;
            float u = (dm - c) / width;
            sRbfT[k * 68 + i] = expf(-0.5f * u * u);
        }
    }
    for (int q = t; q < 512; q += 256)  ((float4*)s_rW1)[q] = ((const float4*)rW1b)[q];
    for (int q = t; q < 3072; q += 256) {
        int k = q / 48, j4 = q - k * 48;
        int txp = j4 / 3, g = j4 - txp * 3;
        ((float4*)s_rW2)[(k * 3 + g) * 16 + txp] = ((const float4*)rW2b)[q];
    }
    if (t < 64) {
        float d = (float)(r0 + t) * TSTEP;
        float tt = fminf(d / CUT, 1.f);
        sFcut[t] = 0.5f * (cosf(3.14159265358979323846f * tt) + 1.f);
        s_rb1[t] = rb1b[t];
    }
    if (t >= 64 && t < 256) s_rb2[t - 64] = rb2b[t - 64];
    __syncthreads();

    int tx = t & 15, ty = t >> 4;
    int i0 = ty * 4;

    {
        int c0 = tx * 4;
        unsigned long long hh2[4][2];
#pragma unroll
        for (int a = 0; a < 4; a++) { hh2[a][0] = 0ull; hh2[a][1] = 0ull; }
#pragma unroll 4
        for (int k = 0; k < 32; k++) {
            float4 a0 = *(const float4*)&sRbfT[k * 68 + i0];
            ulonglong2 bq = *(const ulonglong2*)&s_rW1[k * 64 + c0];
            float av[4] = {a0.x, a0.y, a0.z, a0.w};
#pragma unroll
            for (int a = 0; a < 4; a++) {
                unsigned long long aa = pack2(av[a], av[a]);
                fma2(hh2[a][0], aa, bq.x);
                fma2(hh2[a][1], aa, bq.y);
            }
        }
#pragma unroll
        for (int a = 0; a < 4; a++) {
            float hv[4];
            unpack2(hh2[a][0], hv[0], hv[1]);
            unpack2(hh2[a][1], hv[2], hv[3]);
#pragma unroll
            for (int b = 0; b < 4; b++) {
                float v = hv[b] + s_rb1[c0 + b];
                v = v / (1.f + expf(-v));      // silu
                sHT[(c0 + b) * 68 + (i0 + a)] = v;
            }
        }
    }
    __syncthreads();

    {
        unsigned long long acc2[4][6];
#pragma unroll
        for (int a = 0; a < 4; a++)
#pragma unroll
            for (int b = 0; b < 6; b++) acc2[a][b] = 0ull;
#pragma unroll 4
        for (int k = 0; k < 64; k++) {
            float4 a0 = *(const float4*)&sHT[k * 68 + i0];
            const float4* bbase = (const float4*)s_rW2 + k * 48 + tx;
            float4 f0 = bbase[0];
            float4 f1 = bbase[16];
            float4 f2 = bbase[32];
            unsigned long long bb2[6];
            bb2[0] = pack2(f0.x, f0.y); bb2[1] = pack2(f0.z, f0.w);
            bb2[2] = pack2(f1.x, f1.y); bb2[3] = pack2(f1.z, f1.w);
            bb2[4] = pack2(f2.x, f2.y); bb2[5] = pack2(f2.z, f2.w);
            float av[4] = {a0.x, a0.y, a0.z, a0.w};
#pragma unroll
            for (int a = 0; a < 4; a++) {
                unsigned long long aa = pack2(av[a], av[a]);
#pragma unroll
                for (int b = 0; b < 6; b++) fma2(acc2[a][b], aa, bb2[b]);
            }
        }
        int j0 = tx * 12;
        float rb[12];
#pragma unroll
        for (int b = 0; b < 12; b++) rb[b] = s_rb2[j0 + b];
#pragma unroll
        for (int a = 0; a < 4; a++) {
            float accs[12];
#pragma unroll
            for (int b = 0; b < 6; b++) unpack2(acc2[a][b], accs[2 * b], accs[2 * b + 1]);
            float fc = sFcut[i0 + a];
            float* outp = tbl + (size_t)(r0 + i0 + a) * W3 + j0;
#pragma unroll
            for (int g = 0; g < 3; g++) {
                float4 v;
                v.x = (accs[g * 4 + 0] + rb[g * 4 + 0]) * fc;
                v.y = (accs[g * 4 + 1] + rb[g * 4 + 1]) * fc;
                v.z = (accs[g * 4 + 2] + rb[g * 4 + 2]) * fc;
                v.w = (accs[g * 4 + 3] + rb[g * 4 + 3]) * fc;
                *(float4*)(outp + g * 4) = v;
            }
        }
    }
}

// ---------------- aux launch: CTA 0 scan, CTAs 1..TBL table, rest proj block 0 ----
#define TBL_CTAS (3 * (NT / 64))
#define AUX_SMEM_BYTES (33280 * 4)
__global__ void __launch_bounds__(256) k_aux(const float* __restrict__ Wp0,
                                             const float* __restrict__ rW1,
                                             const float* __restrict__ rb1,
                                             const float* __restrict__ rW2,
                                             const float* __restrict__ rb2) {
    extern __shared__ float sm[];
    int bx = blockIdx.x;
    int t = threadIdx.x;
    if (bx == 0) {
        __shared__ int part[256];
        int base = t * 16;
        int loc[16];
        int s = 0;
#pragma unroll
        for (int i = 0; i < 16; i++) { loc[i] = s; s += g_cnt[base + i]; }
        part[t] = s;
        __syncthreads();
        for (int off = 1; off < 256; off <<= 1) {
            int v = (t >= off) ? part[t - off] : 0;
            __syncthreads();
            part[t] += v;
            __syncthreads();
        }
        int pre = (t == 0) ? 0 : part[t - 1];
#pragma unroll
        for (int i = 0; i < 16; i++) {
            g_off[base + i] = pre + loc[i];
            g_cur[base + i] = pre + loc[i];
            g_cnt[base + i] = 0;
        }
        if (t == 255) g_off[BN] = part[255];
    } else if (bx <= TBL_CTAS) {
        table_body(sm, bx - 1, rW1, rb1, rW2, rb2);
    } else {
        projnode_body(sm, bx - 1 - TBL_CTAS, Wp0);
    }
}

#define PROJN_SMEM_BYTES (33280 * 4)
__global__ void __launch_bounds__(256) k_projnode(const float* __restrict__ Wpb) {
    extern __shared__ float sm[];
    projnode_body(sm, blockIdx.x, Wpb);
}

__global__ void k_fill(const int* __restrict__ dst) {
    int e = blockIdx.x * 256 + threadIdx.x;
    if (e < NE) {
        int p = atomicAdd(&g_cur[dst[e]], 1);
        g_perm[p] = e;
    }
}

// ---------------- sort + gather: per-node warp sorts segment, then writes
// position-ordered (x, src, sh8) so k_seg streams with chain depth 1. ----------
#define SORT_CAP 512
__global__ void __launch_bounds__(256) k_sortgather(const float* __restrict__ ew,
                                                    const int* __restrict__ esrc) {
    __shared__ int sbuf[8 * SORT_CAP];
    int warp = threadIdx.x >> 5, lane = threadIdx.x & 31;
    int n = blockIdx.x * 8 + warp;
    int lo = g_off[n], hi = g_off[n + 1];
    int len = hi - lo;
    int* buf = sbuf + warp * SORT_CAP;
    if (len == 0) return;
    bool in_smem = (len <= SORT_CAP);
    if (len > 1) {
        if (in_smem) {
            for (int i = lane; i < len; i += 32) buf[i] = g_perm[lo + i];
            __syncwarp();
            for (int r = 0; r < len; r++) {
                int st = r & 1;
                for (int i = st + 2 * lane; i + 1 < len; i += 64) {
                    int a = buf[i], b = buf[i + 1];
                    if (a > b) { buf[i] = b; buf[i + 1] = a; }
                }
                __syncwarp();
            }
        } else if (lane == 0) {   // fallback, practically unreachable at Poisson(32)
            for (int i = lo + 1; i < hi; i++) {
                int key = g_perm[i];
                int j = i - 1;
                while (j >= lo && g_perm[j] > key) { g_perm[j + 1] = g_perm[j]; j--; }
                g_perm[j + 1] = key;
            }
        }
        __syncwarp();
    } else if (in_smem) {
        if (lane == 0) buf[0] = g_perm[lo];
        __syncwarp();
    }
    for (int i = lane; i < len; i += 32) {
        int e = in_smem ? buf[i] : g_perm[lo + i];
        int p = lo + i;
        g_px[p] = fminf(ew[e], CUT) * TSCALE;
        g_psrc[p] = esrc[e];
        const float4* shs = (const float4*)(g_sh8 + (size_t)e * 8);
        float4* shd = (float4*)(g_psh + (size_t)p * 8);
        shd[0] = shs[0];
        shd[1] = shs[1];
    }
}

// ---------------- fused segment sum (4 edge-lanes x 48 col-lanes, 2-way pipelined) --------
// streams position-ordered (x, src, sh8); w = P[src] * lerp(table, x) -> g_m
__global__ void __launch_bounds__(192) k_seg(const float* __restrict__ tbl) {
    __shared__ float sred[4 * 48 * 20];    // 15360 B
    int n = blockIdx.x;
    int t = threadIdx.x;
    int el = t / 48;
    int u  = t - el * 48;
    int lo = g_off[n], hi = g_off[n + 1];

    float acc[20];
#pragma unroll
    for (int i = 0; i < 20; i++) acc[i] = 0.f;

    const float4* tbl4 = (const float4*)tbl;
    const float4* P4 = (const float4*)g_P;
    const float4* psh4 = (const float4*)g_psh;

    // accumulate one edge's w into acc (position order preserved by call order)
    auto accum = [&](int p, float4 w) {
        if (u < 16) {
            acc[0] += w.x; acc[1] += w.y; acc[2] += w.z; acc[3] += w.w;
        } else if (u < 32) {
            float4 f0 = psh4[(size_t)p * 2];
            float s0 = f0.x, s1 = f0.y, s2 = f0.z;
            acc[0] += w.x * s0; acc[1] += w.y * s0; acc[2] += w.z * s0; acc[3] += w.w * s0;
            acc[4] += w.x * s1; acc[5] += w.y * s1; acc[6] += w.z * s1; acc[7] += w.w * s1;
            acc[8] += w.x * s2; acc[9] += w.y * s2; acc[10] += w.z * s2; acc[11] += w.w * s2;
        } else {
            float4 f0 = psh4[(size_t)p * 2];
            float4 f1 = psh4[(size_t)p * 2 + 1];
            float sv[5] = {f0.w, f1.x, f1.y, f1.z, f1.w};
#pragma unroll
            for (int dd = 0; dd < 5; dd++) {
                float s = sv[dd];
                acc[dd * 4 + 0] += w.x * s;
                acc[dd * 4 + 1] += w.y * s;
                acc[dd * 4 + 2] += w.z * s;
                acc[dd * 4 + 3] += w.w * s;
            }
        }
    };

    int p = lo + el;
    for (; p + 4 < hi; p += 8) {
        float x0 = g_px[p],     x1 = g_px[p + 4];
        int  s0 = g_psrc[p],    s1 = g_psrc[p + 4];
        int i0 = (int)x0; if (i0 > NT - 2) i0 = NT - 2;
        int i1 = (int)x1; if (i1 > NT - 2) i1 = NT - 2;
        float f0 = x0 - (float)i0;
        float f1 = x1 - (float)i1;
        float4 t00 = tbl4[(size_t)i0 * 48 + u];
        float4 t01 = tbl4[(size_t)(i0 + 1) * 48 + u];
        float4 pv0 = P4[(size_t)s0 * 48 + u];
        float4 t10 = tbl4[(size_t)i1 * 48 + u];
        float4 t11 = tbl4[(size_t)(i1 + 1) * 48 + u];
        float4 pv1 = P4[(size_t)s1 * 48 + u];
        float4 w0, w1;
        w0.x = pv0.x * (t00.x + f0 * (t01.x - t00.x));
        w0.y = pv0.y * (t00.y + f0 * (t01.y - t00.y));
        w0.z = pv0.z * (t00.z + f0 * (t01.z - t00.z));
        w0.w = pv0.w * (t00.w + f0 * (t01.w - t00.w));
        w1.x = pv1.x * (t10.x + f1 * (t11.x - t10.x));
        w1.y = pv1.y * (t10.y + f1 * (t11.y - t10.y));
        w1.z = pv1.z * (t10.z + f1 * (t11.z - t10.z));
        w1.w = pv1.w * (t10.w + f1 * (t11.w - t10.w));
        accum(p, w0);
        accum(p + 4, w1);
    }
    if (p < hi) {
        float x = g_px[p];
        int src = g_psrc[p];
        int i = (int)x; if (i > NT - 2) i = NT - 2;
        float f = x - (float)i;
        float4 t0 = tbl4[(size_t)i * 48 + u];
        float4 t1 = tbl4[(size_t)(i + 1) * 48 + u];
        float4 pv = P4[(size_t)src * 48 + u];
        float4 w;
        w.x = pv.x * (t0.x + f * (t1.x - t0.x));
        w.y = pv.y * (t0.y + f * (t1.y - t0.y));
        w.z = pv.z * (t0.z + f * (t1.z - t0.z));
        w.w = pv.w * (t0.w + f * (t1.w - t0.w));
        accum(p, w);
    }

    float* my = sred + (size_t)t * 20;
#pragma unroll
    for (int i = 0; i < 20; i++) my[i] = acc[i];
    __syncthreads();

    if (el == 0) {
        float s[20];
#pragma unroll
        for (int i = 0; i < 20; i++)
            s[i] = sred[(size_t)u * 20 + i] + sred[(size_t)(48 + u) * 20 + i]
                 + sred[(size_t)(96 + u) * 20 + i] + sred[(size_t)(144 + u) * 20 + i];
        float* mr = g_m + (size_t)n * 576;
        if (u < 16) {
#pragma unroll
            for (int j = 0; j < 4; j++) mr[4 * u + j] = s[j];
        } else if (u < 32) {
            int c0 = 4 * u - 64;
#pragma unroll
            for (int j = 0; j < 4; j++)
#pragma unroll
                for (int dd = 0; dd < 3; dd++)
                    mr[64 + (c0 + j) * 3 + dd] = s[dd * 4 + j];
        } else {
            int c0 = 4 * u - 128;
#pragma unroll
            for (int j = 0; j < 4; j++)
#pragma unroll
                for (int dd = 0; dd < 5; dd++)
                    mr[256 + (c0 + j) * 5 + dd] = s[dd * 4 + j];
        }
    }
}

// ---------------- apply Wo + residual: x += rs * (m @ Wo), 16 nodes/CTA (blocks 0,1) ------
#define OUT_SMEM_BYTES (23552 * 4)
__global__ void __launch_bounds__(256) k_out(const float* __restrict__ Wo0b,
                                             const float* __restrict__ Wo1b,
                                             const float* __restrict__ Wo2b,
                                             const float* __restrict__ res_scale, int b) {
    extern __shared__ float sm[];
    float* sW0 = sm;
    float* sW1 = sm + 8192;
    float* sW2 = sm + 12288;
    float* sM  = sm + 14336;
    int t = threadIdx.x;
    int n0 = blockIdx.x * 16;

    for (int q = t; q < 2048; q += 256) ((float4*)sW0)[q] = ((const float4*)Wo0b)[q];
    for (int q = t; q < 1024; q += 256) ((float4*)sW1)[q] = ((const float4*)Wo1b)[q];
    for (int q = t; q < 512;  q += 256) ((float4*)sW2)[q] = ((const float4*)Wo2b)[q];
    {
        const float4* mg = (const float4*)(g_m + (size_t)n0 * 576);
        for (int q = t; q < 2304; q += 256) ((float4*)sM)[q] = mg[q];
    }
    __syncthreads();

    float rs = res_scale[b];
    for (int idx = t; idx < 16 * 480; idx += 256) {
        int nl = idx / 480, o = idx - nl * 480;
        const float* m = sM + nl * 576;
        float u = 0.f;
        if (o < 128) {
#pragma unroll 8
            for (int k = 0; k < 64; k++) u += m[k] * sW0[k * 128 + o];
        } else if (o < 320) {
            int q = o - 128;
            int c = q / 3, d = q - c * 3;
#pragma unroll 8
            for (int k = 0; k < 64; k++) u += m[64 + k * 3 + d] * sW1[k * 64 + c];
        } else {
            int q = o - 320;
            int c = q / 5, d = q - c * 5;
#pragma unroll 8
            for (int k = 0; k < 64; k++) u += m[256 + k * 5 + d] * sW2[k * 32 + c];
        }
        g_x[(size_t)(n0 + nl) * DIMN + o] += rs * u;
    }
}

// ---------------- final block: out + irrep RMS norm + mask fused -> out buffer ----------
// 16 lanes per node, 30 outputs per thread (o = ln + 16k).
__global__ void __launch_bounds__(256) k_out_norm(const float* __restrict__ Wo0b,
                                                  const float* __restrict__ Wo1b,
                                                  const float* __restrict__ Wo2b,
                                                  const float* __restrict__ res_scale,
                                                  const float* __restrict__ mask,
                                                  float* __restrict__ out) {
    extern __shared__ float sm[];
    float* sW0 = sm;
    float* sW1 = sm + 8192;
    float* sW2 = sm + 12288;
    float* sM  = sm + 14336;
    int t = threadIdx.x;
    int n0 = blockIdx.x * 16;

    for (int q = t; q < 2048; q += 256) ((float4*)sW0)[q] = ((const float4*)Wo0b)[q];
    for (int q = t; q < 1024; q += 256) ((float4*)sW1)[q] = ((const float4*)Wo1b)[q];
    for (int q = t; q < 512;  q += 256) ((float4*)sW2)[q] = ((const float4*)Wo2b)[q];
    {
        const float4* mg = (const float4*)(g_m + (size_t)n0 * 576);
        for (int q = t; q < 2304; q += 256) ((float4*)sM)[q] = mg[q];
    }
    __syncthreads();

    float rs = res_scale[2];
    int nl = t >> 4, ln = t & 15;
    int n = n0 + nl;
    const float* m = sM + nl * 576;
    const float* xr = g_x + (size_t)n * DIMN;

    float xv[30];
    float p0 = 0.f, p1 = 0.f, p2 = 0.f;
#pragma unroll
    for (int k = 0; k < 30; k++) {
        int o = ln + 16 * k;
        float u = 0.f;
        if (k < 8) {
#pragma unroll 8
            for (int kk = 0; kk < 64; kk++) u += m[kk] * sW0[kk * 128 + o];
        } else if (k < 20) {
            int q = o - 128;
            int c = q / 3, d = q - c * 3;
#pragma unroll 8
            for (int kk = 0; kk < 64; kk++) u += m[64 + kk * 3 + d] * sW1[kk * 64 + c];
        } else {
            int q = o - 320;
            int c = q / 5, d = q - c * 5;
#pragma unroll 8
            for (int kk = 0; kk < 64; kk++) u += m[256 + kk * 5 + d] * sW2[kk * 32 + c];
        }
        float xn = xr[o] + rs * u;
        xv[k] = xn;
        float sq = xn * xn;
        if (k < 8) p0 += sq;
        else if (k < 20) p1 += sq;
        else p2 += sq;
    }
    // butterfly reduce across the 16 lanes of this node
#pragma unroll
    for (int off = 8; off >= 1; off >>= 1) {
        p0 += __shfl_xor_sync(0xffffffffu, p0, off, 16);
        p1 += __shfl_xor_sync(0xffffffffu, p1, off, 16);
        p2 += __shfl_xor_sync(0xffffffffu, p2, off, 16);
    }
    float inv0 = 1.f / sqrtf(p0 / 128.f + 1e-6f);
    float inv1 = 1.f / sqrtf(p1 / 64.f + 1e-6f);
    float inv2 = 1.f / sqrtf(p2 / 32.f + 1e-6f);
    float mm = mask[n];
    float* outr = out + (size_t)n * DIMN;
#pragma unroll
    for (int k = 0; k < 30; k++) {
        int o = ln + 16 * k;
        float inv = (k < 8) ? inv0 : ((k < 20) ? inv1 : inv2);
        outr[o] = xv[k] * inv * mm;
    }
}

// ---------------- launch ----------------
extern "C" void kernel_launch(void* const* d_in, const int* in_sizes, int n_in,
                              void* d_out, int out_size) {
    const int*   z         = (const int*)d_in[0];
    const float* mask      = (const float*)d_in[1];
    const int*   edge_src  = (const int*)d_in[2];
    const int*   edge_dst  = (const int*)d_in[3];
    const float* edge_w    = (const float*)d_in[4];
    const float* edge_vec  = (const float*)d_in[5];
    const float* z_emb     = (const float*)d_in[6];
    const float* W_in      = (const float*)d_in[7];
    const float* Wp        = (const float*)d_in[8];
    const float* rW1       = (const float*)d_in[9];
    const float* rb1       = (const float*)d_in[10];
    const float* rW2       = (const float*)d_in[11];
    const float* rb2       = (const float*)d_in[12];
    const float* Wo0       = (const float*)d_in[13];
    const float* Wo1       = (const float*)d_in[14];
    const float* Wo2       = (const float*)d_in[15];
    const float* res_scale = (const float*)d_in[16];
    float* out = (float*)d_out;

    cudaFuncSetAttribute(k_aux, cudaFuncAttributeMaxDynamicSharedMemorySize, AUX_SMEM_BYTES);
    cudaFuncSetAttribute(k_projnode, cudaFuncAttributeMaxDynamicSharedMemorySize, PROJN_SMEM_BYTES);
    cudaFuncSetAttribute(k_out, cudaFuncAttributeMaxDynamicSharedMemorySize, OUT_SMEM_BYTES);
    cudaFuncSetAttribute(k_out_norm, cudaFuncAttributeMaxDynamicSharedMemorySize, OUT_SMEM_BYTES);

    float* tbl_dev;
    cudaGetSymbolAddress((void**)&tbl_dev, g_table);

    k_setup<<<G_INIT + G_GEO + G_CNT, 256>>>(z, mask, z_emb, W_in, edge_w, edge_vec, edge_dst); // 0
    k_aux<<<1 + TBL_CTAS + 64, 256, AUX_SMEM_BYTES>>>(Wp, rW1, rb1, rW2, rb2);                   // 1
    k_fill<<<NE / 256, 256>>>(edge_dst);                                                         // 2
    k_sortgather<<<BN / 8, 256>>>(edge_w, edge_src);                                             // 3 <- ncu
    k_seg<<<BN, 192>>>(tbl_dev);                                                                 // 4
    k_out<<<BN / 16, 256, OUT_SMEM_BYTES>>>(Wo0, Wo1, Wo2, res_scale, 0);                        // 5

    // block 1
    k_projnode<<<BN / 64, 256, PROJN_SMEM_BYTES>>>(Wp + 1 * 128 * 192);
    k_seg<<<BN, 192>>>(tbl_dev + (size_t)1 * NT * W3);
    k_out<<<BN / 16, 256, OUT_SMEM_BYTES>>>(Wo0 + 1 * 64 * 128, Wo1 + 1 * 64 * 64,
                                            Wo2 + 1 * 64 * 32, res_scale, 1);
    // block 2 (fused with irrep norm + mask -> final output)
    k_projnode<<<BN / 64, 256, PROJN_SMEM_BYTES>>>(Wp + 2 * 128 * 192);
    k_seg<<<BN, 192>>>(tbl_dev + (size_t)2 * NT * W3);
    k_out_norm<<<BN / 16, 256, OUT_SMEM_BYTES>>>(Wo0 + 2 * 64 * 128, Wo1 + 2 * 64 * 64,
                                                 Wo2 + 2 * 64 * 32, res_scale, mask, out);
}